// round 3
// baseline (speedup 1.0000x reference)
#include <cuda_runtime.h>
#include <math.h>

#define D_MODEL 1024
#define NHEAD   16
#define DKH     64
#define BATCH   4
#define SEQ     2048
#define M_TOT   (BATCH*SEQ)     // 8192
#define BH      (BATCH*NHEAD)   // 64

// Scratch (allocation-free rule: __device__ globals)
__device__ float g_q[(size_t)BH*SEQ*DKH];      // [B,H,S,dk]
__device__ float g_k[(size_t)BH*SEQ*DKH];
__device__ float g_v[(size_t)BH*SEQ*DKH];
__device__ float g_attn[(size_t)M_TOT*D_MODEL]; // [B*S, D] pre-Wo

typedef unsigned long long ull;

// ---- packed f32x2 helpers (full-rate fp32 on sm_103a) ----
__device__ __forceinline__ ull pack2(float lo, float hi) {
    ull r; asm("mov.b64 %0, {%1, %2};" : "=l"(r) : "f"(lo), "f"(hi)); return r;
}
__device__ __forceinline__ void unpack2(ull v, float& lo, float& hi) {
    asm("mov.b64 {%0, %1}, %2;" : "=f"(lo), "=f"(hi) : "l"(v));
}
__device__ __forceinline__ ull ffma2(ull a, ull b, ull c) {
    ull d; asm("fma.rn.f32x2 %0, %1, %2, %3;" : "=l"(d) : "l"(a), "l"(b), "l"(c)); return d;
}
__device__ __forceinline__ ull fmul2(ull a, ull b) {
    ull d; asm("mul.rn.f32x2 %0, %1, %2;" : "=l"(d) : "l"(a), "l"(b)); return d;
}

// ============================================================================
// GEMM: out[M,N] = A[M,K] @ W[N,K]^T + bias   (nn.Linear semantics)
// mode 0/1/2: A = x, out = g_q/g_k/g_v with [B,H,S,dk] head-split epilogue
// mode 3:     A = g_attn, out = outp (row-major [M,N])
// Tiles: 128x128x16, 256 threads, 8x8 microtile, f32x2 packed FMA.
// ============================================================================
__global__ __launch_bounds__(256, 2)
void gemm_bias_kernel(const float* __restrict__ Ain, const float* __restrict__ W,
                      const float* __restrict__ bias, float* __restrict__ outp,
                      int mode)
{
    __shared__ float As[16][132];   // k-major (transposed) for float4 frag reads
    __shared__ float Ws[16][132];

    const float* A = (mode == 3) ? g_attn : Ain;
    float* out = (mode == 0) ? g_q : (mode == 1) ? g_k : (mode == 2) ? g_v : outp;

    const int tid = threadIdx.x;
    const int tx = tid & 15, ty = tid >> 4;
    const int m0 = blockIdx.y * 128;
    const int n0 = blockIdx.x * 128;
    const int lr = tid >> 2;          // 0..63 : tile row
    const int lk = (tid & 3) << 2;    // 0,4,8,12 : k offset

    ull acc[8][4];
    #pragma unroll
    for (int i = 0; i < 8; i++)
        #pragma unroll
        for (int j = 0; j < 4; j++) acc[i][j] = 0ull;

    for (int k0 = 0; k0 < D_MODEL; k0 += 16) {
        #pragma unroll
        for (int h = 0; h < 2; h++) {
            int row = lr + h * 64;
            float4 va = *reinterpret_cast<const float4*>(A + (size_t)(m0 + row) * D_MODEL + k0 + lk);
            As[lk+0][row] = va.x; As[lk+1][row] = va.y; As[lk+2][row] = va.z; As[lk+3][row] = va.w;
            float4 vw = *reinterpret_cast<const float4*>(W + (size_t)(n0 + row) * D_MODEL + k0 + lk);
            Ws[lk+0][row] = vw.x; Ws[lk+1][row] = vw.y; Ws[lk+2][row] = vw.z; Ws[lk+3][row] = vw.w;
        }
        __syncthreads();
        #pragma unroll
        for (int kk = 0; kk < 16; kk++) {
            float4 a0 = *reinterpret_cast<const float4*>(&As[kk][ty * 8]);
            float4 a1 = *reinterpret_cast<const float4*>(&As[kk][ty * 8 + 4]);
            ulonglong2 b0 = *reinterpret_cast<const ulonglong2*>(&Ws[kk][tx * 8]);
            ulonglong2 b1 = *reinterpret_cast<const ulonglong2*>(&Ws[kk][tx * 8 + 4]);
            float af[8] = {a0.x, a0.y, a0.z, a0.w, a1.x, a1.y, a1.z, a1.w};
            ull bp[4] = {b0.x, b0.y, b1.x, b1.y};
            #pragma unroll
            for (int i = 0; i < 8; i++) {
                ull ai = pack2(af[i], af[i]);
                #pragma unroll
                for (int j = 0; j < 4; j++) acc[i][j] = ffma2(ai, bp[j], acc[i][j]);
            }
        }
        __syncthreads();
    }

    // Epilogue: + bias, scatter
    #pragma unroll
    for (int i = 0; i < 8; i++) {
        int m = m0 + ty * 8 + i;
        float c[8];
        #pragma unroll
        for (int j = 0; j < 4; j++) unpack2(acc[i][j], c[2*j], c[2*j+1]);
        int nbase = n0 + tx * 8;
        if (mode < 3) {
            // head-split: n -> (h, d); m -> (b, s); 8 cols stay in one head (64%8==0)
            int b = m >> 11, s = m & (SEQ - 1);
            int h = nbase >> 6, d0 = nbase & 63;
            float* dst = out + (((size_t)(b * NHEAD + h)) * SEQ + s) * DKH + d0;
            #pragma unroll
            for (int j = 0; j < 8; j++) dst[j] = c[j] + bias[nbase + j];
        } else {
            float* dst = out + (size_t)m * D_MODEL + nbase;
            #pragma unroll
            for (int j = 0; j < 8; j++) dst[j] = c[j] + bias[nbase + j];
        }
    }
}

// ============================================================================
// Flash attention, causal. One block = 64 queries of one (b,h).
// smem: Qt [d][i] 64x68, KtP (K as [d][j], then aliased as P [j][i]) 64x68,
//       Vs [j][d] 64x68.  256 threads, each owns 4 rows x 4 cols.
// ============================================================================
__global__ __launch_bounds__(256)
void flash_attn_kernel()
{
    extern __shared__ float smf[];
    float* Qt  = smf;               // [64][68] d-major
    float* KtP = smf + 64 * 68;     // K d-major, later P j-major (aliased)
    float* Vs  = smf + 2 * 64 * 68; // [64][68] j-major

    const int tid = threadIdx.x;
    const int tx = tid & 15, ty = tid >> 4;
    const int qt = blockIdx.x;      // query tile 0..31
    const int bh = blockIdx.y;      // 0..63

    const float* Qg = g_q + (size_t)bh * SEQ * DKH;
    const float* Kg = g_k + (size_t)bh * SEQ * DKH;
    const float* Vg = g_v + (size_t)bh * SEQ * DKH;

    const int li = tid >> 4;          // 0..15
    const int ld = (tid & 15) << 2;   // 0..60

    // Load Q tile transposed (d-major)
    #pragma unroll
    for (int r = 0; r < 4; r++) {
        int i = r * 16 + li;
        float4 v = *reinterpret_cast<const float4*>(Qg + (size_t)(qt * 64 + i) * DKH + ld);
        Qt[(ld+0)*68 + i] = v.x; Qt[(ld+1)*68 + i] = v.y;
        Qt[(ld+2)*68 + i] = v.z; Qt[(ld+3)*68 + i] = v.w;
    }

    ull o2[4][2];
    #pragma unroll
    for (int i = 0; i < 4; i++) { o2[i][0] = 0ull; o2[i][1] = 0ull; }
    float mrow[4], lrow[4];
    #pragma unroll
    for (int i = 0; i < 4; i++) { mrow[i] = -INFINITY; lrow[i] = 0.f; }

    for (int kt = 0; kt <= qt; kt++) {
        __syncthreads();   // prev tile's P/V reads done before overwrite
        #pragma unroll
        for (int r = 0; r < 4; r++) {
            int i = r * 16 + li;
            float4 kv = *reinterpret_cast<const float4*>(Kg + (size_t)(kt * 64 + i) * DKH + ld);
            KtP[(ld+0)*68 + i] = kv.x; KtP[(ld+1)*68 + i] = kv.y;
            KtP[(ld+2)*68 + i] = kv.z; KtP[(ld+3)*68 + i] = kv.w;
            float4 vv = *reinterpret_cast<const float4*>(Vg + (size_t)(kt * 64 + i) * DKH + ld);
            *reinterpret_cast<float4*>(&Vs[i * 68 + ld]) = vv;
        }
        __syncthreads();   // tiles ready (covers Qt on first iter)

        // S = Q K^T (each thread: rows ty*4.., cols tx*4..)
        ull s2[4][2];
        #pragma unroll
        for (int i = 0; i < 4; i++) { s2[i][0] = 0ull; s2[i][1] = 0ull; }
        #pragma unroll 8
        for (int d = 0; d < 64; d++) {
            float4 qv = *reinterpret_cast<const float4*>(&Qt[d * 68 + ty * 4]);
            ulonglong2 kv = *reinterpret_cast<const ulonglong2*>(&KtP[d * 68 + tx * 4]);
            float qf[4] = {qv.x, qv.y, qv.z, qv.w};
            #pragma unroll
            for (int ii = 0; ii < 4; ii++) {
                ull ai = pack2(qf[ii], qf[ii]);
                s2[ii][0] = ffma2(ai, kv.x, s2[ii][0]);
                s2[ii][1] = ffma2(ai, kv.y, s2[ii][1]);
            }
        }
        float s[4][4];
        #pragma unroll
        for (int ii = 0; ii < 4; ii++) {
            unpack2(s2[ii][0], s[ii][0], s[ii][1]);
            unpack2(s2[ii][1], s[ii][2], s[ii][3]);
            #pragma unroll
            for (int jj = 0; jj < 4; jj++) s[ii][jj] *= 0.125f;  // 1/sqrt(64)
        }

        if (kt == qt) {  // causal mask on diagonal tile: key > query -> -inf
            #pragma unroll
            for (int ii = 0; ii < 4; ii++)
                #pragma unroll
                for (int jj = 0; jj < 4; jj++)
                    if (tx * 4 + jj > ty * 4 + ii) s[ii][jj] = -INFINITY;
        }

        // Online softmax update (row reductions across tx via shfl, lane bits 0-3)
        #pragma unroll
        for (int ii = 0; ii < 4; ii++) {
            float rm = fmaxf(fmaxf(s[ii][0], s[ii][1]), fmaxf(s[ii][2], s[ii][3]));
            rm = fmaxf(rm, __shfl_xor_sync(0xffffffffu, rm, 8));
            rm = fmaxf(rm, __shfl_xor_sync(0xffffffffu, rm, 4));
            rm = fmaxf(rm, __shfl_xor_sync(0xffffffffu, rm, 2));
            rm = fmaxf(rm, __shfl_xor_sync(0xffffffffu, rm, 1));
            float mn = fmaxf(mrow[ii], rm);
            float alpha = __expf(mrow[ii] - mn);   // -inf -> 0 on first tile
            mrow[ii] = mn;
            float rs = 0.f;
            #pragma unroll
            for (int jj = 0; jj < 4; jj++) {
                float p = __expf(s[ii][jj] - mn);  // masked -inf -> 0
                s[ii][jj] = p;
                rs += p;
            }
            rs += __shfl_xor_sync(0xffffffffu, rs, 8);
            rs += __shfl_xor_sync(0xffffffffu, rs, 4);
            rs += __shfl_xor_sync(0xffffffffu, rs, 2);
            rs += __shfl_xor_sync(0xffffffffu, rs, 1);
            lrow[ii] = lrow[ii] * alpha + rs;
            ull a2 = pack2(alpha, alpha);
            o2[ii][0] = fmul2(o2[ii][0], a2);
            o2[ii][1] = fmul2(o2[ii][1], a2);
        }

        __syncthreads();   // all reads of K(t) done before aliasing as P
        // Write P transposed: P[j][i] (i contiguous for float4 reads)
        #pragma unroll
        for (int jj = 0; jj < 4; jj++) {
            float4 pv = make_float4(s[0][jj], s[1][jj], s[2][jj], s[3][jj]);
            *reinterpret_cast<float4*>(&KtP[(tx * 4 + jj) * 68 + ty * 4]) = pv;
        }
        __syncthreads();   // P ready

        // O += P @ V  (contraction over j)
        #pragma unroll 8
        for (int j = 0; j < 64; j++) {
            float4 pv = *reinterpret_cast<const float4*>(&KtP[j * 68 + ty * 4]);
            ulonglong2 vv = *reinterpret_cast<const ulonglong2*>(&Vs[j * 68 + tx * 4]);
            float pf[4] = {pv.x, pv.y, pv.z, pv.w};
            #pragma unroll
            for (int ii = 0; ii < 4; ii++) {
                ull ai = pack2(pf[ii], pf[ii]);
                o2[ii][0] = ffma2(ai, vv.x, o2[ii][0]);
                o2[ii][1] = ffma2(ai, vv.y, o2[ii][1]);
            }
        }
    }

    // Normalize and write to [B, S, H*dk] scratch
    int b = bh >> 4, h = bh & 15;
    #pragma unroll
    for (int ii = 0; ii < 4; ii++) {
        float inv = 1.0f / lrow[ii];
        float o[4];
        unpack2(o2[ii][0], o[0], o[1]);
        unpack2(o2[ii][1], o[2], o[3]);
        int srow = qt * 64 + ty * 4 + ii;
        float4 ov = make_float4(o[0]*inv, o[1]*inv, o[2]*inv, o[3]*inv);
        *reinterpret_cast<float4*>(
            &g_attn[((size_t)(b * SEQ + srow)) * D_MODEL + h * 64 + tx * 4]) = ov;
    }
}

// ============================================================================
extern "C" void kernel_launch(void* const* d_in, const int* in_sizes, int n_in,
                              void* d_out, int out_size)
{
    const float* x  = (const float*)d_in[0];
    const float* Wq = (const float*)d_in[1];
    const float* bq = (const float*)d_in[2];
    const float* Wk = (const float*)d_in[3];
    const float* bk = (const float*)d_in[4];
    const float* Wv = (const float*)d_in[5];
    const float* bv = (const float*)d_in[6];
    const float* Wo = (const float*)d_in[7];
    const float* bo = (const float*)d_in[8];
    float* out = (float*)d_out;

    dim3 gg(D_MODEL / 128, M_TOT / 128);   // (8, 64)

    gemm_bias_kernel<<<gg, 256>>>(x, Wq, bq, nullptr, 0);
    gemm_bias_kernel<<<gg, 256>>>(x, Wk, bk, nullptr, 1);
    gemm_bias_kernel<<<gg, 256>>>(x, Wv, bv, nullptr, 2);

    const int attn_smem = 3 * 64 * 68 * 4;   // 52224 B > 48K default
    cudaFuncSetAttribute(flash_attn_kernel,
                         cudaFuncAttributeMaxDynamicSharedMemorySize, attn_smem);
    flash_attn_kernel<<<dim3(SEQ / 64, BH), 256, attn_smem>>>();

    gemm_bias_kernel<<<gg, 256>>>(x, Wo, bo, out, 3);
}

// round 6
// speedup vs baseline: 1.6340x; 1.6340x over previous
#include <cuda_runtime.h>
#include <cuda_bf16.h>
#include <math.h>
#include <stdint.h>

#define D_MODEL 1024
#define NHEAD   16
#define DKH     64
#define BATCH   4
#define SEQ     2048
#define M_TOT   (BATCH*SEQ)     // 8192
#define BH      (BATCH*NHEAD)   // 64

// ---- scratch (__device__ globals: allocation-free rule) ----
__device__ float g_q[(size_t)BH*SEQ*DKH];       // [B,H,S,dk]
__device__ float g_k[(size_t)BH*SEQ*DKH];
__device__ float g_v[(size_t)BH*SEQ*DKH];
__device__ float g_attn[(size_t)M_TOT*D_MODEL]; // [B*S, D] pre-Wo (fp32)
// bf16 hi/lo split operands for mma.sync GEMMs
__device__ __nv_bfloat16 g_xh[(size_t)M_TOT*D_MODEL];
__device__ __nv_bfloat16 g_xl[(size_t)M_TOT*D_MODEL];
__device__ __nv_bfloat16 g_ah[(size_t)M_TOT*D_MODEL];
__device__ __nv_bfloat16 g_al[(size_t)M_TOT*D_MODEL];
__device__ __nv_bfloat16 g_wh[4][(size_t)D_MODEL*D_MODEL];
__device__ __nv_bfloat16 g_wl[4][(size_t)D_MODEL*D_MODEL];

typedef unsigned long long ull;

// ---- packed f32x2 helpers (attention kernel) ----
__device__ __forceinline__ ull pack2(float lo, float hi) {
    ull r; asm("mov.b64 %0, {%1, %2};" : "=l"(r) : "f"(lo), "f"(hi)); return r;
}
__device__ __forceinline__ void unpack2(ull v, float& lo, float& hi) {
    asm("mov.b64 {%0, %1}, %2;" : "=f"(lo), "=f"(hi) : "l"(v));
}
__device__ __forceinline__ ull ffma2(ull a, ull b, ull c) {
    ull d; asm("fma.rn.f32x2 %0, %1, %2, %3;" : "=l"(d) : "l"(a), "l"(b), "l"(c)); return d;
}
__device__ __forceinline__ ull fmul2(ull a, ull b) {
    ull d; asm("mul.rn.f32x2 %0, %1, %2;" : "=l"(d) : "l"(a), "l"(b)); return d;
}

__device__ __forceinline__ uint32_t smem_u32(const void* p) {
    uint32_t a;
    asm("{ .reg .u64 t; cvta.to.shared.u64 t, %1; cvt.u32.u64 %0, t; }" : "=r"(a) : "l"(p));
    return a;
}
__device__ __forceinline__ void ldsm4(uint32_t& r0, uint32_t& r1, uint32_t& r2, uint32_t& r3,
                                      uint32_t addr) {
    asm volatile("ldmatrix.sync.aligned.m8n8.x4.shared.b16 {%0,%1,%2,%3}, [%4];"
                 : "=r"(r0), "=r"(r1), "=r"(r2), "=r"(r3) : "r"(addr));
}
__device__ __forceinline__ void mma16816(float* c, const uint32_t* a, const uint32_t* b) {
    asm volatile(
        "mma.sync.aligned.m16n8k16.row.col.f32.bf16.bf16.f32 "
        "{%0,%1,%2,%3}, {%4,%5,%6,%7}, {%8,%9}, {%0,%1,%2,%3};"
        : "+f"(c[0]), "+f"(c[1]), "+f"(c[2]), "+f"(c[3])
        : "r"(a[0]), "r"(a[1]), "r"(a[2]), "r"(a[3]), "r"(b[0]), "r"(b[1]));
}

// ============================================================================
// split fp32 -> bf16 (hi, lo) pairs.  which: 0=x, 1..4=W[q,k,v,o], 5=g_attn
// ============================================================================
__global__ void split_kernel(const float* __restrict__ in, int which, int n4)
{
    __nv_bfloat16 *hi, *lo;
    if (which == 0)      { hi = g_xh; lo = g_xl; }
    else if (which <= 4) { hi = g_wh[which-1]; lo = g_wl[which-1]; }
    else                 { hi = g_ah; lo = g_al; }
    const float* src = (which == 5) ? g_attn : in;

    int i = blockIdx.x * blockDim.x + threadIdx.x;
    if (i >= n4) return;
    float4 v = reinterpret_cast<const float4*>(src)[i];
    __nv_bfloat16 h[4], l[4];
    float f[4] = {v.x, v.y, v.z, v.w};
    #pragma unroll
    for (int j = 0; j < 4; ++j) {
        h[j] = __float2bfloat16(f[j]);
        l[j] = __float2bfloat16(f[j] - __bfloat162float(h[j]));
    }
    reinterpret_cast<ull*>(hi)[i] = *reinterpret_cast<ull*>(h);
    reinterpret_cast<ull*>(lo)[i] = *reinterpret_cast<ull*>(l);
}

// ============================================================================
// mma.sync 3xbf16 GEMM: out[M,N] = A[M,K] @ W[N,K]^T + bias
// CTA 128x128, K-chunk 32, 2-stage cp.async double buffer.
// 8 warps: warp tile 32(m) x 64(n); per warp 2 m-tiles x 8 n-tiles of m16n8k16.
// smem tile: [128 rows][32 k bf16] = 64B/row; 16B-chunk swizzle kc ^ ((row>>1)&3).
// ============================================================================
#define GTILE_B 8192                 // one 128x32 bf16 tile
#define GSTAGE_B (4 * GTILE_B)       // Ah, Al, Bh, Bl
#define GEMM_SMEM (2 * GSTAGE_B)     // 65536

__device__ __forceinline__ void load_chunk(
    uint32_t sstage, const __nv_bfloat16* Ah, const __nv_bfloat16* Al,
    const __nv_bfloat16* Bh, const __nv_bfloat16* Bl,
    int m0, int n0, int k0, int tid)
{
    const __nv_bfloat16* srcs[4] = {Ah, Al, Bh, Bl};
    const int bases[4] = {m0, m0, n0, n0};
    #pragma unroll
    for (int t = 0; t < 4; ++t) {
        #pragma unroll
        for (int i = 0; i < 2; ++i) {
            int idx = tid + i * 256;          // 0..511
            int row = idx >> 2, kc = idx & 3;
            const void* g = srcs[t] + (size_t)(bases[t] + row) * D_MODEL + k0 + kc * 8;
            uint32_t s = sstage + t * GTILE_B + row * 64 + ((kc ^ ((row >> 1) & 3)) * 16);
            asm volatile("cp.async.cg.shared.global [%0], [%1], 16;" :: "r"(s), "l"(g));
        }
    }
}

__global__ __launch_bounds__(256, 1)
void gemm_mma_kernel(int mode, const float* __restrict__ bias, float* __restrict__ outp)
{
    extern __shared__ __align__(128) char smem[];
    const uint32_t sb = smem_u32(smem);

    const __nv_bfloat16* Ah = (mode == 3) ? g_ah : g_xh;
    const __nv_bfloat16* Al = (mode == 3) ? g_al : g_xl;
    const __nv_bfloat16* Bh = g_wh[mode];
    const __nv_bfloat16* Bl = g_wl[mode];
    float* out = (mode == 0) ? g_q : (mode == 1) ? g_k : (mode == 2) ? g_v : outp;

    const int tid = threadIdx.x, wid = tid >> 5, lane = tid & 31;
    const int m0 = blockIdx.y * 128, n0 = blockIdx.x * 128;
    const int mw = (wid & 3) * 32, nw = (wid >> 2) * 64;
    const int mid = lane >> 3, lrow = lane & 7;

    float acc[2][8][4];
    #pragma unroll
    for (int im = 0; im < 2; ++im)
        #pragma unroll
        for (int jn = 0; jn < 8; ++jn)
            #pragma unroll
            for (int r = 0; r < 4; ++r) acc[im][jn][r] = 0.f;

    // prologue: chunk 0 -> stage 0
    load_chunk(sb, Ah, Al, Bh, Bl, m0, n0, 0, tid);
    asm volatile("cp.async.commit_group;" ::: "memory");

    const int NCH = D_MODEL / 32;   // 32
    for (int c = 0; c < NCH; ++c) {
        const uint32_t sstage = sb + (c & 1) * GSTAGE_B;
        if (c + 1 < NCH) {
            load_chunk(sb + ((c + 1) & 1) * GSTAGE_B, Ah, Al, Bh, Bl, m0, n0, (c + 1) * 32, tid);
            asm volatile("cp.async.commit_group;" ::: "memory");
            asm volatile("cp.async.wait_group 1;" ::: "memory");
        } else {
            asm volatile("cp.async.wait_group 0;" ::: "memory");
        }
        __syncthreads();

        #pragma unroll
        for (int s = 0; s < 2; ++s) {
            uint32_t ah[2][4], al[2][4], bh[8][2], bl[8][2];
            // A fragments (hi & lo): x4 matrices M0..M3 = (r+0,k0-7),(r+8,k0-7),(r+0,k8-15),(r+8,k8-15)
            #pragma unroll
            for (int im = 0; im < 2; ++im) {
                int row = mw + im * 16 + ((mid & 1) << 3) + lrow;
                int kc  = 2 * s + (mid >> 1);
                uint32_t addr = sstage + row * 64 + ((kc ^ ((row >> 1) & 3)) * 16);
                ldsm4(ah[im][0], ah[im][1], ah[im][2], ah[im][3], addr);
                ldsm4(al[im][0], al[im][1], al[im][2], al[im][3], addr + GTILE_B);
            }
            // B fragments: x4 covers n-tiles (2jp, 2jp+1): M0=(nj,k0-7) M1=(nj,k8-15) M2=(nj+1,k0-7) M3=(nj+1,k8-15)
            #pragma unroll
            for (int jp = 0; jp < 4; ++jp) {
                int row = nw + jp * 16 + ((mid >> 1) << 3) + lrow;
                int kc  = 2 * s + (mid & 1);
                uint32_t addr = sstage + 2 * GTILE_B + row * 64 + ((kc ^ ((row >> 1) & 3)) * 16);
                ldsm4(bh[2*jp][0], bh[2*jp][1], bh[2*jp+1][0], bh[2*jp+1][1], addr);
                ldsm4(bl[2*jp][0], bl[2*jp][1], bl[2*jp+1][0], bl[2*jp+1][1], addr + GTILE_B);
            }
            #pragma unroll
            for (int im = 0; im < 2; ++im)
                #pragma unroll
                for (int jn = 0; jn < 8; ++jn) {
                    mma16816(acc[im][jn], ah[im], bh[jn]);   // hi*hi
                    mma16816(acc[im][jn], ah[im], bl[jn]);   // hi*lo
                    mma16816(acc[im][jn], al[im], bh[jn]);   // lo*hi
                }
        }
        __syncthreads();
    }

    // Epilogue: D frag: c0=D[g][2t] c1=D[g][2t+1] c2=D[g+8][2t] c3=D[g+8][2t+1]
    const int g = lane >> 2, t = lane & 3;
    #pragma unroll
    for (int im = 0; im < 2; ++im) {
        #pragma unroll
        for (int jn = 0; jn < 8; ++jn) {
            int r0 = m0 + mw + im * 16 + g;
            int cc = n0 + nw + jn * 8 + 2 * t;
            float2 b2 = *reinterpret_cast<const float2*>(bias + cc);
            float2 v0 = make_float2(acc[im][jn][0] + b2.x, acc[im][jn][1] + b2.y);
            float2 v1 = make_float2(acc[im][jn][2] + b2.x, acc[im][jn][3] + b2.y);
            if (mode < 3) {
                int h = cc >> 6, d = cc & 63;
                int b0 = r0 >> 11, s0 = r0 & (SEQ - 1);
                *reinterpret_cast<float2*>(
                    out + (((size_t)(b0 * NHEAD + h)) * SEQ + s0) * DKH + d) = v0;
                int r1 = r0 + 8;
                int b1 = r1 >> 11, s1 = r1 & (SEQ - 1);
                *reinterpret_cast<float2*>(
                    out + (((size_t)(b1 * NHEAD + h)) * SEQ + s1) * DKH + d) = v1;
            } else {
                *reinterpret_cast<float2*>(out + (size_t)r0 * D_MODEL + cc) = v0;
                *reinterpret_cast<float2*>(out + (size_t)(r0 + 8) * D_MODEL + cc) = v1;
            }
        }
    }
}

// ============================================================================
// Flash attention, causal — verbatim R3 (known good, fp32/f32x2)
// ============================================================================
__global__ __launch_bounds__(256)
void flash_attn_kernel()
{
    extern __shared__ float smf[];
    float* Qt  = smf;               // [64][68] d-major
    float* KtP = smf + 64 * 68;     // K d-major, later P j-major (aliased)
    float* Vs  = smf + 2 * 64 * 68; // [64][68] j-major

    const int tid = threadIdx.x;
    const int tx = tid & 15, ty = tid >> 4;
    const int qt = blockIdx.x;
    const int bh = blockIdx.y;

    const float* Qg = g_q + (size_t)bh * SEQ * DKH;
    const float* Kg = g_k + (size_t)bh * SEQ * DKH;
    const float* Vg = g_v + (size_t)bh * SEQ * DKH;

    const int li = tid >> 4;
    const int ld = (tid & 15) << 2;

    #pragma unroll
    for (int r = 0; r < 4; r++) {
        int i = r * 16 + li;
        float4 v = *reinterpret_cast<const float4*>(Qg + (size_t)(qt * 64 + i) * DKH + ld);
        Qt[(ld+0)*68 + i] = v.x; Qt[(ld+1)*68 + i] = v.y;
        Qt[(ld+2)*68 + i] = v.z; Qt[(ld+3)*68 + i] = v.w;
    }

    ull o2[4][2];
    #pragma unroll
    for (int i = 0; i < 4; i++) { o2[i][0] = 0ull; o2[i][1] = 0ull; }
    float mrow[4], lrow[4];
    #pragma unroll
    for (int i = 0; i < 4; i++) { mrow[i] = -INFINITY; lrow[i] = 0.f; }

    for (int kt = 0; kt <= qt; kt++) {
        __syncthreads();
        #pragma unroll
        for (int r = 0; r < 4; r++) {
            int i = r * 16 + li;
            float4 kv = *reinterpret_cast<const float4*>(Kg + (size_t)(kt * 64 + i) * DKH + ld);
            KtP[(ld+0)*68 + i] = kv.x; KtP[(ld+1)*68 + i] = kv.y;
            KtP[(ld+2)*68 + i] = kv.z; KtP[(ld+3)*68 + i] = kv.w;
            float4 vv = *reinterpret_cast<const float4*>(Vg + (size_t)(kt * 64 + i) * DKH + ld);
            *reinterpret_cast<float4*>(&Vs[i * 68 + ld]) = vv;
        }
        __syncthreads();

        ull s2[4][2];
        #pragma unroll
        for (int i = 0; i < 4; i++) { s2[i][0] = 0ull; s2[i][1] = 0ull; }
        #pragma unroll 8
        for (int d = 0; d < 64; d++) {
            float4 qv = *reinterpret_cast<const float4*>(&Qt[d * 68 + ty * 4]);
            ulonglong2 kv = *reinterpret_cast<const ulonglong2*>(&KtP[d * 68 + tx * 4]);
            float qf[4] = {qv.x, qv.y, qv.z, qv.w};
            #pragma unroll
            for (int ii = 0; ii < 4; ii++) {
                ull ai = pack2(qf[ii], qf[ii]);
                s2[ii][0] = ffma2(ai, kv.x, s2[ii][0]);
                s2[ii][1] = ffma2(ai, kv.y, s2[ii][1]);
            }
        }
        float s[4][4];
        #pragma unroll
        for (int ii = 0; ii < 4; ii++) {
            unpack2(s2[ii][0], s[ii][0], s[ii][1]);
            unpack2(s2[ii][1], s[ii][2], s[ii][3]);
            #pragma unroll
            for (int jj = 0; jj < 4; jj++) s[ii][jj] *= 0.125f;
        }

        if (kt == qt) {
            #pragma unroll
            for (int ii = 0; ii < 4; ii++)
                #pragma unroll
                for (int jj = 0; jj < 4; jj++)
                    if (tx * 4 + jj > ty * 4 + ii) s[ii][jj] = -INFINITY;
        }

        #pragma unroll
        for (int ii = 0; ii < 4; ii++) {
            float rm = fmaxf(fmaxf(s[ii][0], s[ii][1]), fmaxf(s[ii][2], s[ii][3]));
            rm = fmaxf(rm, __shfl_xor_sync(0xffffffffu, rm, 8));
            rm = fmaxf(rm, __shfl_xor_sync(0xffffffffu, rm, 4));
            rm = fmaxf(rm, __shfl_xor_sync(0xffffffffu, rm, 2));
            rm = fmaxf(rm, __shfl_xor_sync(0xffffffffu, rm, 1));
            float mn = fmaxf(mrow[ii], rm);
            float alpha = __expf(mrow[ii] - mn);
            mrow[ii] = mn;
            float rs = 0.f;
            #pragma unroll
            for (int jj = 0; jj < 4; jj++) {
                float p = __expf(s[ii][jj] - mn);
                s[ii][jj] = p;
                rs += p;
            }
            rs += __shfl_xor_sync(0xffffffffu, rs, 8);
            rs += __shfl_xor_sync(0xffffffffu, rs, 4);
            rs += __shfl_xor_sync(0xffffffffu, rs, 2);
            rs += __shfl_xor_sync(0xffffffffu, rs, 1);
            lrow[ii] = lrow[ii] * alpha + rs;
            ull a2 = pack2(alpha, alpha);
            o2[ii][0] = fmul2(o2[ii][0], a2);
            o2[ii][1] = fmul2(o2[ii][1], a2);
        }

        __syncthreads();
        #pragma unroll
        for (int jj = 0; jj < 4; jj++) {
            float4 pv = make_float4(s[0][jj], s[1][jj], s[2][jj], s[3][jj]);
            *reinterpret_cast<float4*>(&KtP[(tx * 4 + jj) * 68 + ty * 4]) = pv;
        }
        __syncthreads();

        #pragma unroll 8
        for (int j = 0; j < 64; j++) {
            float4 pv = *reinterpret_cast<const float4*>(&KtP[j * 68 + ty * 4]);
            ulonglong2 vv = *reinterpret_cast<const ulonglong2*>(&Vs[j * 68 + tx * 4]);
            float pf[4] = {pv.x, pv.y, pv.z, pv.w};
            #pragma unroll
            for (int ii = 0; ii < 4; ii++) {
                ull ai = pack2(pf[ii], pf[ii]);
                o2[ii][0] = ffma2(ai, vv.x, o2[ii][0]);
                o2[ii][1] = ffma2(ai, vv.y, o2[ii][1]);
            }
        }
    }

    int b = bh >> 4, h = bh & 15;
    #pragma unroll
    for (int ii = 0; ii < 4; ii++) {
        float inv = 1.0f / lrow[ii];
        float o[4];
        unpack2(o2[ii][0], o[0], o[1]);
        unpack2(o2[ii][1], o[2], o[3]);
        int srow = qt * 64 + ty * 4 + ii;
        float4 ov = make_float4(o[0]*inv, o[1]*inv, o[2]*inv, o[3]*inv);
        *reinterpret_cast<float4*>(
            &g_attn[((size_t)(b * SEQ + srow)) * D_MODEL + h * 64 + tx * 4]) = ov;
    }
}

// ============================================================================
extern "C" void kernel_launch(void* const* d_in, const int* in_sizes, int n_in,
                              void* d_out, int out_size)
{
    const float* x  = (const float*)d_in[0];
    const float* Wq = (const float*)d_in[1];
    const float* bq = (const float*)d_in[2];
    const float* Wk = (const float*)d_in[3];
    const float* bk = (const float*)d_in[4];
    const float* Wv = (const float*)d_in[5];
    const float* bv = (const float*)d_in[6];
    const float* Wo = (const float*)d_in[7];
    const float* bo = (const float*)d_in[8];
    float* out = (float*)d_out;

    const int nx4 = M_TOT * D_MODEL / 4;     // 2M
    const int nw4 = D_MODEL * D_MODEL / 4;   // 256K

    split_kernel<<<nx4 / 256, 256>>>(x,  0, nx4);
    split_kernel<<<nw4 / 256, 256>>>(Wq, 1, nw4);
    split_kernel<<<nw4 / 256, 256>>>(Wk, 2, nw4);
    split_kernel<<<nw4 / 256, 256>>>(Wv, 3, nw4);
    split_kernel<<<nw4 / 256, 256>>>(Wo, 4, nw4);

    cudaFuncSetAttribute(gemm_mma_kernel,
                         cudaFuncAttributeMaxDynamicSharedMemorySize, GEMM_SMEM);

    dim3 gg(D_MODEL / 128, M_TOT / 128);     // (8, 64)
    gemm_mma_kernel<<<gg, 256, GEMM_SMEM>>>(0, bq, nullptr);
    gemm_mma_kernel<<<gg, 256, GEMM_SMEM>>>(1, bk, nullptr);
    gemm_mma_kernel<<<gg, 256, GEMM_SMEM>>>(2, bv, nullptr);

    const int attn_smem = 3 * 64 * 68 * 4;   // 52224 B
    cudaFuncSetAttribute(flash_attn_kernel,
                         cudaFuncAttributeMaxDynamicSharedMemorySize, attn_smem);
    flash_attn_kernel<<<dim3(SEQ / 64, BH), 256, attn_smem>>>();

    split_kernel<<<nx4 / 256, 256>>>(nullptr, 5, nx4);
    gemm_mma_kernel<<<gg, 256, GEMM_SMEM>>>(3, bo, out);
}

// round 7
// speedup vs baseline: 3.0260x; 1.8519x over previous
#include <cuda_runtime.h>
#include <cuda_bf16.h>
#include <math.h>
#include <stdint.h>

#define D_MODEL 1024
#define NHEAD   16
#define DKH     64
#define BATCH   4
#define SEQ     2048
#define M_TOT   (BATCH*SEQ)     // 8192
#define BH      (BATCH*NHEAD)   // 64

// ---- scratch (__device__ globals: allocation-free rule) ----
__device__ float g_attn[(size_t)M_TOT*D_MODEL];           // [B*S, D] pre-Wo (fp32)
// bf16 hi/lo split operands
__device__ __nv_bfloat16 g_xh[(size_t)M_TOT*D_MODEL];     // x
__device__ __nv_bfloat16 g_xl[(size_t)M_TOT*D_MODEL];
__device__ __nv_bfloat16 g_ah[(size_t)M_TOT*D_MODEL];     // attn out (for Wo gemm)
__device__ __nv_bfloat16 g_al[(size_t)M_TOT*D_MODEL];
__device__ __nv_bfloat16 g_wh[4][(size_t)D_MODEL*D_MODEL];
__device__ __nv_bfloat16 g_wl[4][(size_t)D_MODEL*D_MODEL];
// q/k/v in [B,H,S,dk], bf16 hi/lo (written by QKV gemm epilogue; q pre-scaled 1/8)
__device__ __nv_bfloat16 g_qh[(size_t)BH*SEQ*DKH];
__device__ __nv_bfloat16 g_ql[(size_t)BH*SEQ*DKH];
__device__ __nv_bfloat16 g_kh[(size_t)BH*SEQ*DKH];
__device__ __nv_bfloat16 g_kl[(size_t)BH*SEQ*DKH];
__device__ __nv_bfloat16 g_vh[(size_t)BH*SEQ*DKH];
__device__ __nv_bfloat16 g_vl[(size_t)BH*SEQ*DKH];

typedef unsigned long long ull;

__device__ __forceinline__ uint32_t smem_u32(const void* p) {
    uint32_t a;
    asm("{ .reg .u64 t; cvta.to.shared.u64 t, %1; cvt.u32.u64 %0, t; }" : "=r"(a) : "l"(p));
    return a;
}
__device__ __forceinline__ void ldsm4(uint32_t& r0, uint32_t& r1, uint32_t& r2, uint32_t& r3,
                                      uint32_t addr) {
    asm volatile("ldmatrix.sync.aligned.m8n8.x4.shared.b16 {%0,%1,%2,%3}, [%4];"
                 : "=r"(r0), "=r"(r1), "=r"(r2), "=r"(r3) : "r"(addr));
}
__device__ __forceinline__ void ldsm4t(uint32_t& r0, uint32_t& r1, uint32_t& r2, uint32_t& r3,
                                       uint32_t addr) {
    asm volatile("ldmatrix.sync.aligned.m8n8.x4.trans.shared.b16 {%0,%1,%2,%3}, [%4];"
                 : "=r"(r0), "=r"(r1), "=r"(r2), "=r"(r3) : "r"(addr));
}
__device__ __forceinline__ void mma16816(float* c, const uint32_t* a, const uint32_t* b) {
    asm volatile(
        "mma.sync.aligned.m16n8k16.row.col.f32.bf16.bf16.f32 "
        "{%0,%1,%2,%3}, {%4,%5,%6,%7}, {%8,%9}, {%0,%1,%2,%3};"
        : "+f"(c[0]), "+f"(c[1]), "+f"(c[2]), "+f"(c[3])
        : "r"(a[0]), "r"(a[1]), "r"(a[2]), "r"(a[3]), "r"(b[0]), "r"(b[1]));
}
// pack two f32 -> bf16x2 (e0 in low half)
__device__ __forceinline__ uint32_t packbf(float e0, float e1) {
    uint32_t r; asm("cvt.rn.bf16x2.f32 %0, %1, %2;" : "=r"(r) : "f"(e1), "f"(e0)); return r;
}

// ============================================================================
// split fp32 -> bf16 (hi, lo).  which: 0=x, 1..4=W[q,k,v,o], 5=g_attn
// ============================================================================
__global__ void split_kernel(const float* __restrict__ in, int which, int n4)
{
    __nv_bfloat16 *hi, *lo;
    if (which == 0)      { hi = g_xh; lo = g_xl; }
    else if (which <= 4) { hi = g_wh[which-1]; lo = g_wl[which-1]; }
    else                 { hi = g_ah; lo = g_al; }
    const float* src = (which == 5) ? g_attn : in;

    int i = blockIdx.x * blockDim.x + threadIdx.x;
    if (i >= n4) return;
    float4 v = reinterpret_cast<const float4*>(src)[i];
    __nv_bfloat16 h[4], l[4];
    float f[4] = {v.x, v.y, v.z, v.w};
    #pragma unroll
    for (int j = 0; j < 4; ++j) {
        h[j] = __float2bfloat16(f[j]);
        l[j] = __float2bfloat16(f[j] - __bfloat162float(h[j]));
    }
    reinterpret_cast<ull*>(hi)[i] = *reinterpret_cast<ull*>(h);
    reinterpret_cast<ull*>(lo)[i] = *reinterpret_cast<ull*>(l);
}

// ============================================================================
// mma.sync 3xbf16 GEMM (validated R6).  modes 0-2: epilogue writes bf16 hi/lo
// q/k/v in [B,H,S,dk] (mode 0 scaled by 0.125).  mode 3: fp32 out + bias.
// ============================================================================
#define GTILE_B 8192
#define GSTAGE_B (4 * GTILE_B)
#define GEMM_SMEM (2 * GSTAGE_B)     // 65536

__device__ __forceinline__ void load_chunk(
    uint32_t sstage, const __nv_bfloat16* Ah, const __nv_bfloat16* Al,
    const __nv_bfloat16* Bh, const __nv_bfloat16* Bl,
    int m0, int n0, int k0, int tid)
{
    const __nv_bfloat16* srcs[4] = {Ah, Al, Bh, Bl};
    const int bases[4] = {m0, m0, n0, n0};
    #pragma unroll
    for (int t = 0; t < 4; ++t) {
        #pragma unroll
        for (int i = 0; i < 2; ++i) {
            int idx = tid + i * 256;
            int row = idx >> 2, kc = idx & 3;
            const void* g = srcs[t] + (size_t)(bases[t] + row) * D_MODEL + k0 + kc * 8;
            uint32_t s = sstage + t * GTILE_B + row * 64 + ((kc ^ ((row >> 1) & 3)) * 16);
            asm volatile("cp.async.cg.shared.global [%0], [%1], 16;" :: "r"(s), "l"(g));
        }
    }
}

__global__ __launch_bounds__(256, 1)
void gemm_mma_kernel(int mode, const float* __restrict__ bias, float* __restrict__ outp)
{
    extern __shared__ __align__(128) char smem[];
    const uint32_t sb = smem_u32(smem);

    const __nv_bfloat16* Ah = (mode == 3) ? g_ah : g_xh;
    const __nv_bfloat16* Al = (mode == 3) ? g_al : g_xl;
    const __nv_bfloat16* Bh = g_wh[mode];
    const __nv_bfloat16* Bl = g_wl[mode];

    const int tid = threadIdx.x, wid = tid >> 5, lane = tid & 31;
    const int m0 = blockIdx.y * 128, n0 = blockIdx.x * 128;
    const int mw = (wid & 3) * 32, nw = (wid >> 2) * 64;
    const int mid = lane >> 3, lrow = lane & 7;

    float acc[2][8][4];
    #pragma unroll
    for (int im = 0; im < 2; ++im)
        #pragma unroll
        for (int jn = 0; jn < 8; ++jn)
            #pragma unroll
            for (int r = 0; r < 4; ++r) acc[im][jn][r] = 0.f;

    load_chunk(sb, Ah, Al, Bh, Bl, m0, n0, 0, tid);
    asm volatile("cp.async.commit_group;" ::: "memory");

    const int NCH = D_MODEL / 32;
    for (int c = 0; c < NCH; ++c) {
        const uint32_t sstage = sb + (c & 1) * GSTAGE_B;
        if (c + 1 < NCH) {
            load_chunk(sb + ((c + 1) & 1) * GSTAGE_B, Ah, Al, Bh, Bl, m0, n0, (c + 1) * 32, tid);
            asm volatile("cp.async.commit_group;" ::: "memory");
            asm volatile("cp.async.wait_group 1;" ::: "memory");
        } else {
            asm volatile("cp.async.wait_group 0;" ::: "memory");
        }
        __syncthreads();

        #pragma unroll
        for (int s = 0; s < 2; ++s) {
            uint32_t ah[2][4], al[2][4], bh[8][2], bl[8][2];
            #pragma unroll
            for (int im = 0; im < 2; ++im) {
                int row = mw + im * 16 + ((mid & 1) << 3) + lrow;
                int kc  = 2 * s + (mid >> 1);
                uint32_t addr = sstage + row * 64 + ((kc ^ ((row >> 1) & 3)) * 16);
                ldsm4(ah[im][0], ah[im][1], ah[im][2], ah[im][3], addr);
                ldsm4(al[im][0], al[im][1], al[im][2], al[im][3], addr + GTILE_B);
            }
            #pragma unroll
            for (int jp = 0; jp < 4; ++jp) {
                int row = nw + jp * 16 + ((mid >> 1) << 3) + lrow;
                int kc  = 2 * s + (mid & 1);
                uint32_t addr = sstage + 2 * GTILE_B + row * 64 + ((kc ^ ((row >> 1) & 3)) * 16);
                ldsm4(bh[2*jp][0], bh[2*jp][1], bh[2*jp+1][0], bh[2*jp+1][1], addr);
                ldsm4(bl[2*jp][0], bl[2*jp][1], bl[2*jp+1][0], bl[2*jp+1][1], addr + GTILE_B);
            }
            #pragma unroll
            for (int im = 0; im < 2; ++im)
                #pragma unroll
                for (int jn = 0; jn < 8; ++jn) {
                    mma16816(acc[im][jn], ah[im], bh[jn]);
                    mma16816(acc[im][jn], ah[im], bl[jn]);
                    mma16816(acc[im][jn], al[im], bh[jn]);
                }
        }
        __syncthreads();
    }

    const int g = lane >> 2, t = lane & 3;
    const float sc = (mode == 0) ? 0.125f : 1.0f;
    __nv_bfloat16* oh = (mode == 0) ? g_qh : (mode == 1) ? g_kh : g_vh;
    __nv_bfloat16* ol = (mode == 0) ? g_ql : (mode == 1) ? g_kl : g_vl;

    #pragma unroll
    for (int im = 0; im < 2; ++im) {
        #pragma unroll
        for (int jn = 0; jn < 8; ++jn) {
            int r0 = m0 + mw + im * 16 + g;
            int cc = n0 + nw + jn * 8 + 2 * t;
            float2 b2 = *reinterpret_cast<const float2*>(bias + cc);
            float v00 = (acc[im][jn][0] + b2.x) * sc, v01 = (acc[im][jn][1] + b2.y) * sc;
            float v10 = (acc[im][jn][2] + b2.x) * sc, v11 = (acc[im][jn][3] + b2.y) * sc;
            if (mode < 3) {
                int h = cc >> 6, d = cc & 63;
                #pragma unroll
                for (int rr = 0; rr < 2; ++rr) {
                    int r = r0 + rr * 8;
                    float e0 = rr ? v10 : v00, e1 = rr ? v11 : v01;
                    int b = r >> 11, srow = r & (SEQ - 1);
                    size_t idx = (((size_t)(b * NHEAD + h)) * SEQ + srow) * DKH + d;
                    uint32_t hp = packbf(e0, e1);
                    float h0 = __uint_as_float(hp << 16);
                    float h1 = __uint_as_float(hp & 0xffff0000u);
                    uint32_t lp = packbf(e0 - h0, e1 - h1);
                    *reinterpret_cast<uint32_t*>(oh + idx) = hp;
                    *reinterpret_cast<uint32_t*>(ol + idx) = lp;
                }
            } else {
                *reinterpret_cast<float2*>(outp + (size_t)r0 * D_MODEL + cc) = make_float2(v00, v01);
                *reinterpret_cast<float2*>(outp + (size_t)(r0+8) * D_MODEL + cc) = make_float2(v10, v11);
            }
        }
    }
}

// ============================================================================
// Flash attention via mma.sync 3xbf16.  CTA = 128 queries x one (b,h).
// smem: Qh 16K, Ql 16K, 2 stages x (Kh,Kl,Vh,Vl) 8K each = 96KB.
// rows of 64 bf16 = 128B, swizzle: chunk ^= (row & 7).
// ============================================================================
#define AT_SMEM 98304

__device__ __forceinline__ void load_kv(uint32_t sstage, size_t hoff, int kt, int tid)
{
    const __nv_bfloat16* srcs[4] = { g_kh + hoff, g_kl + hoff, g_vh + hoff, g_vl + hoff };
    #pragma unroll
    for (int tI = 0; tI < 4; ++tI)
        #pragma unroll
        for (int i = 0; i < 2; ++i) {
            int idx = tid + i * 256;
            int row = idx >> 3, c = idx & 7;
            const void* gsrc = srcs[tI] + (size_t)(kt * 64 + row) * DKH + c * 8;
            uint32_t d = sstage + tI * 8192 + row * 128 + ((c ^ (row & 7)) * 16);
            asm volatile("cp.async.cg.shared.global [%0], [%1], 16;" :: "r"(d), "l"(gsrc));
        }
}

__global__ __launch_bounds__(256)
void flash_mma_kernel()
{
    extern __shared__ __align__(128) char smem[];
    const uint32_t sb = smem_u32(smem);
    const uint32_t sQh = sb, sQl = sb + 16384, sKV = sb + 32768;

    const int tid = threadIdx.x, wid = tid >> 5, lane = tid & 31;
    const int mid = lane >> 3, lrow = lane & 7;
    const int g = lane >> 2, t = lane & 3;
    const int bh = blockIdx.x;
    const int qt = (int)(gridDim.y - 1 - blockIdx.y);   // heavy tiles first
    const int qbase = qt * 128;
    const size_t hoff = (size_t)bh * SEQ * DKH;
    const int nkt = 2 * qt + 2;

    // Q hi/lo (group 0 together with KV0)
    {
        const __nv_bfloat16* srcs[2] = { g_qh + hoff, g_ql + hoff };
        const uint32_t dsts[2] = { sQh, sQl };
        #pragma unroll
        for (int tI = 0; tI < 2; ++tI)
            #pragma unroll
            for (int i = 0; i < 4; ++i) {
                int idx = tid + i * 256;
                int row = idx >> 3, c = idx & 7;
                const void* gsrc = srcs[tI] + (size_t)(qbase + row) * DKH + c * 8;
                uint32_t d = dsts[tI] + row * 128 + ((c ^ (row & 7)) * 16);
                asm volatile("cp.async.cg.shared.global [%0], [%1], 16;" :: "r"(d), "l"(gsrc));
            }
    }
    load_kv(sKV, hoff, 0, tid);
    asm volatile("cp.async.commit_group;" ::: "memory");
    load_kv(sKV + 32768, hoff, 1, tid);     // nkt >= 2 always
    asm volatile("cp.async.commit_group;" ::: "memory");

    float oacc[8][4];
    #pragma unroll
    for (int jn = 0; jn < 8; ++jn)
        #pragma unroll
        for (int r = 0; r < 4; ++r) oacc[jn][r] = 0.f;
    float mrow[2] = {-INFINITY, -INFINITY};
    float lsum[2] = {0.f, 0.f};
    uint32_t qh[4][4];

    for (int kt = 0; kt < nkt; ++kt) {
        if (kt + 1 < nkt) asm volatile("cp.async.wait_group 1;" ::: "memory");
        else              asm volatile("cp.async.wait_group 0;" ::: "memory");
        __syncthreads();

        if (kt == 0) {
            #pragma unroll
            for (int s = 0; s < 4; ++s) {
                int row = wid * 16 + ((mid & 1) << 3) + lrow;
                int kc = 2 * s + (mid >> 1);
                uint32_t a = sQh + row * 128 + ((kc ^ (row & 7)) * 16);
                ldsm4(qh[s][0], qh[s][1], qh[s][2], qh[s][3], a);
            }
        }

        const uint32_t sKh = sKV + (kt & 1) * 32768;
        const uint32_t sKl = sKh + 8192, sVh = sKh + 16384, sVl = sKh + 24576;

        // ---- S = (q/8) K^T : 3 passes ----
        float sacc[8][4];
        #pragma unroll
        for (int jn = 0; jn < 8; ++jn)
            #pragma unroll
            for (int r = 0; r < 4; ++r) sacc[jn][r] = 0.f;

        #pragma unroll
        for (int s = 0; s < 4; ++s) {
            uint32_t kb[8][2];
            #pragma unroll
            for (int jp = 0; jp < 4; ++jp) {
                int row = jp * 16 + ((mid >> 1) << 3) + lrow;
                int kc = 2 * s + (mid & 1);
                uint32_t a = sKh + row * 128 + ((kc ^ (row & 7)) * 16);
                ldsm4(kb[2*jp][0], kb[2*jp][1], kb[2*jp+1][0], kb[2*jp+1][1], a);
            }
            #pragma unroll
            for (int jn = 0; jn < 8; ++jn) mma16816(sacc[jn], qh[s], kb[jn]);   // qh*kh
            uint32_t qlf[4];
            {
                int row = wid * 16 + ((mid & 1) << 3) + lrow;
                int kc = 2 * s + (mid >> 1);
                uint32_t a = sQl + row * 128 + ((kc ^ (row & 7)) * 16);
                ldsm4(qlf[0], qlf[1], qlf[2], qlf[3], a);
            }
            #pragma unroll
            for (int jn = 0; jn < 8; ++jn) mma16816(sacc[jn], qlf, kb[jn]);     // ql*kh
            #pragma unroll
            for (int jp = 0; jp < 4; ++jp) {
                int row = jp * 16 + ((mid >> 1) << 3) + lrow;
                int kc = 2 * s + (mid & 1);
                uint32_t a = sKl + row * 128 + ((kc ^ (row & 7)) * 16);
                ldsm4(kb[2*jp][0], kb[2*jp][1], kb[2*jp+1][0], kb[2*jp+1][1], a);
            }
            #pragma unroll
            for (int jn = 0; jn < 8; ++jn) mma16816(sacc[jn], qh[s], kb[jn]);   // qh*kl
        }

        // ---- causal mask (only last two key tiles can clip) ----
        if (kt >= 2 * qt) {
            int q0 = qbase + wid * 16 + g;
            #pragma unroll
            for (int jn = 0; jn < 8; ++jn) {
                int j0 = kt * 64 + jn * 8 + 2 * t;
                if (j0     > q0)     sacc[jn][0] = -INFINITY;
                if (j0 + 1 > q0)     sacc[jn][1] = -INFINITY;
                if (j0     > q0 + 8) sacc[jn][2] = -INFINITY;
                if (j0 + 1 > q0 + 8) sacc[jn][3] = -INFINITY;
            }
        }

        // ---- online softmax: rows g (c0,c1) and g+8 (c2,c3); 4 lanes/row ----
        #pragma unroll
        for (int hf = 0; hf < 2; ++hf) {
            float mx = -INFINITY;
            #pragma unroll
            for (int jn = 0; jn < 8; ++jn)
                mx = fmaxf(mx, fmaxf(sacc[jn][2*hf], sacc[jn][2*hf+1]));
            mx = fmaxf(mx, __shfl_xor_sync(0xffffffffu, mx, 1));
            mx = fmaxf(mx, __shfl_xor_sync(0xffffffffu, mx, 2));
            float mn = fmaxf(mrow[hf], mx);
            float al = __expf(mrow[hf] - mn);
            mrow[hf] = mn;
            float sum = 0.f;
            #pragma unroll
            for (int jn = 0; jn < 8; ++jn) {
                float p0 = __expf(sacc[jn][2*hf]   - mn);
                float p1 = __expf(sacc[jn][2*hf+1] - mn);
                sacc[jn][2*hf] = p0; sacc[jn][2*hf+1] = p1;
                sum += p0 + p1;
            }
            sum += __shfl_xor_sync(0xffffffffu, sum, 1);
            sum += __shfl_xor_sync(0xffffffffu, sum, 2);
            lsum[hf] = lsum[hf] * al + sum;
            #pragma unroll
            for (int jn = 0; jn < 8; ++jn) { oacc[jn][2*hf] *= al; oacc[jn][2*hf+1] *= al; }
        }

        // ---- O += P V : P split in registers, V hi/lo from smem (trans) ----
        #pragma unroll
        for (int s = 0; s < 4; ++s) {
            uint32_t ph[4], pl[4];
            #pragma unroll
            for (int r = 0; r < 4; ++r) {
                int tile = 2 * s + (r >> 1);
                int c0 = (r & 1) * 2;
                float p0 = sacc[tile][c0], p1 = sacc[tile][c0 + 1];
                uint32_t hp = packbf(p0, p1);
                float h0 = __uint_as_float(hp << 16);
                float h1 = __uint_as_float(hp & 0xffff0000u);
                ph[r] = hp;
                pl[r] = packbf(p0 - h0, p1 - h1);
            }
            uint32_t vb[8][2];
            #pragma unroll
            for (int jp = 0; jp < 4; ++jp) {
                int row = 16 * s + ((mid & 1) << 3) + lrow;
                int c = 2 * jp + (mid >> 1);
                uint32_t a = sVh + row * 128 + ((c ^ (row & 7)) * 16);
                ldsm4t(vb[2*jp][0], vb[2*jp][1], vb[2*jp+1][0], vb[2*jp+1][1], a);
            }
            #pragma unroll
            for (int jn = 0; jn < 8; ++jn) mma16816(oacc[jn], ph, vb[jn]);   // ph*vh
            #pragma unroll
            for (int jn = 0; jn < 8; ++jn) mma16816(oacc[jn], pl, vb[jn]);   // pl*vh
            #pragma unroll
            for (int jp = 0; jp < 4; ++jp) {
                int row = 16 * s + ((mid & 1) << 3) + lrow;
                int c = 2 * jp + (mid >> 1);
                uint32_t a = sVl + row * 128 + ((c ^ (row & 7)) * 16);
                ldsm4t(vb[2*jp][0], vb[2*jp][1], vb[2*jp+1][0], vb[2*jp+1][1], a);
            }
            #pragma unroll
            for (int jn = 0; jn < 8; ++jn) mma16816(oacc[jn], ph, vb[jn]);   // ph*vl
        }

        __syncthreads();
        if (kt + 2 < nkt) {
            load_kv(sKV + (kt & 1) * 32768, hoff, kt + 2, tid);
            asm volatile("cp.async.commit_group;" ::: "memory");
        }
    }

    // ---- normalize + write [B,S,H*dk] fp32 ----
    const int b = bh >> 4, h = bh & 15;
    #pragma unroll
    for (int hf = 0; hf < 2; ++hf) {
        float inv = 1.0f / lsum[hf];
        int row = qbase + wid * 16 + g + 8 * hf;
        float* dst = g_attn + ((size_t)(b * SEQ + row)) * D_MODEL + h * 64;
        #pragma unroll
        for (int jn = 0; jn < 8; ++jn) {
            float2 v = make_float2(oacc[jn][2*hf] * inv, oacc[jn][2*hf+1] * inv);
            *reinterpret_cast<float2*>(dst + jn * 8 + 2 * t) = v;
        }
    }
}

// ============================================================================
extern "C" void kernel_launch(void* const* d_in, const int* in_sizes, int n_in,
                              void* d_out, int out_size)
{
    const float* x  = (const float*)d_in[0];
    const float* Wq = (const float*)d_in[1];
    const float* bq = (const float*)d_in[2];
    const float* Wk = (const float*)d_in[3];
    const float* bk = (const float*)d_in[4];
    const float* Wv = (const float*)d_in[5];
    const float* bv = (const float*)d_in[6];
    const float* Wo = (const float*)d_in[7];
    const float* bo = (const float*)d_in[8];
    float* out = (float*)d_out;

    const int nx4 = M_TOT * D_MODEL / 4;
    const int nw4 = D_MODEL * D_MODEL / 4;

    split_kernel<<<nx4 / 256, 256>>>(x,  0, nx4);
    split_kernel<<<nw4 / 256, 256>>>(Wq, 1, nw4);
    split_kernel<<<nw4 / 256, 256>>>(Wk, 2, nw4);
    split_kernel<<<nw4 / 256, 256>>>(Wv, 3, nw4);
    split_kernel<<<nw4 / 256, 256>>>(Wo, 4, nw4);

    cudaFuncSetAttribute(gemm_mma_kernel,
                         cudaFuncAttributeMaxDynamicSharedMemorySize, GEMM_SMEM);

    dim3 gg(D_MODEL / 128, M_TOT / 128);
    gemm_mma_kernel<<<gg, 256, GEMM_SMEM>>>(0, bq, nullptr);
    gemm_mma_kernel<<<gg, 256, GEMM_SMEM>>>(1, bk, nullptr);
    gemm_mma_kernel<<<gg, 256, GEMM_SMEM>>>(2, bv, nullptr);

    cudaFuncSetAttribute(flash_mma_kernel,
                         cudaFuncAttributeMaxDynamicSharedMemorySize, AT_SMEM);
    flash_mma_kernel<<<dim3(BH, SEQ / 128), 256, AT_SMEM>>>();

    split_kernel<<<nx4 / 256, 256>>>(nullptr, 5, nx4);
    gemm_mma_kernel<<<gg, 256, GEMM_SMEM>>>(3, bo, out);
}

// round 8
// speedup vs baseline: 3.3613x; 1.1108x over previous
#include <cuda_runtime.h>
#include <cuda_bf16.h>
#include <math.h>
#include <stdint.h>

#define D_MODEL 1024
#define NHEAD   16
#define DKH     64
#define BATCH   4
#define SEQ     2048
#define M_TOT   (BATCH*SEQ)     // 8192
#define BH      (BATCH*NHEAD)   // 64

// ---- scratch (__device__ globals: allocation-free rule) ----
__device__ __nv_bfloat16 g_xh[(size_t)M_TOT*D_MODEL];     // x hi/lo
__device__ __nv_bfloat16 g_xl[(size_t)M_TOT*D_MODEL];
__device__ __nv_bfloat16 g_ah[(size_t)M_TOT*D_MODEL];     // attn out hi/lo (flash writes)
__device__ __nv_bfloat16 g_al[(size_t)M_TOT*D_MODEL];
__device__ __nv_bfloat16 g_wh[4][(size_t)D_MODEL*D_MODEL];
__device__ __nv_bfloat16 g_wl[4][(size_t)D_MODEL*D_MODEL];
// q/k/v in [B,H,S,dk], bf16 hi/lo (QKV gemm epilogue; q pre-scaled 1/8)
__device__ __nv_bfloat16 g_qh[(size_t)BH*SEQ*DKH];
__device__ __nv_bfloat16 g_ql[(size_t)BH*SEQ*DKH];
__device__ __nv_bfloat16 g_kh[(size_t)BH*SEQ*DKH];
__device__ __nv_bfloat16 g_kl[(size_t)BH*SEQ*DKH];
__device__ __nv_bfloat16 g_vh[(size_t)BH*SEQ*DKH];
__device__ __nv_bfloat16 g_vl[(size_t)BH*SEQ*DKH];

typedef unsigned long long ull;

__device__ __forceinline__ uint32_t smem_u32(const void* p) {
    uint32_t a;
    asm("{ .reg .u64 t; cvta.to.shared.u64 t, %1; cvt.u32.u64 %0, t; }" : "=r"(a) : "l"(p));
    return a;
}
__device__ __forceinline__ void ldsm4(uint32_t& r0, uint32_t& r1, uint32_t& r2, uint32_t& r3,
                                      uint32_t addr) {
    asm volatile("ldmatrix.sync.aligned.m8n8.x4.shared.b16 {%0,%1,%2,%3}, [%4];"
                 : "=r"(r0), "=r"(r1), "=r"(r2), "=r"(r3) : "r"(addr));
}
__device__ __forceinline__ void ldsm4t(uint32_t& r0, uint32_t& r1, uint32_t& r2, uint32_t& r3,
                                       uint32_t addr) {
    asm volatile("ldmatrix.sync.aligned.m8n8.x4.trans.shared.b16 {%0,%1,%2,%3}, [%4];"
                 : "=r"(r0), "=r"(r1), "=r"(r2), "=r"(r3) : "r"(addr));
}
__device__ __forceinline__ void mma16816(float* c, const uint32_t* a, const uint32_t* b) {
    asm volatile(
        "mma.sync.aligned.m16n8k16.row.col.f32.bf16.bf16.f32 "
        "{%0,%1,%2,%3}, {%4,%5,%6,%7}, {%8,%9}, {%0,%1,%2,%3};"
        : "+f"(c[0]), "+f"(c[1]), "+f"(c[2]), "+f"(c[3])
        : "r"(a[0]), "r"(a[1]), "r"(a[2]), "r"(a[3]), "r"(b[0]), "r"(b[1]));
}
// pack two f32 -> bf16x2 (e0 in low half)
__device__ __forceinline__ uint32_t packbf(float e0, float e1) {
    uint32_t r; asm("cvt.rn.bf16x2.f32 %0, %1, %2;" : "=r"(r) : "f"(e1), "f"(e0)); return r;
}

// ============================================================================
// splits: x -> g_xh/g_xl;  4 weights in one launch (blockIdx.y = which)
// ============================================================================
__global__ void split_x_kernel(const float* __restrict__ in, int n4)
{
    int i = blockIdx.x * blockDim.x + threadIdx.x;
    if (i >= n4) return;
    float4 v = reinterpret_cast<const float4*>(in)[i];
    __nv_bfloat16 h[4], l[4];
    float f[4] = {v.x, v.y, v.z, v.w};
    #pragma unroll
    for (int j = 0; j < 4; ++j) {
        h[j] = __float2bfloat16(f[j]);
        l[j] = __float2bfloat16(f[j] - __bfloat162float(h[j]));
    }
    reinterpret_cast<ull*>(g_xh)[i] = *reinterpret_cast<ull*>(h);
    reinterpret_cast<ull*>(g_xl)[i] = *reinterpret_cast<ull*>(l);
}

__global__ void split_w4_kernel(const float* __restrict__ W0, const float* __restrict__ W1,
                                const float* __restrict__ W2, const float* __restrict__ W3,
                                int n4)
{
    int which = blockIdx.y;
    const float* src = (which == 0) ? W0 : (which == 1) ? W1 : (which == 2) ? W2 : W3;
    int i = blockIdx.x * blockDim.x + threadIdx.x;
    if (i >= n4) return;
    float4 v = reinterpret_cast<const float4*>(src)[i];
    __nv_bfloat16 h[4], l[4];
    float f[4] = {v.x, v.y, v.z, v.w};
    #pragma unroll
    for (int j = 0; j < 4; ++j) {
        h[j] = __float2bfloat16(f[j]);
        l[j] = __float2bfloat16(f[j] - __bfloat162float(h[j]));
    }
    reinterpret_cast<ull*>(g_wh[which])[i] = *reinterpret_cast<ull*>(h);
    reinterpret_cast<ull*>(g_wl[which])[i] = *reinterpret_cast<ull*>(l);
}

// ============================================================================
// mma.sync 3xbf16 GEMM.  mode = (mode_base==3) ? 3 : blockIdx.z.
// 3-stage cp.async ring, single __syncthreads per chunk.
// modes 0-2: bf16 hi/lo q/k/v epilogue (mode 0 scaled 1/8); mode 3: fp32+bias.
// ============================================================================
#define GTILE_B 8192
#define GSTAGE_B (4 * GTILE_B)
#define GEMM_SMEM (3 * GSTAGE_B)     // 98304

__device__ __forceinline__ void load_chunk(
    uint32_t sstage, const __nv_bfloat16* Ah, const __nv_bfloat16* Al,
    const __nv_bfloat16* Bh, const __nv_bfloat16* Bl,
    int m0, int n0, int k0, int tid)
{
    const __nv_bfloat16* srcs[4] = {Ah, Al, Bh, Bl};
    const int bases[4] = {m0, m0, n0, n0};
    #pragma unroll
    for (int t = 0; t < 4; ++t) {
        #pragma unroll
        for (int i = 0; i < 2; ++i) {
            int idx = tid + i * 256;
            int row = idx >> 2, kc = idx & 3;
            const void* g = srcs[t] + (size_t)(bases[t] + row) * D_MODEL + k0 + kc * 8;
            uint32_t s = sstage + t * GTILE_B + row * 64 + ((kc ^ ((row >> 1) & 3)) * 16);
            asm volatile("cp.async.cg.shared.global [%0], [%1], 16;" :: "r"(s), "l"(g));
        }
    }
}

__global__ __launch_bounds__(256, 1)
void gemm_mma_kernel(int mode_base, const float* __restrict__ b0,
                     const float* __restrict__ b1, const float* __restrict__ b2,
                     float* __restrict__ outp)
{
    extern __shared__ __align__(128) char smem[];
    const uint32_t sb = smem_u32(smem);

    const int mode = (mode_base == 3) ? 3 : (int)blockIdx.z;
    const float* bias = (mode == 1) ? b1 : (mode == 2) ? b2 : b0;
    const __nv_bfloat16* Ah = (mode == 3) ? g_ah : g_xh;
    const __nv_bfloat16* Al = (mode == 3) ? g_al : g_xl;
    const __nv_bfloat16* Bh = g_wh[mode];
    const __nv_bfloat16* Bl = g_wl[mode];

    const int tid = threadIdx.x, wid = tid >> 5, lane = tid & 31;
    const int m0 = blockIdx.y * 128, n0 = blockIdx.x * 128;
    const int mw = (wid & 3) * 32, nw = (wid >> 2) * 64;
    const int mid = lane >> 3, lrow = lane & 7;

    float acc[2][8][4];
    #pragma unroll
    for (int im = 0; im < 2; ++im)
        #pragma unroll
        for (int jn = 0; jn < 8; ++jn)
            #pragma unroll
            for (int r = 0; r < 4; ++r) acc[im][jn][r] = 0.f;

    // prologue: chunks 0,1 -> stages 0,1
    load_chunk(sb, Ah, Al, Bh, Bl, m0, n0, 0, tid);
    asm volatile("cp.async.commit_group;" ::: "memory");
    load_chunk(sb + GSTAGE_B, Ah, Al, Bh, Bl, m0, n0, 32, tid);
    asm volatile("cp.async.commit_group;" ::: "memory");

    const int NCH = D_MODEL / 32;   // 32
    for (int c = 0; c < NCH; ++c) {
        const uint32_t sstage = sb + (c % 3) * GSTAGE_B;
        if (c + 1 < NCH) asm volatile("cp.async.wait_group 1;" ::: "memory");
        else             asm volatile("cp.async.wait_group 0;" ::: "memory");
        __syncthreads();   // single barrier per chunk (3-stage ring)

        #pragma unroll
        for (int s = 0; s < 2; ++s) {
            uint32_t ah[2][4], al[2][4], bh[8][2], bl[8][2];
            #pragma unroll
            for (int im = 0; im < 2; ++im) {
                int row = mw + im * 16 + ((mid & 1) << 3) + lrow;
                int kc  = 2 * s + (mid >> 1);
                uint32_t addr = sstage + row * 64 + ((kc ^ ((row >> 1) & 3)) * 16);
                ldsm4(ah[im][0], ah[im][1], ah[im][2], ah[im][3], addr);
                ldsm4(al[im][0], al[im][1], al[im][2], al[im][3], addr + GTILE_B);
            }
            #pragma unroll
            for (int jp = 0; jp < 4; ++jp) {
                int row = nw + jp * 16 + ((mid >> 1) << 3) + lrow;
                int kc  = 2 * s + (mid & 1);
                uint32_t addr = sstage + 2 * GTILE_B + row * 64 + ((kc ^ ((row >> 1) & 3)) * 16);
                ldsm4(bh[2*jp][0], bh[2*jp][1], bh[2*jp+1][0], bh[2*jp+1][1], addr);
                ldsm4(bl[2*jp][0], bl[2*jp][1], bl[2*jp+1][0], bl[2*jp+1][1], addr + GTILE_B);
            }
            #pragma unroll
            for (int im = 0; im < 2; ++im)
                #pragma unroll
                for (int jn = 0; jn < 8; ++jn) {
                    mma16816(acc[im][jn], ah[im], bh[jn]);
                    mma16816(acc[im][jn], ah[im], bl[jn]);
                    mma16816(acc[im][jn], al[im], bh[jn]);
                }
        }
        if (c + 2 < NCH) {   // stage (c+2)%3 not read this iteration; safe post-sync
            load_chunk(sb + ((c + 2) % 3) * GSTAGE_B, Ah, Al, Bh, Bl, m0, n0, (c + 2) * 32, tid);
            asm volatile("cp.async.commit_group;" ::: "memory");
        }
    }

    const int g = lane >> 2, t = lane & 3;
    const float sc = (mode == 0) ? 0.125f : 1.0f;
    __nv_bfloat16* oh = (mode == 0) ? g_qh : (mode == 1) ? g_kh : g_vh;
    __nv_bfloat16* ol = (mode == 0) ? g_ql : (mode == 1) ? g_kl : g_vl;

    #pragma unroll
    for (int im = 0; im < 2; ++im) {
        #pragma unroll
        for (int jn = 0; jn < 8; ++jn) {
            int r0 = m0 + mw + im * 16 + g;
            int cc = n0 + nw + jn * 8 + 2 * t;
            float2 b2v = *reinterpret_cast<const float2*>(bias + cc);
            float v00 = (acc[im][jn][0] + b2v.x) * sc, v01 = (acc[im][jn][1] + b2v.y) * sc;
            float v10 = (acc[im][jn][2] + b2v.x) * sc, v11 = (acc[im][jn][3] + b2v.y) * sc;
            if (mode < 3) {
                int h = cc >> 6, d = cc & 63;
                #pragma unroll
                for (int rr = 0; rr < 2; ++rr) {
                    int r = r0 + rr * 8;
                    float e0 = rr ? v10 : v00, e1 = rr ? v11 : v01;
                    int b = r >> 11, srow = r & (SEQ - 1);
                    size_t idx = (((size_t)(b * NHEAD + h)) * SEQ + srow) * DKH + d;
                    uint32_t hp = packbf(e0, e1);
                    float h0 = __uint_as_float(hp << 16);
                    float h1 = __uint_as_float(hp & 0xffff0000u);
                    uint32_t lp = packbf(e0 - h0, e1 - h1);
                    *reinterpret_cast<uint32_t*>(oh + idx) = hp;
                    *reinterpret_cast<uint32_t*>(ol + idx) = lp;
                }
            } else {
                *reinterpret_cast<float2*>(outp + (size_t)r0 * D_MODEL + cc) = make_float2(v00, v01);
                *reinterpret_cast<float2*>(outp + (size_t)(r0+8) * D_MODEL + cc) = make_float2(v10, v11);
            }
        }
    }
}

// ============================================================================
// Flash attention via mma.sync 3xbf16 (validated R7).  Epilogue now emits
// bf16 hi/lo directly into g_ah/g_al (no fp32 roundtrip, no post split).
// ============================================================================
#define AT_SMEM 98304

__device__ __forceinline__ void load_kv(uint32_t sstage, size_t hoff, int kt, int tid)
{
    const __nv_bfloat16* srcs[4] = { g_kh + hoff, g_kl + hoff, g_vh + hoff, g_vl + hoff };
    #pragma unroll
    for (int tI = 0; tI < 4; ++tI)
        #pragma unroll
        for (int i = 0; i < 2; ++i) {
            int idx = tid + i * 256;
            int row = idx >> 3, c = idx & 7;
            const void* gsrc = srcs[tI] + (size_t)(kt * 64 + row) * DKH + c * 8;
            uint32_t d = sstage + tI * 8192 + row * 128 + ((c ^ (row & 7)) * 16);
            asm volatile("cp.async.cg.shared.global [%0], [%1], 16;" :: "r"(d), "l"(gsrc));
        }
}

__global__ __launch_bounds__(256)
void flash_mma_kernel()
{
    extern __shared__ __align__(128) char smem[];
    const uint32_t sb = smem_u32(smem);
    const uint32_t sQh = sb, sQl = sb + 16384, sKV = sb + 32768;

    const int tid = threadIdx.x, wid = tid >> 5, lane = tid & 31;
    const int mid = lane >> 3, lrow = lane & 7;
    const int g = lane >> 2, t = lane & 3;
    const int bh = blockIdx.x;
    const int qt = (int)(gridDim.y - 1 - blockIdx.y);   // heavy tiles first
    const int qbase = qt * 128;
    const size_t hoff = (size_t)bh * SEQ * DKH;
    const int nkt = 2 * qt + 2;

    {
        const __nv_bfloat16* srcs[2] = { g_qh + hoff, g_ql + hoff };
        const uint32_t dsts[2] = { sQh, sQl };
        #pragma unroll
        for (int tI = 0; tI < 2; ++tI)
            #pragma unroll
            for (int i = 0; i < 4; ++i) {
                int idx = tid + i * 256;
                int row = idx >> 3, c = idx & 7;
                const void* gsrc = srcs[tI] + (size_t)(qbase + row) * DKH + c * 8;
                uint32_t d = dsts[tI] + row * 128 + ((c ^ (row & 7)) * 16);
                asm volatile("cp.async.cg.shared.global [%0], [%1], 16;" :: "r"(d), "l"(gsrc));
            }
    }
    load_kv(sKV, hoff, 0, tid);
    asm volatile("cp.async.commit_group;" ::: "memory");
    load_kv(sKV + 32768, hoff, 1, tid);
    asm volatile("cp.async.commit_group;" ::: "memory");

    float oacc[8][4];
    #pragma unroll
    for (int jn = 0; jn < 8; ++jn)
        #pragma unroll
        for (int r = 0; r < 4; ++r) oacc[jn][r] = 0.f;
    float mrow[2] = {-INFINITY, -INFINITY};
    float lsum[2] = {0.f, 0.f};
    uint32_t qh[4][4];

    for (int kt = 0; kt < nkt; ++kt) {
        if (kt + 1 < nkt) asm volatile("cp.async.wait_group 1;" ::: "memory");
        else              asm volatile("cp.async.wait_group 0;" ::: "memory");
        __syncthreads();

        if (kt == 0) {
            #pragma unroll
            for (int s = 0; s < 4; ++s) {
                int row = wid * 16 + ((mid & 1) << 3) + lrow;
                int kc = 2 * s + (mid >> 1);
                uint32_t a = sQh + row * 128 + ((kc ^ (row & 7)) * 16);
                ldsm4(qh[s][0], qh[s][1], qh[s][2], qh[s][3], a);
            }
        }

        const uint32_t sKh = sKV + (kt & 1) * 32768;
        const uint32_t sKl = sKh + 8192, sVh = sKh + 16384, sVl = sKh + 24576;

        float sacc[8][4];
        #pragma unroll
        for (int jn = 0; jn < 8; ++jn)
            #pragma unroll
            for (int r = 0; r < 4; ++r) sacc[jn][r] = 0.f;

        #pragma unroll
        for (int s = 0; s < 4; ++s) {
            uint32_t kb[8][2];
            #pragma unroll
            for (int jp = 0; jp < 4; ++jp) {
                int row = jp * 16 + ((mid >> 1) << 3) + lrow;
                int kc = 2 * s + (mid & 1);
                uint32_t a = sKh + row * 128 + ((kc ^ (row & 7)) * 16);
                ldsm4(kb[2*jp][0], kb[2*jp][1], kb[2*jp+1][0], kb[2*jp+1][1], a);
            }
            #pragma unroll
            for (int jn = 0; jn < 8; ++jn) mma16816(sacc[jn], qh[s], kb[jn]);
            uint32_t qlf[4];
            {
                int row = wid * 16 + ((mid & 1) << 3) + lrow;
                int kc = 2 * s + (mid >> 1);
                uint32_t a = sQl + row * 128 + ((kc ^ (row & 7)) * 16);
                ldsm4(qlf[0], qlf[1], qlf[2], qlf[3], a);
            }
            #pragma unroll
            for (int jn = 0; jn < 8; ++jn) mma16816(sacc[jn], qlf, kb[jn]);
            #pragma unroll
            for (int jp = 0; jp < 4; ++jp) {
                int row = jp * 16 + ((mid >> 1) << 3) + lrow;
                int kc = 2 * s + (mid & 1);
                uint32_t a = sKl + row * 128 + ((kc ^ (row & 7)) * 16);
                ldsm4(kb[2*jp][0], kb[2*jp][1], kb[2*jp+1][0], kb[2*jp+1][1], a);
            }
            #pragma unroll
            for (int jn = 0; jn < 8; ++jn) mma16816(sacc[jn], qh[s], kb[jn]);
        }

        if (kt >= 2 * qt) {
            int q0 = qbase + wid * 16 + g;
            #pragma unroll
            for (int jn = 0; jn < 8; ++jn) {
                int j0 = kt * 64 + jn * 8 + 2 * t;
                if (j0     > q0)     sacc[jn][0] = -INFINITY;
                if (j0 + 1 > q0)     sacc[jn][1] = -INFINITY;
                if (j0     > q0 + 8) sacc[jn][2] = -INFINITY;
                if (j0 + 1 > q0 + 8) sacc[jn][3] = -INFINITY;
            }
        }

        #pragma unroll
        for (int hf = 0; hf < 2; ++hf) {
            float mx = -INFINITY;
            #pragma unroll
            for (int jn = 0; jn < 8; ++jn)
                mx = fmaxf(mx, fmaxf(sacc[jn][2*hf], sacc[jn][2*hf+1]));
            mx = fmaxf(mx, __shfl_xor_sync(0xffffffffu, mx, 1));
            mx = fmaxf(mx, __shfl_xor_sync(0xffffffffu, mx, 2));
            float mn = fmaxf(mrow[hf], mx);
            float al = __expf(mrow[hf] - mn);
            mrow[hf] = mn;
            float sum = 0.f;
            #pragma unroll
            for (int jn = 0; jn < 8; ++jn) {
                float p0 = __expf(sacc[jn][2*hf]   - mn);
                float p1 = __expf(sacc[jn][2*hf+1] - mn);
                sacc[jn][2*hf] = p0; sacc[jn][2*hf+1] = p1;
                sum += p0 + p1;
            }
            sum += __shfl_xor_sync(0xffffffffu, sum, 1);
            sum += __shfl_xor_sync(0xffffffffu, sum, 2);
            lsum[hf] = lsum[hf] * al + sum;
            #pragma unroll
            for (int jn = 0; jn < 8; ++jn) { oacc[jn][2*hf] *= al; oacc[jn][2*hf+1] *= al; }
        }

        #pragma unroll
        for (int s = 0; s < 4; ++s) {
            uint32_t ph[4], pl[4];
            #pragma unroll
            for (int r = 0; r < 4; ++r) {
                int tile = 2 * s + (r >> 1);
                int c0 = (r & 1) * 2;
                float p0 = sacc[tile][c0], p1 = sacc[tile][c0 + 1];
                uint32_t hp = packbf(p0, p1);
                float h0 = __uint_as_float(hp << 16);
                float h1 = __uint_as_float(hp & 0xffff0000u);
                ph[r] = hp;
                pl[r] = packbf(p0 - h0, p1 - h1);
            }
            uint32_t vb[8][2];
            #pragma unroll
            for (int jp = 0; jp < 4; ++jp) {
                int row = 16 * s + ((mid & 1) << 3) + lrow;
                int c = 2 * jp + (mid >> 1);
                uint32_t a = sVh + row * 128 + ((c ^ (row & 7)) * 16);
                ldsm4t(vb[2*jp][0], vb[2*jp][1], vb[2*jp+1][0], vb[2*jp+1][1], a);
            }
            #pragma unroll
            for (int jn = 0; jn < 8; ++jn) mma16816(oacc[jn], ph, vb[jn]);
            #pragma unroll
            for (int jn = 0; jn < 8; ++jn) mma16816(oacc[jn], pl, vb[jn]);
            #pragma unroll
            for (int jp = 0; jp < 4; ++jp) {
                int row = 16 * s + ((mid & 1) << 3) + lrow;
                int c = 2 * jp + (mid >> 1);
                uint32_t a = sVl + row * 128 + ((c ^ (row & 7)) * 16);
                ldsm4t(vb[2*jp][0], vb[2*jp][1], vb[2*jp+1][0], vb[2*jp+1][1], a);
            }
            #pragma unroll
            for (int jn = 0; jn < 8; ++jn) mma16816(oacc[jn], ph, vb[jn]);
        }

        __syncthreads();
        if (kt + 2 < nkt) {
            load_kv(sKV + (kt & 1) * 32768, hoff, kt + 2, tid);
            asm volatile("cp.async.commit_group;" ::: "memory");
        }
    }

    // ---- normalize + write bf16 hi/lo into [B,S,H*dk] (g_ah / g_al) ----
    const int b = bh >> 4, h = bh & 15;
    #pragma unroll
    for (int hf = 0; hf < 2; ++hf) {
        float inv = 1.0f / lsum[hf];
        int row = qbase + wid * 16 + g + 8 * hf;
        size_t base = ((size_t)(b * SEQ + row)) * D_MODEL + h * 64;
        #pragma unroll
        for (int jn = 0; jn < 8; ++jn) {
            float e0 = oacc[jn][2*hf] * inv, e1 = oacc[jn][2*hf+1] * inv;
            uint32_t hp = packbf(e0, e1);
            float h0 = __uint_as_float(hp << 16);
            float h1 = __uint_as_float(hp & 0xffff0000u);
            uint32_t lp = packbf(e0 - h0, e1 - h1);
            *reinterpret_cast<uint32_t*>(g_ah + base + jn * 8 + 2 * t) = hp;
            *reinterpret_cast<uint32_t*>(g_al + base + jn * 8 + 2 * t) = lp;
        }
    }
}

// ============================================================================
extern "C" void kernel_launch(void* const* d_in, const int* in_sizes, int n_in,
                              void* d_out, int out_size)
{
    const float* x  = (const float*)d_in[0];
    const float* Wq = (const float*)d_in[1];
    const float* bq = (const float*)d_in[2];
    const float* Wk = (const float*)d_in[3];
    const float* bk = (const float*)d_in[4];
    const float* Wv = (const float*)d_in[5];
    const float* bv = (const float*)d_in[6];
    const float* Wo = (const float*)d_in[7];
    const float* bo = (const float*)d_in[8];
    float* out = (float*)d_out;

    const int nx4 = M_TOT * D_MODEL / 4;
    const int nw4 = D_MODEL * D_MODEL / 4;

    split_x_kernel<<<nx4 / 256, 256>>>(x, nx4);
    split_w4_kernel<<<dim3(nw4 / 256, 4), 256>>>(Wq, Wk, Wv, Wo, nw4);

    cudaFuncSetAttribute(gemm_mma_kernel,
                         cudaFuncAttributeMaxDynamicSharedMemorySize, GEMM_SMEM);

    // fused QKV: blockIdx.z = mode (0,1,2)
    gemm_mma_kernel<<<dim3(D_MODEL / 128, M_TOT / 128, 3), 256, GEMM_SMEM>>>(
        0, bq, bk, bv, nullptr);

    cudaFuncSetAttribute(flash_mma_kernel,
                         cudaFuncAttributeMaxDynamicSharedMemorySize, AT_SMEM);
    flash_mma_kernel<<<dim3(BH, SEQ / 128), 256, AT_SMEM>>>();

    gemm_mma_kernel<<<dim3(D_MODEL / 128, M_TOT / 128, 1), 256, GEMM_SMEM>>>(
        3, bo, bo, bo, out);
}

// round 9
// speedup vs baseline: 3.3933x; 1.0095x over previous
#include <cuda_runtime.h>
#include <cuda_bf16.h>
#include <math.h>
#include <stdint.h>

#define D_MODEL 1024
#define NHEAD   16
#define DKH     64
#define BATCH   4
#define SEQ     2048
#define M_TOT   (BATCH*SEQ)     // 8192
#define BH      (BATCH*NHEAD)   // 64

// ---- scratch (__device__ globals: allocation-free rule) ----
__device__ __nv_bfloat16 g_xh[(size_t)M_TOT*D_MODEL];     // x hi/lo
__device__ __nv_bfloat16 g_xl[(size_t)M_TOT*D_MODEL];
__device__ __nv_bfloat16 g_ah[(size_t)M_TOT*D_MODEL];     // attn out hi/lo (flash writes)
__device__ __nv_bfloat16 g_al[(size_t)M_TOT*D_MODEL];
__device__ __nv_bfloat16 g_wh[4][(size_t)D_MODEL*D_MODEL];
__device__ __nv_bfloat16 g_wl[4][(size_t)D_MODEL*D_MODEL];
// q/k/v in [B,H,S,dk], bf16 hi/lo (QKV gemm epilogue; q pre-scaled 1/8)
__device__ __nv_bfloat16 g_qh[(size_t)BH*SEQ*DKH];
__device__ __nv_bfloat16 g_ql[(size_t)BH*SEQ*DKH];
__device__ __nv_bfloat16 g_kh[(size_t)BH*SEQ*DKH];
__device__ __nv_bfloat16 g_kl[(size_t)BH*SEQ*DKH];
__device__ __nv_bfloat16 g_vh[(size_t)BH*SEQ*DKH];
__device__ __nv_bfloat16 g_vl[(size_t)BH*SEQ*DKH];

typedef unsigned long long ull;

__device__ __forceinline__ uint32_t smem_u32(const void* p) {
    uint32_t a;
    asm("{ .reg .u64 t; cvta.to.shared.u64 t, %1; cvt.u32.u64 %0, t; }" : "=r"(a) : "l"(p));
    return a;
}
__device__ __forceinline__ void ldsm4(uint32_t& r0, uint32_t& r1, uint32_t& r2, uint32_t& r3,
                                      uint32_t addr) {
    asm volatile("ldmatrix.sync.aligned.m8n8.x4.shared.b16 {%0,%1,%2,%3}, [%4];"
                 : "=r"(r0), "=r"(r1), "=r"(r2), "=r"(r3) : "r"(addr));
}
__device__ __forceinline__ void ldsm4t(uint32_t& r0, uint32_t& r1, uint32_t& r2, uint32_t& r3,
                                       uint32_t addr) {
    asm volatile("ldmatrix.sync.aligned.m8n8.x4.trans.shared.b16 {%0,%1,%2,%3}, [%4];"
                 : "=r"(r0), "=r"(r1), "=r"(r2), "=r"(r3) : "r"(addr));
}
__device__ __forceinline__ void mma16816(float* c, const uint32_t* a, const uint32_t* b) {
    asm volatile(
        "mma.sync.aligned.m16n8k16.row.col.f32.bf16.bf16.f32 "
        "{%0,%1,%2,%3}, {%4,%5,%6,%7}, {%8,%9}, {%0,%1,%2,%3};"
        : "+f"(c[0]), "+f"(c[1]), "+f"(c[2]), "+f"(c[3])
        : "r"(a[0]), "r"(a[1]), "r"(a[2]), "r"(a[3]), "r"(b[0]), "r"(b[1]));
}
// pack two f32 -> bf16x2 (e0 in low half)
__device__ __forceinline__ uint32_t packbf(float e0, float e1) {
    uint32_t r; asm("cvt.rn.bf16x2.f32 %0, %1, %2;" : "=r"(r) : "f"(e1), "f"(e0)); return r;
}

// ============================================================================
// splits: x -> g_xh/g_xl;  4 weights in one launch (blockIdx.y = which)
// ============================================================================
__global__ void split_x_kernel(const float* __restrict__ in, int n4)
{
    int i = blockIdx.x * blockDim.x + threadIdx.x;
    if (i >= n4) return;
    float4 v = reinterpret_cast<const float4*>(in)[i];
    __nv_bfloat16 h[4], l[4];
    float f[4] = {v.x, v.y, v.z, v.w};
    #pragma unroll
    for (int j = 0; j < 4; ++j) {
        h[j] = __float2bfloat16(f[j]);
        l[j] = __float2bfloat16(f[j] - __bfloat162float(h[j]));
    }
    reinterpret_cast<ull*>(g_xh)[i] = *reinterpret_cast<ull*>(h);
    reinterpret_cast<ull*>(g_xl)[i] = *reinterpret_cast<ull*>(l);
}

__global__ void split_w4_kernel(const float* __restrict__ W0, const float* __restrict__ W1,
                                const float* __restrict__ W2, const float* __restrict__ W3,
                                int n4)
{
    int which = blockIdx.y;
    const float* src = (which == 0) ? W0 : (which == 1) ? W1 : (which == 2) ? W2 : W3;
    int i = blockIdx.x * blockDim.x + threadIdx.x;
    if (i >= n4) return;
    float4 v = reinterpret_cast<const float4*>(src)[i];
    __nv_bfloat16 h[4], l[4];
    float f[4] = {v.x, v.y, v.z, v.w};
    #pragma unroll
    for (int j = 0; j < 4; ++j) {
        h[j] = __float2bfloat16(f[j]);
        l[j] = __float2bfloat16(f[j] - __bfloat162float(h[j]));
    }
    reinterpret_cast<ull*>(g_wh[which])[i] = *reinterpret_cast<ull*>(h);
    reinterpret_cast<ull*>(g_wl[which])[i] = *reinterpret_cast<ull*>(l);
}

// ============================================================================
// mma.sync 3xbf16 GEMM — 512 threads (16 warps = 4/SMSP), CTA tile 128x128,
// warp tile 32x32 (acc 32 regs/thread).  3-stage cp.async ring, one barrier
// per chunk.  modes 0-2 (blockIdx.z): bf16 hi/lo q/k/v epilogue (mode 0
// scaled 1/8); mode 3: fp32 + bias.
// ============================================================================
#define GTILE_B 8192
#define GSTAGE_B (4 * GTILE_B)
#define GEMM_SMEM (3 * GSTAGE_B)     // 98304

__device__ __forceinline__ void load_chunk(
    uint32_t sstage, const __nv_bfloat16* Ah, const __nv_bfloat16* Al,
    const __nv_bfloat16* Bh, const __nv_bfloat16* Bl,
    int m0, int n0, int k0, int tid)
{
    const __nv_bfloat16* srcs[4] = {Ah, Al, Bh, Bl};
    const int bases[4] = {m0, m0, n0, n0};
    const int row = tid >> 2, kc = tid & 3;    // 512 threads: one 16B per tile
    #pragma unroll
    for (int t = 0; t < 4; ++t) {
        const void* g = srcs[t] + (size_t)(bases[t] + row) * D_MODEL + k0 + kc * 8;
        uint32_t s = sstage + t * GTILE_B + row * 64 + ((kc ^ ((row >> 1) & 3)) * 16);
        asm volatile("cp.async.cg.shared.global [%0], [%1], 16;" :: "r"(s), "l"(g));
    }
}

__global__ __launch_bounds__(512, 1)
void gemm_mma_kernel(int mode_base, const float* __restrict__ b0,
                     const float* __restrict__ b1, const float* __restrict__ b2,
                     float* __restrict__ outp)
{
    extern __shared__ __align__(128) char smem[];
    const uint32_t sb = smem_u32(smem);

    const int mode = (mode_base == 3) ? 3 : (int)blockIdx.z;
    const float* bias = (mode == 1) ? b1 : (mode == 2) ? b2 : b0;
    const __nv_bfloat16* Ah = (mode == 3) ? g_ah : g_xh;
    const __nv_bfloat16* Al = (mode == 3) ? g_al : g_xl;
    const __nv_bfloat16* Bh = g_wh[mode];
    const __nv_bfloat16* Bl = g_wl[mode];

    const int tid = threadIdx.x, wid = tid >> 5, lane = tid & 31;
    const int m0 = blockIdx.y * 128, n0 = blockIdx.x * 128;
    const int mw = (wid & 3) * 32, nw = (wid >> 2) * 32;   // 4x4 warp grid
    const int mid = lane >> 3, lrow = lane & 7;

    float acc[2][4][4];
    #pragma unroll
    for (int im = 0; im < 2; ++im)
        #pragma unroll
        for (int jn = 0; jn < 4; ++jn)
            #pragma unroll
            for (int r = 0; r < 4; ++r) acc[im][jn][r] = 0.f;

    load_chunk(sb, Ah, Al, Bh, Bl, m0, n0, 0, tid);
    asm volatile("cp.async.commit_group;" ::: "memory");
    load_chunk(sb + GSTAGE_B, Ah, Al, Bh, Bl, m0, n0, 32, tid);
    asm volatile("cp.async.commit_group;" ::: "memory");

    const int NCH = D_MODEL / 32;   // 32
    for (int c = 0; c < NCH; ++c) {
        const uint32_t sstage = sb + (c % 3) * GSTAGE_B;
        if (c + 1 < NCH) asm volatile("cp.async.wait_group 1;" ::: "memory");
        else             asm volatile("cp.async.wait_group 0;" ::: "memory");
        __syncthreads();   // single barrier per chunk (3-stage ring)

        #pragma unroll
        for (int s = 0; s < 2; ++s) {
            uint32_t ah[2][4], al[2][4], bh[4][2], bl[4][2];
            #pragma unroll
            for (int im = 0; im < 2; ++im) {
                int row = mw + im * 16 + ((mid & 1) << 3) + lrow;
                int kc  = 2 * s + (mid >> 1);
                uint32_t addr = sstage + row * 64 + ((kc ^ ((row >> 1) & 3)) * 16);
                ldsm4(ah[im][0], ah[im][1], ah[im][2], ah[im][3], addr);
                ldsm4(al[im][0], al[im][1], al[im][2], al[im][3], addr + GTILE_B);
            }
            #pragma unroll
            for (int jp = 0; jp < 2; ++jp) {
                int row = nw + jp * 16 + ((mid >> 1) << 3) + lrow;
                int kc  = 2 * s + (mid & 1);
                uint32_t addr = sstage + 2 * GTILE_B + row * 64 + ((kc ^ ((row >> 1) & 3)) * 16);
                ldsm4(bh[2*jp][0], bh[2*jp][1], bh[2*jp+1][0], bh[2*jp+1][1], addr);
                ldsm4(bl[2*jp][0], bl[2*jp][1], bl[2*jp+1][0], bl[2*jp+1][1], addr + GTILE_B);
            }
            #pragma unroll
            for (int im = 0; im < 2; ++im)
                #pragma unroll
                for (int jn = 0; jn < 4; ++jn) {
                    mma16816(acc[im][jn], ah[im], bh[jn]);
                    mma16816(acc[im][jn], ah[im], bl[jn]);
                    mma16816(acc[im][jn], al[im], bh[jn]);
                }
        }
        if (c + 2 < NCH) {
            load_chunk(sb + ((c + 2) % 3) * GSTAGE_B, Ah, Al, Bh, Bl, m0, n0, (c + 2) * 32, tid);
            asm volatile("cp.async.commit_group;" ::: "memory");
        }
    }

    const int g = lane >> 2, t = lane & 3;
    const float sc = (mode == 0) ? 0.125f : 1.0f;
    __nv_bfloat16* oh = (mode == 0) ? g_qh : (mode == 1) ? g_kh : g_vh;
    __nv_bfloat16* ol = (mode == 0) ? g_ql : (mode == 1) ? g_kl : g_vl;

    #pragma unroll
    for (int im = 0; im < 2; ++im) {
        #pragma unroll
        for (int jn = 0; jn < 4; ++jn) {
            int r0 = m0 + mw + im * 16 + g;
            int cc = n0 + nw + jn * 8 + 2 * t;
            float2 b2v = *reinterpret_cast<const float2*>(bias + cc);
            float v00 = (acc[im][jn][0] + b2v.x) * sc, v01 = (acc[im][jn][1] + b2v.y) * sc;
            float v10 = (acc[im][jn][2] + b2v.x) * sc, v11 = (acc[im][jn][3] + b2v.y) * sc;
            if (mode < 3) {
                int h = cc >> 6, d = cc & 63;
                #pragma unroll
                for (int rr = 0; rr < 2; ++rr) {
                    int r = r0 + rr * 8;
                    float e0 = rr ? v10 : v00, e1 = rr ? v11 : v01;
                    int b = r >> 11, srow = r & (SEQ - 1);
                    size_t idx = (((size_t)(b * NHEAD + h)) * SEQ + srow) * DKH + d;
                    uint32_t hp = packbf(e0, e1);
                    float h0 = __uint_as_float(hp << 16);
                    float h1 = __uint_as_float(hp & 0xffff0000u);
                    uint32_t lp = packbf(e0 - h0, e1 - h1);
                    *reinterpret_cast<uint32_t*>(oh + idx) = hp;
                    *reinterpret_cast<uint32_t*>(ol + idx) = lp;
                }
            } else {
                *reinterpret_cast<float2*>(outp + (size_t)r0 * D_MODEL + cc) = make_float2(v00, v01);
                *reinterpret_cast<float2*>(outp + (size_t)(r0+8) * D_MODEL + cc) = make_float2(v10, v11);
            }
        }
    }
}

// ============================================================================
// Flash attention via mma.sync 3xbf16 (validated R7/R8, unchanged this round)
// ============================================================================
#define AT_SMEM 98304

__device__ __forceinline__ void load_kv(uint32_t sstage, size_t hoff, int kt, int tid)
{
    const __nv_bfloat16* srcs[4] = { g_kh + hoff, g_kl + hoff, g_vh + hoff, g_vl + hoff };
    #pragma unroll
    for (int tI = 0; tI < 4; ++tI)
        #pragma unroll
        for (int i = 0; i < 2; ++i) {
            int idx = tid + i * 256;
            int row = idx >> 3, c = idx & 7;
            const void* gsrc = srcs[tI] + (size_t)(kt * 64 + row) * DKH + c * 8;
            uint32_t d = sstage + tI * 8192 + row * 128 + ((c ^ (row & 7)) * 16);
            asm volatile("cp.async.cg.shared.global [%0], [%1], 16;" :: "r"(d), "l"(gsrc));
        }
}

__global__ __launch_bounds__(256)
void flash_mma_kernel()
{
    extern __shared__ __align__(128) char smem[];
    const uint32_t sb = smem_u32(smem);
    const uint32_t sQh = sb, sQl = sb + 16384, sKV = sb + 32768;

    const int tid = threadIdx.x, wid = tid >> 5, lane = tid & 31;
    const int mid = lane >> 3, lrow = lane & 7;
    const int g = lane >> 2, t = lane & 3;
    const int bh = blockIdx.x;
    const int qt = (int)(gridDim.y - 1 - blockIdx.y);   // heavy tiles first
    const int qbase = qt * 128;
    const size_t hoff = (size_t)bh * SEQ * DKH;
    const int nkt = 2 * qt + 2;

    {
        const __nv_bfloat16* srcs[2] = { g_qh + hoff, g_ql + hoff };
        const uint32_t dsts[2] = { sQh, sQl };
        #pragma unroll
        for (int tI = 0; tI < 2; ++tI)
            #pragma unroll
            for (int i = 0; i < 4; ++i) {
                int idx = tid + i * 256;
                int row = idx >> 3, c = idx & 7;
                const void* gsrc = srcs[tI] + (size_t)(qbase + row) * DKH + c * 8;
                uint32_t d = dsts[tI] + row * 128 + ((c ^ (row & 7)) * 16);
                asm volatile("cp.async.cg.shared.global [%0], [%1], 16;" :: "r"(d), "l"(gsrc));
            }
    }
    load_kv(sKV, hoff, 0, tid);
    asm volatile("cp.async.commit_group;" ::: "memory");
    load_kv(sKV + 32768, hoff, 1, tid);
    asm volatile("cp.async.commit_group;" ::: "memory");

    float oacc[8][4];
    #pragma unroll
    for (int jn = 0; jn < 8; ++jn)
        #pragma unroll
        for (int r = 0; r < 4; ++r) oacc[jn][r] = 0.f;
    float mrow[2] = {-INFINITY, -INFINITY};
    float lsum[2] = {0.f, 0.f};
    uint32_t qh[4][4];

    for (int kt = 0; kt < nkt; ++kt) {
        if (kt + 1 < nkt) asm volatile("cp.async.wait_group 1;" ::: "memory");
        else              asm volatile("cp.async.wait_group 0;" ::: "memory");
        __syncthreads();

        if (kt == 0) {
            #pragma unroll
            for (int s = 0; s < 4; ++s) {
                int row = wid * 16 + ((mid & 1) << 3) + lrow;
                int kc = 2 * s + (mid >> 1);
                uint32_t a = sQh + row * 128 + ((kc ^ (row & 7)) * 16);
                ldsm4(qh[s][0], qh[s][1], qh[s][2], qh[s][3], a);
            }
        }

        const uint32_t sKh = sKV + (kt & 1) * 32768;
        const uint32_t sKl = sKh + 8192, sVh = sKh + 16384, sVl = sKh + 24576;

        float sacc[8][4];
        #pragma unroll
        for (int jn = 0; jn < 8; ++jn)
            #pragma unroll
            for (int r = 0; r < 4; ++r) sacc[jn][r] = 0.f;

        #pragma unroll
        for (int s = 0; s < 4; ++s) {
            uint32_t kb[8][2];
            #pragma unroll
            for (int jp = 0; jp < 4; ++jp) {
                int row = jp * 16 + ((mid >> 1) << 3) + lrow;
                int kc = 2 * s + (mid & 1);
                uint32_t a = sKh + row * 128 + ((kc ^ (row & 7)) * 16);
                ldsm4(kb[2*jp][0], kb[2*jp][1], kb[2*jp+1][0], kb[2*jp+1][1], a);
            }
            #pragma unroll
            for (int jn = 0; jn < 8; ++jn) mma16816(sacc[jn], qh[s], kb[jn]);
            uint32_t qlf[4];
            {
                int row = wid * 16 + ((mid & 1) << 3) + lrow;
                int kc = 2 * s + (mid >> 1);
                uint32_t a = sQl + row * 128 + ((kc ^ (row & 7)) * 16);
                ldsm4(qlf[0], qlf[1], qlf[2], qlf[3], a);
            }
            #pragma unroll
            for (int jn = 0; jn < 8; ++jn) mma16816(sacc[jn], qlf, kb[jn]);
            #pragma unroll
            for (int jp = 0; jp < 4; ++jp) {
                int row = jp * 16 + ((mid >> 1) << 3) + lrow;
                int kc = 2 * s + (mid & 1);
                uint32_t a = sKl + row * 128 + ((kc ^ (row & 7)) * 16);
                ldsm4(kb[2*jp][0], kb[2*jp][1], kb[2*jp+1][0], kb[2*jp+1][1], a);
            }
            #pragma unroll
            for (int jn = 0; jn < 8; ++jn) mma16816(sacc[jn], qh[s], kb[jn]);
        }

        if (kt >= 2 * qt) {
            int q0 = qbase + wid * 16 + g;
            #pragma unroll
            for (int jn = 0; jn < 8; ++jn) {
                int j0 = kt * 64 + jn * 8 + 2 * t;
                if (j0     > q0)     sacc[jn][0] = -INFINITY;
                if (j0 + 1 > q0)     sacc[jn][1] = -INFINITY;
                if (j0     > q0 + 8) sacc[jn][2] = -INFINITY;
                if (j0 + 1 > q0 + 8) sacc[jn][3] = -INFINITY;
            }
        }

        #pragma unroll
        for (int hf = 0; hf < 2; ++hf) {
            float mx = -INFINITY;
            #pragma unroll
            for (int jn = 0; jn < 8; ++jn)
                mx = fmaxf(mx, fmaxf(sacc[jn][2*hf], sacc[jn][2*hf+1]));
            mx = fmaxf(mx, __shfl_xor_sync(0xffffffffu, mx, 1));
            mx = fmaxf(mx, __shfl_xor_sync(0xffffffffu, mx, 2));
            float mn = fmaxf(mrow[hf], mx);
            float al = __expf(mrow[hf] - mn);
            mrow[hf] = mn;
            float sum = 0.f;
            #pragma unroll
            for (int jn = 0; jn < 8; ++jn) {
                float p0 = __expf(sacc[jn][2*hf]   - mn);
                float p1 = __expf(sacc[jn][2*hf+1] - mn);
                sacc[jn][2*hf] = p0; sacc[jn][2*hf+1] = p1;
                sum += p0 + p1;
            }
            sum += __shfl_xor_sync(0xffffffffu, sum, 1);
            sum += __shfl_xor_sync(0xffffffffu, sum, 2);
            lsum[hf] = lsum[hf] * al + sum;
            #pragma unroll
            for (int jn = 0; jn < 8; ++jn) { oacc[jn][2*hf] *= al; oacc[jn][2*hf+1] *= al; }
        }

        #pragma unroll
        for (int s = 0; s < 4; ++s) {
            uint32_t ph[4], pl[4];
            #pragma unroll
            for (int r = 0; r < 4; ++r) {
                int tile = 2 * s + (r >> 1);
                int c0 = (r & 1) * 2;
                float p0 = sacc[tile][c0], p1 = sacc[tile][c0 + 1];
                uint32_t hp = packbf(p0, p1);
                float h0 = __uint_as_float(hp << 16);
                float h1 = __uint_as_float(hp & 0xffff0000u);
                ph[r] = hp;
                pl[r] = packbf(p0 - h0, p1 - h1);
            }
            uint32_t vb[8][2];
            #pragma unroll
            for (int jp = 0; jp < 4; ++jp) {
                int row = 16 * s + ((mid & 1) << 3) + lrow;
                int c = 2 * jp + (mid >> 1);
                uint32_t a = sVh + row * 128 + ((c ^ (row & 7)) * 16);
                ldsm4t(vb[2*jp][0], vb[2*jp][1], vb[2*jp+1][0], vb[2*jp+1][1], a);
            }
            #pragma unroll
            for (int jn = 0; jn < 8; ++jn) mma16816(oacc[jn], ph, vb[jn]);
            #pragma unroll
            for (int jn = 0; jn < 8; ++jn) mma16816(oacc[jn], pl, vb[jn]);
            #pragma unroll
            for (int jp = 0; jp < 4; ++jp) {
                int row = 16 * s + ((mid & 1) << 3) + lrow;
                int c = 2 * jp + (mid >> 1);
                uint32_t a = sVl + row * 128 + ((c ^ (row & 7)) * 16);
                ldsm4t(vb[2*jp][0], vb[2*jp][1], vb[2*jp+1][0], vb[2*jp+1][1], a);
            }
            #pragma unroll
            for (int jn = 0; jn < 8; ++jn) mma16816(oacc[jn], ph, vb[jn]);
        }

        __syncthreads();
        if (kt + 2 < nkt) {
            load_kv(sKV + (kt & 1) * 32768, hoff, kt + 2, tid);
            asm volatile("cp.async.commit_group;" ::: "memory");
        }
    }

    const int b = bh >> 4, h = bh & 15;
    #pragma unroll
    for (int hf = 0; hf < 2; ++hf) {
        float inv = 1.0f / lsum[hf];
        int row = qbase + wid * 16 + g + 8 * hf;
        size_t base = ((size_t)(b * SEQ + row)) * D_MODEL + h * 64;
        #pragma unroll
        for (int jn = 0; jn < 8; ++jn) {
            float e0 = oacc[jn][2*hf] * inv, e1 = oacc[jn][2*hf+1] * inv;
            uint32_t hp = packbf(e0, e1);
            float h0 = __uint_as_float(hp << 16);
            float h1 = __uint_as_float(hp & 0xffff0000u);
            uint32_t lp = packbf(e0 - h0, e1 - h1);
            *reinterpret_cast<uint32_t*>(g_ah + base + jn * 8 + 2 * t) = hp;
            *reinterpret_cast<uint32_t*>(g_al + base + jn * 8 + 2 * t) = lp;
        }
    }
}

// ============================================================================
extern "C" void kernel_launch(void* const* d_in, const int* in_sizes, int n_in,
                              void* d_out, int out_size)
{
    const float* x  = (const float*)d_in[0];
    const float* Wq = (const float*)d_in[1];
    const float* bq = (const float*)d_in[2];
    const float* Wk = (const float*)d_in[3];
    const float* bk = (const float*)d_in[4];
    const float* Wv = (const float*)d_in[5];
    const float* bv = (const float*)d_in[6];
    const float* Wo = (const float*)d_in[7];
    const float* bo = (const float*)d_in[8];
    float* out = (float*)d_out;

    const int nx4 = M_TOT * D_MODEL / 4;
    const int nw4 = D_MODEL * D_MODEL / 4;

    split_x_kernel<<<nx4 / 256, 256>>>(x, nx4);
    split_w4_kernel<<<dim3(nw4 / 256, 4), 256>>>(Wq, Wk, Wv, Wo, nw4);

    cudaFuncSetAttribute(gemm_mma_kernel,
                         cudaFuncAttributeMaxDynamicSharedMemorySize, GEMM_SMEM);

    // fused QKV: blockIdx.z = mode (0,1,2)
    gemm_mma_kernel<<<dim3(D_MODEL / 128, M_TOT / 128, 3), 512, GEMM_SMEM>>>(
        0, bq, bk, bv, nullptr);

    cudaFuncSetAttribute(flash_mma_kernel,
                         cudaFuncAttributeMaxDynamicSharedMemorySize, AT_SMEM);
    flash_mma_kernel<<<dim3(BH, SEQ / 128), 256, AT_SMEM>>>();

    gemm_mma_kernel<<<dim3(D_MODEL / 128, M_TOT / 128, 1), 512, GEMM_SMEM>>>(
        3, bo, bo, bo, out);
}

// round 10
// speedup vs baseline: 3.5025x; 1.0322x over previous
#include <cuda_runtime.h>
#include <cuda_fp16.h>
#include <math.h>
#include <stdint.h>

#define D_MODEL 1024
#define NHEAD   16
#define DKH     64
#define BATCH   4
#define SEQ     2048
#define M_TOT   (BATCH*SEQ)     // 8192
#define BH      (BATCH*NHEAD)   // 64

// ---- scratch (__device__ globals: allocation-free rule) ----
__device__ __half g_xh[(size_t)M_TOT*D_MODEL];     // x hi/lo (exact fp16 split)
__device__ __half g_xl[(size_t)M_TOT*D_MODEL];
__device__ __half g_ah[(size_t)M_TOT*D_MODEL];     // attn out hi/lo (flash writes)
__device__ __half g_al[(size_t)M_TOT*D_MODEL];
__device__ __half g_wh[4][(size_t)D_MODEL*D_MODEL];
__device__ __half g_wl[4][(size_t)D_MODEL*D_MODEL];
// q split (pre-scaled 1/8), k single, v split — all [B,H,S,dk] fp16
__device__ __half g_qh[(size_t)BH*SEQ*DKH];
__device__ __half g_ql[(size_t)BH*SEQ*DKH];
__device__ __half g_k1[(size_t)BH*SEQ*DKH];
__device__ __half g_vh[(size_t)BH*SEQ*DKH];
__device__ __half g_vl[(size_t)BH*SEQ*DKH];

typedef unsigned long long ull;

__device__ __forceinline__ uint32_t smem_u32(const void* p) {
    uint32_t a;
    asm("{ .reg .u64 t; cvta.to.shared.u64 t, %1; cvt.u32.u64 %0, t; }" : "=r"(a) : "l"(p));
    return a;
}
__device__ __forceinline__ void ldsm4(uint32_t& r0, uint32_t& r1, uint32_t& r2, uint32_t& r3,
                                      uint32_t addr) {
    asm volatile("ldmatrix.sync.aligned.m8n8.x4.shared.b16 {%0,%1,%2,%3}, [%4];"
                 : "=r"(r0), "=r"(r1), "=r"(r2), "=r"(r3) : "r"(addr));
}
__device__ __forceinline__ void ldsm4t(uint32_t& r0, uint32_t& r1, uint32_t& r2, uint32_t& r3,
                                       uint32_t addr) {
    asm volatile("ldmatrix.sync.aligned.m8n8.x4.trans.shared.b16 {%0,%1,%2,%3}, [%4];"
                 : "=r"(r0), "=r"(r1), "=r"(r2), "=r"(r3) : "r"(addr));
}
__device__ __forceinline__ void mma16816(float* c, const uint32_t* a, const uint32_t* b) {
    asm volatile(
        "mma.sync.aligned.m16n8k16.row.col.f32.f16.f16.f32 "
        "{%0,%1,%2,%3}, {%4,%5,%6,%7}, {%8,%9}, {%0,%1,%2,%3};"
        : "+f"(c[0]), "+f"(c[1]), "+f"(c[2]), "+f"(c[3])
        : "r"(a[0]), "r"(a[1]), "r"(a[2]), "r"(a[3]), "r"(b[0]), "r"(b[1]));
}
// exact fp16 split of (e0,e1): hp = rounded pair (e0 low), lp = residual pair
__device__ __forceinline__ void split_h2(float e0, float e1, uint32_t& hp, uint32_t& lp) {
    __half2 hh = __floats2half2_rn(e0, e1);          // x=e0 (low), y=e1 (high)
    float2 bk = __half22float2(hh);
    __half2 ll = __floats2half2_rn(e0 - bk.x, e1 - bk.y);
    hp = *reinterpret_cast<uint32_t*>(&hh);
    lp = *reinterpret_cast<uint32_t*>(&ll);
}

// ============================================================================
// splits: x -> g_xh/g_xl;  4 weights in one launch (blockIdx.y = which)
// ============================================================================
__global__ void split_x_kernel(const float* __restrict__ in, int n4)
{
    int i = blockIdx.x * blockDim.x + threadIdx.x;
    if (i >= n4) return;
    float4 v = reinterpret_cast<const float4*>(in)[i];
    __half h[4], l[4];
    float f[4] = {v.x, v.y, v.z, v.w};
    #pragma unroll
    for (int j = 0; j < 4; ++j) {
        h[j] = __float2half_rn(f[j]);
        l[j] = __float2half_rn(f[j] - __half2float(h[j]));
    }
    reinterpret_cast<ull*>(g_xh)[i] = *reinterpret_cast<ull*>(h);
    reinterpret_cast<ull*>(g_xl)[i] = *reinterpret_cast<ull*>(l);
}

__global__ void split_w4_kernel(const float* __restrict__ W0, const float* __restrict__ W1,
                                const float* __restrict__ W2, const float* __restrict__ W3,
                                int n4)
{
    int which = blockIdx.y;
    const float* src = (which == 0) ? W0 : (which == 1) ? W1 : (which == 2) ? W2 : W3;
    int i = blockIdx.x * blockDim.x + threadIdx.x;
    if (i >= n4) return;
    float4 v = reinterpret_cast<const float4*>(src)[i];
    __half h[4], l[4];
    float f[4] = {v.x, v.y, v.z, v.w};
    #pragma unroll
    for (int j = 0; j < 4; ++j) {
        h[j] = __float2half_rn(f[j]);
        l[j] = __float2half_rn(f[j] - __half2float(h[j]));
    }
    reinterpret_cast<ull*>(g_wh[which])[i] = *reinterpret_cast<ull*>(h);
    reinterpret_cast<ull*>(g_wl[which])[i] = *reinterpret_cast<ull*>(l);
}

// ============================================================================
// mma.sync fp16 GEMM — 512 threads, CTA tile 128x128, 3-stage cp.async ring.
// modes 0 (Q), 1 (K): 2-pass (ah*bh + al*bh; B single fp16)
// modes 2 (V), 3 (Wo): 3-pass (ah*bh + al*bh + ah*bl)
// Epilogues: 0: q/8 exact split -> g_qh/g_ql; 1: round -> g_k1;
//            2: exact split -> g_vh/g_vl; 3: fp32 + bias -> out.
// ============================================================================
#define GTILE_B 8192
#define GSTAGE_B (4 * GTILE_B)
#define GEMM_SMEM (3 * GSTAGE_B)     // 98304

__device__ __forceinline__ void load_chunk(
    uint32_t sstage, const __half* Ah, const __half* Al,
    const __half* Bh, const __half* Bl,
    int m0, int n0, int k0, int tid, int ntiles)
{
    const __half* srcs[4] = {Ah, Al, Bh, Bl};
    const int bases[4] = {m0, m0, n0, n0};
    const int row = tid >> 2, kc = tid & 3;
    #pragma unroll
    for (int t = 0; t < 4; ++t) {
        if (t >= ntiles) break;
        const void* g = srcs[t] + (size_t)(bases[t] + row) * D_MODEL + k0 + kc * 8;
        uint32_t s = sstage + t * GTILE_B + row * 64 + ((kc ^ ((row >> 1) & 3)) * 16);
        asm volatile("cp.async.cg.shared.global [%0], [%1], 16;" :: "r"(s), "l"(g));
    }
}

__global__ __launch_bounds__(512, 1)
void gemm_mma_kernel(int mode_base, const float* __restrict__ b0,
                     const float* __restrict__ b1, const float* __restrict__ b2,
                     float* __restrict__ outp)
{
    extern __shared__ __align__(128) char smem[];
    const uint32_t sb = smem_u32(smem);

    const int mode = (mode_base == 3) ? 3 : (int)blockIdx.z;
    const bool p3 = (mode >= 2);
    const int ntiles = p3 ? 4 : 3;
    const float* bias = (mode == 1) ? b1 : (mode == 2) ? b2 : b0;
    const __half* Ah = (mode == 3) ? g_ah : g_xh;
    const __half* Al = (mode == 3) ? g_al : g_xl;
    const __half* Bh = g_wh[mode];
    const __half* Bl = g_wl[mode];

    const int tid = threadIdx.x, wid = tid >> 5, lane = tid & 31;
    const int m0 = blockIdx.y * 128, n0 = blockIdx.x * 128;
    const int mw = (wid & 3) * 32, nw = (wid >> 2) * 32;   // 4x4 warp grid
    const int mid = lane >> 3, lrow = lane & 7;

    float acc[2][4][4];
    #pragma unroll
    for (int im = 0; im < 2; ++im)
        #pragma unroll
        for (int jn = 0; jn < 4; ++jn)
            #pragma unroll
            for (int r = 0; r < 4; ++r) acc[im][jn][r] = 0.f;

    load_chunk(sb, Ah, Al, Bh, Bl, m0, n0, 0, tid, ntiles);
    asm volatile("cp.async.commit_group;" ::: "memory");
    load_chunk(sb + GSTAGE_B, Ah, Al, Bh, Bl, m0, n0, 32, tid, ntiles);
    asm volatile("cp.async.commit_group;" ::: "memory");

    const int NCH = D_MODEL / 32;   // 32
    for (int c = 0; c < NCH; ++c) {
        const uint32_t sstage = sb + (c % 3) * GSTAGE_B;
        if (c + 1 < NCH) asm volatile("cp.async.wait_group 1;" ::: "memory");
        else             asm volatile("cp.async.wait_group 0;" ::: "memory");
        __syncthreads();

        #pragma unroll
        for (int s = 0; s < 2; ++s) {
            uint32_t ah[2][4], al[2][4], bh[4][2], bl[4][2];
            #pragma unroll
            for (int im = 0; im < 2; ++im) {
                int row = mw + im * 16 + ((mid & 1) << 3) + lrow;
                int kc  = 2 * s + (mid >> 1);
                uint32_t addr = sstage + row * 64 + ((kc ^ ((row >> 1) & 3)) * 16);
                ldsm4(ah[im][0], ah[im][1], ah[im][2], ah[im][3], addr);
                ldsm4(al[im][0], al[im][1], al[im][2], al[im][3], addr + GTILE_B);
            }
            #pragma unroll
            for (int jp = 0; jp < 2; ++jp) {
                int row = nw + jp * 16 + ((mid >> 1) << 3) + lrow;
                int kc  = 2 * s + (mid & 1);
                uint32_t addr = sstage + 2 * GTILE_B + row * 64 + ((kc ^ ((row >> 1) & 3)) * 16);
                ldsm4(bh[2*jp][0], bh[2*jp][1], bh[2*jp+1][0], bh[2*jp+1][1], addr);
                if (p3)
                    ldsm4(bl[2*jp][0], bl[2*jp][1], bl[2*jp+1][0], bl[2*jp+1][1], addr + GTILE_B);
            }
            #pragma unroll
            for (int im = 0; im < 2; ++im)
                #pragma unroll
                for (int jn = 0; jn < 4; ++jn) {
                    mma16816(acc[im][jn], ah[im], bh[jn]);
                    mma16816(acc[im][jn], al[im], bh[jn]);
                    if (p3) mma16816(acc[im][jn], ah[im], bl[jn]);
                }
        }
        if (c + 2 < NCH) {
            load_chunk(sb + ((c + 2) % 3) * GSTAGE_B, Ah, Al, Bh, Bl, m0, n0, (c + 2) * 32, tid, ntiles);
            asm volatile("cp.async.commit_group;" ::: "memory");
        }
    }

    const int g = lane >> 2, t = lane & 3;
    const float sc = (mode == 0) ? 0.125f : 1.0f;

    #pragma unroll
    for (int im = 0; im < 2; ++im) {
        #pragma unroll
        for (int jn = 0; jn < 4; ++jn) {
            int r0 = m0 + mw + im * 16 + g;
            int cc = n0 + nw + jn * 8 + 2 * t;
            float2 b2v = *reinterpret_cast<const float2*>(bias + cc);
            float v00 = (acc[im][jn][0] + b2v.x) * sc, v01 = (acc[im][jn][1] + b2v.y) * sc;
            float v10 = (acc[im][jn][2] + b2v.x) * sc, v11 = (acc[im][jn][3] + b2v.y) * sc;
            if (mode < 3) {
                int h = cc >> 6, d = cc & 63;
                #pragma unroll
                for (int rr = 0; rr < 2; ++rr) {
                    int r = r0 + rr * 8;
                    float e0 = rr ? v10 : v00, e1 = rr ? v11 : v01;
                    int b = r >> 11, srow = r & (SEQ - 1);
                    size_t idx = (((size_t)(b * NHEAD + h)) * SEQ + srow) * DKH + d;
                    if (mode == 1) {          // K: single fp16
                        __half2 hh = __floats2half2_rn(e0, e1);
                        *reinterpret_cast<uint32_t*>(g_k1 + idx) =
                            *reinterpret_cast<uint32_t*>(&hh);
                    } else {                  // Q or V: exact split
                        uint32_t hp, lp;
                        split_h2(e0, e1, hp, lp);
                        __half* oh = (mode == 0) ? g_qh : g_vh;
                        __half* ol = (mode == 0) ? g_ql : g_vl;
                        *reinterpret_cast<uint32_t*>(oh + idx) = hp;
                        *reinterpret_cast<uint32_t*>(ol + idx) = lp;
                    }
                }
            } else {
                *reinterpret_cast<float2*>(outp + (size_t)r0 * D_MODEL + cc) = make_float2(v00, v01);
                *reinterpret_cast<float2*>(outp + (size_t)(r0+8) * D_MODEL + cc) = make_float2(v10, v11);
            }
        }
    }
}

// ============================================================================
// Flash attention, fp16 mma.sync.
// S = qh*k + ql*k (2 passes, K single fp16)
// PV = ph*vh + pl*vh + ph*vl (3 passes, P split exact in registers)
// smem: Qh 16K, Ql 16K, 2 stages x (K 8K, Vh 8K, Vl 8K) = 80K.
// ============================================================================
#define AT_STAGE 24576
#define AT_SMEM (32768 + 2 * AT_STAGE)   // 81920

__device__ __forceinline__ void load_kv(uint32_t sstage, size_t hoff, int kt, int tid)
{
    const __half* srcs[3] = { g_k1 + hoff, g_vh + hoff, g_vl + hoff };
    #pragma unroll
    for (int tI = 0; tI < 3; ++tI)
        #pragma unroll
        for (int i = 0; i < 2; ++i) {
            int idx = tid + i * 256;
            int row = idx >> 3, c = idx & 7;
            const void* gsrc = srcs[tI] + (size_t)(kt * 64 + row) * DKH + c * 8;
            uint32_t d = sstage + tI * 8192 + row * 128 + ((c ^ (row & 7)) * 16);
            asm volatile("cp.async.cg.shared.global [%0], [%1], 16;" :: "r"(d), "l"(gsrc));
        }
}

__global__ __launch_bounds__(256)
void flash_mma_kernel()
{
    extern __shared__ __align__(128) char smem[];
    const uint32_t sb = smem_u32(smem);
    const uint32_t sQh = sb, sQl = sb + 16384, sKV = sb + 32768;

    const int tid = threadIdx.x, wid = tid >> 5, lane = tid & 31;
    const int mid = lane >> 3, lrow = lane & 7;
    const int g = lane >> 2, t = lane & 3;
    const int bh = blockIdx.x;
    const int qt = (int)(gridDim.y - 1 - blockIdx.y);   // heavy tiles first
    const int qbase = qt * 128;
    const size_t hoff = (size_t)bh * SEQ * DKH;
    const int nkt = 2 * qt + 2;

    {
        const __half* srcs[2] = { g_qh + hoff, g_ql + hoff };
        const uint32_t dsts[2] = { sQh, sQl };
        #pragma unroll
        for (int tI = 0; tI < 2; ++tI)
            #pragma unroll
            for (int i = 0; i < 4; ++i) {
                int idx = tid + i * 256;
                int row = idx >> 3, c = idx & 7;
                const void* gsrc = srcs[tI] + (size_t)(qbase + row) * DKH + c * 8;
                uint32_t d = dsts[tI] + row * 128 + ((c ^ (row & 7)) * 16);
                asm volatile("cp.async.cg.shared.global [%0], [%1], 16;" :: "r"(d), "l"(gsrc));
            }
    }
    load_kv(sKV, hoff, 0, tid);
    asm volatile("cp.async.commit_group;" ::: "memory");
    load_kv(sKV + AT_STAGE, hoff, 1, tid);
    asm volatile("cp.async.commit_group;" ::: "memory");

    float oacc[8][4];
    #pragma unroll
    for (int jn = 0; jn < 8; ++jn)
        #pragma unroll
        for (int r = 0; r < 4; ++r) oacc[jn][r] = 0.f;
    float mrow[2] = {-INFINITY, -INFINITY};
    float lsum[2] = {0.f, 0.f};
    uint32_t qh[4][4];

    for (int kt = 0; kt < nkt; ++kt) {
        if (kt + 1 < nkt) asm volatile("cp.async.wait_group 1;" ::: "memory");
        else              asm volatile("cp.async.wait_group 0;" ::: "memory");
        __syncthreads();

        if (kt == 0) {
            #pragma unroll
            for (int s = 0; s < 4; ++s) {
                int row = wid * 16 + ((mid & 1) << 3) + lrow;
                int kc = 2 * s + (mid >> 1);
                uint32_t a = sQh + row * 128 + ((kc ^ (row & 7)) * 16);
                ldsm4(qh[s][0], qh[s][1], qh[s][2], qh[s][3], a);
            }
        }

        const uint32_t sK  = sKV + (kt & 1) * AT_STAGE;
        const uint32_t sVh = sK + 8192, sVl = sK + 16384;

        // ---- S = q·K (2 passes over one K fragment set) ----
        float sacc[8][4];
        #pragma unroll
        for (int jn = 0; jn < 8; ++jn)
            #pragma unroll
            for (int r = 0; r < 4; ++r) sacc[jn][r] = 0.f;

        #pragma unroll
        for (int s = 0; s < 4; ++s) {
            uint32_t kb[8][2];
            #pragma unroll
            for (int jp = 0; jp < 4; ++jp) {
                int row = jp * 16 + ((mid >> 1) << 3) + lrow;
                int kc = 2 * s + (mid & 1);
                uint32_t a = sK + row * 128 + ((kc ^ (row & 7)) * 16);
                ldsm4(kb[2*jp][0], kb[2*jp][1], kb[2*jp+1][0], kb[2*jp+1][1], a);
            }
            #pragma unroll
            for (int jn = 0; jn < 8; ++jn) mma16816(sacc[jn], qh[s], kb[jn]);
            uint32_t qlf[4];
            {
                int row = wid * 16 + ((mid & 1) << 3) + lrow;
                int kc = 2 * s + (mid >> 1);
                uint32_t a = sQl + row * 128 + ((kc ^ (row & 7)) * 16);
                ldsm4(qlf[0], qlf[1], qlf[2], qlf[3], a);
            }
            #pragma unroll
            for (int jn = 0; jn < 8; ++jn) mma16816(sacc[jn], qlf, kb[jn]);
        }

        if (kt >= 2 * qt) {
            int q0 = qbase + wid * 16 + g;
            #pragma unroll
            for (int jn = 0; jn < 8; ++jn) {
                int j0 = kt * 64 + jn * 8 + 2 * t;
                if (j0     > q0)     sacc[jn][0] = -INFINITY;
                if (j0 + 1 > q0)     sacc[jn][1] = -INFINITY;
                if (j0     > q0 + 8) sacc[jn][2] = -INFINITY;
                if (j0 + 1 > q0 + 8) sacc[jn][3] = -INFINITY;
            }
        }

        #pragma unroll
        for (int hf = 0; hf < 2; ++hf) {
            float mx = -INFINITY;
            #pragma unroll
            for (int jn = 0; jn < 8; ++jn)
                mx = fmaxf(mx, fmaxf(sacc[jn][2*hf], sacc[jn][2*hf+1]));
            mx = fmaxf(mx, __shfl_xor_sync(0xffffffffu, mx, 1));
            mx = fmaxf(mx, __shfl_xor_sync(0xffffffffu, mx, 2));
            float mn = fmaxf(mrow[hf], mx);
            float al = __expf(mrow[hf] - mn);
            mrow[hf] = mn;
            float sum = 0.f;
            #pragma unroll
            for (int jn = 0; jn < 8; ++jn) {
                float p0 = __expf(sacc[jn][2*hf]   - mn);
                float p1 = __expf(sacc[jn][2*hf+1] - mn);
                sacc[jn][2*hf] = p0; sacc[jn][2*hf+1] = p1;
                sum += p0 + p1;
            }
            sum += __shfl_xor_sync(0xffffffffu, sum, 1);
            sum += __shfl_xor_sync(0xffffffffu, sum, 2);
            lsum[hf] = lsum[hf] * al + sum;
            #pragma unroll
            for (int jn = 0; jn < 8; ++jn) { oacc[jn][2*hf] *= al; oacc[jn][2*hf+1] *= al; }
        }

        // ---- O += P V : ph*vh + pl*vh + ph*vl (drop pl*vl only) ----
        #pragma unroll
        for (int s = 0; s < 4; ++s) {
            uint32_t ph[4], pl[4];
            #pragma unroll
            for (int r = 0; r < 4; ++r) {
                int tile = 2 * s + (r >> 1);
                int c0 = (r & 1) * 2;
                split_h2(sacc[tile][c0], sacc[tile][c0 + 1], ph[r], pl[r]);
            }
            uint32_t vb[8][2];
            #pragma unroll
            for (int jp = 0; jp < 4; ++jp) {
                int row = 16 * s + ((mid & 1) << 3) + lrow;
                int c = 2 * jp + (mid >> 1);
                uint32_t a = sVh + row * 128 + ((c ^ (row & 7)) * 16);
                ldsm4t(vb[2*jp][0], vb[2*jp][1], vb[2*jp+1][0], vb[2*jp+1][1], a);
            }
            #pragma unroll
            for (int jn = 0; jn < 8; ++jn) mma16816(oacc[jn], ph, vb[jn]);
            #pragma unroll
            for (int jn = 0; jn < 8; ++jn) mma16816(oacc[jn], pl, vb[jn]);
            #pragma unroll
            for (int jp = 0; jp < 4; ++jp) {
                int row = 16 * s + ((mid & 1) << 3) + lrow;
                int c = 2 * jp + (mid >> 1);
                uint32_t a = sVl + row * 128 + ((c ^ (row & 7)) * 16);
                ldsm4t(vb[2*jp][0], vb[2*jp][1], vb[2*jp+1][0], vb[2*jp+1][1], a);
            }
            #pragma unroll
            for (int jn = 0; jn < 8; ++jn) mma16816(oacc[jn], ph, vb[jn]);
        }

        __syncthreads();
        if (kt + 2 < nkt) {
            load_kv(sKV + (kt & 1) * AT_STAGE, hoff, kt + 2, tid);
            asm volatile("cp.async.commit_group;" ::: "memory");
        }
    }

    // ---- normalize + write fp16 hi/lo into [B,S,H*dk] (g_ah / g_al) ----
    const int b = bh >> 4, h = bh & 15;
    #pragma unroll
    for (int hf = 0; hf < 2; ++hf) {
        float inv = 1.0f / lsum[hf];
        int row = qbase + wid * 16 + g + 8 * hf;
        size_t base = ((size_t)(b * SEQ + row)) * D_MODEL + h * 64;
        #pragma unroll
        for (int jn = 0; jn < 8; ++jn) {
            uint32_t hp, lp;
            split_h2(oacc[jn][2*hf] * inv, oacc[jn][2*hf+1] * inv, hp, lp);
            *reinterpret_cast<uint32_t*>(g_ah + base + jn * 8 + 2 * t) = hp;
            *reinterpret_cast<uint32_t*>(g_al + base + jn * 8 + 2 * t) = lp;
        }
    }
}

// ============================================================================
extern "C" void kernel_launch(void* const* d_in, const int* in_sizes, int n_in,
                              void* d_out, int out_size)
{
    const float* x  = (const float*)d_in[0];
    const float* Wq = (const float*)d_in[1];
    const float* bq = (const float*)d_in[2];
    const float* Wk = (const float*)d_in[3];
    const float* bk = (const float*)d_in[4];
    const float* Wv = (const float*)d_in[5];
    const float* bv = (const float*)d_in[6];
    const float* Wo = (const float*)d_in[7];
    const float* bo = (const float*)d_in[8];
    float* out = (float*)d_out;

    const int nx4 = M_TOT * D_MODEL / 4;
    const int nw4 = D_MODEL * D_MODEL / 4;

    split_x_kernel<<<nx4 / 256, 256>>>(x, nx4);
    split_w4_kernel<<<dim3(nw4 / 256, 4), 256>>>(Wq, Wk, Wv, Wo, nw4);

    cudaFuncSetAttribute(gemm_mma_kernel,
                         cudaFuncAttributeMaxDynamicSharedMemorySize, GEMM_SMEM);

    // fused QKV: blockIdx.z = mode (0=Q 2-pass, 1=K 2-pass, 2=V 3-pass)
    gemm_mma_kernel<<<dim3(D_MODEL / 128, M_TOT / 128, 3), 512, GEMM_SMEM>>>(
        0, bq, bk, bv, nullptr);

    cudaFuncSetAttribute(flash_mma_kernel,
                         cudaFuncAttributeMaxDynamicSharedMemorySize, AT_SMEM);
    flash_mma_kernel<<<dim3(BH, SEQ / 128), 256, AT_SMEM>>>();

    gemm_mma_kernel<<<dim3(D_MODEL / 128, M_TOT / 128, 1), 512, GEMM_SMEM>>>(
        3, bo, bo, bo, out);
}

// round 11
// speedup vs baseline: 4.4413x; 1.2680x over previous
#include <cuda_runtime.h>
#include <cuda_fp16.h>
#include <math.h>
#include <stdint.h>

#define D_MODEL 1024
#define NHEAD   16
#define DKH     64
#define BATCH   4
#define SEQ     2048
#define M_TOT   (BATCH*SEQ)     // 8192
#define BH      (BATCH*NHEAD)   // 64

// ---- scratch (__device__ globals: allocation-free rule) ----
__device__ __half g_xh[(size_t)M_TOT*D_MODEL];     // x hi/lo (exact fp16 split)
__device__ __half g_xl[(size_t)M_TOT*D_MODEL];
__device__ __half g_ah[(size_t)M_TOT*D_MODEL];     // attn out hi/lo (flash writes)
__device__ __half g_al[(size_t)M_TOT*D_MODEL];
__device__ __half g_wh[4][(size_t)D_MODEL*D_MODEL];  // weights single fp16
// q split (pre-scaled 1/8), k single, v single — all [B,H,S,dk] fp16
__device__ __half g_qh[(size_t)BH*SEQ*DKH];
__device__ __half g_ql[(size_t)BH*SEQ*DKH];
__device__ __half g_k1[(size_t)BH*SEQ*DKH];
__device__ __half g_v1[(size_t)BH*SEQ*DKH];

typedef unsigned long long ull;

__device__ __forceinline__ uint32_t smem_u32(const void* p) {
    uint32_t a;
    asm("{ .reg .u64 t; cvta.to.shared.u64 t, %1; cvt.u32.u64 %0, t; }" : "=r"(a) : "l"(p));
    return a;
}
__device__ __forceinline__ void ldsm4(uint32_t& r0, uint32_t& r1, uint32_t& r2, uint32_t& r3,
                                      uint32_t addr) {
    asm volatile("ldmatrix.sync.aligned.m8n8.x4.shared.b16 {%0,%1,%2,%3}, [%4];"
                 : "=r"(r0), "=r"(r1), "=r"(r2), "=r"(r3) : "r"(addr));
}
__device__ __forceinline__ void ldsm4t(uint32_t& r0, uint32_t& r1, uint32_t& r2, uint32_t& r3,
                                       uint32_t addr) {
    asm volatile("ldmatrix.sync.aligned.m8n8.x4.trans.shared.b16 {%0,%1,%2,%3}, [%4];"
                 : "=r"(r0), "=r"(r1), "=r"(r2), "=r"(r3) : "r"(addr));
}
__device__ __forceinline__ void mma16816(float* c, const uint32_t* a, const uint32_t* b) {
    asm volatile(
        "mma.sync.aligned.m16n8k16.row.col.f32.f16.f16.f32 "
        "{%0,%1,%2,%3}, {%4,%5,%6,%7}, {%8,%9}, {%0,%1,%2,%3};"
        : "+f"(c[0]), "+f"(c[1]), "+f"(c[2]), "+f"(c[3])
        : "r"(a[0]), "r"(a[1]), "r"(a[2]), "r"(a[3]), "r"(b[0]), "r"(b[1]));
}
// exact fp16 split of (e0,e1): hp = rounded pair (e0 low), lp = residual pair
__device__ __forceinline__ void split_h2(float e0, float e1, uint32_t& hp, uint32_t& lp) {
    __half2 hh = __floats2half2_rn(e0, e1);
    float2 bk = __half22float2(hh);
    __half2 ll = __floats2half2_rn(e0 - bk.x, e1 - bk.y);
    hp = *reinterpret_cast<uint32_t*>(&hh);
    lp = *reinterpret_cast<uint32_t*>(&ll);
}

// ============================================================================
// splits: x -> g_xh/g_xl (exact);  4 weights -> g_wh (single fp16, one launch)
// ============================================================================
__global__ void split_x_kernel(const float* __restrict__ in, int n4)
{
    int i = blockIdx.x * blockDim.x + threadIdx.x;
    if (i >= n4) return;
    float4 v = reinterpret_cast<const float4*>(in)[i];
    __half h[4], l[4];
    float f[4] = {v.x, v.y, v.z, v.w};
    #pragma unroll
    for (int j = 0; j < 4; ++j) {
        h[j] = __float2half_rn(f[j]);
        l[j] = __float2half_rn(f[j] - __half2float(h[j]));
    }
    reinterpret_cast<ull*>(g_xh)[i] = *reinterpret_cast<ull*>(h);
    reinterpret_cast<ull*>(g_xl)[i] = *reinterpret_cast<ull*>(l);
}

__global__ void split_w4_kernel(const float* __restrict__ W0, const float* __restrict__ W1,
                                const float* __restrict__ W2, const float* __restrict__ W3,
                                int n4)
{
    int which = blockIdx.y;
    const float* src = (which == 0) ? W0 : (which == 1) ? W1 : (which == 2) ? W2 : W3;
    int i = blockIdx.x * blockDim.x + threadIdx.x;
    if (i >= n4) return;
    float4 v = reinterpret_cast<const float4*>(src)[i];
    __half h[4];
    h[0] = __float2half_rn(v.x); h[1] = __float2half_rn(v.y);
    h[2] = __float2half_rn(v.z); h[3] = __float2half_rn(v.w);
    reinterpret_cast<ull*>(g_wh[which])[i] = *reinterpret_cast<ull*>(h);
}

// ============================================================================
// mma.sync fp16 GEMM — uniform 2-pass (ah*B + al*B), B single fp16.
// 512 threads, CTA 128x128, 3-stage cp.async ring (3 tiles x 8KB per stage).
// Epilogues: 0: q/8 exact split; 1: K round; 2: V round; 3: fp32+bias out.
// ============================================================================
#define GTILE_B 8192
#define GSTAGE_B (3 * GTILE_B)       // Ah, Al, Bh
#define GEMM_SMEM (3 * GSTAGE_B)     // 73728

__device__ __forceinline__ void load_chunk(
    uint32_t sstage, const __half* Ah, const __half* Al, const __half* Bh,
    int m0, int n0, int k0, int tid)
{
    const __half* srcs[3] = {Ah, Al, Bh};
    const int bases[3] = {m0, m0, n0};
    const int row = tid >> 2, kc = tid & 3;
    #pragma unroll
    for (int t = 0; t < 3; ++t) {
        const void* g = srcs[t] + (size_t)(bases[t] + row) * D_MODEL + k0 + kc * 8;
        uint32_t s = sstage + t * GTILE_B + row * 64 + ((kc ^ ((row >> 1) & 3)) * 16);
        asm volatile("cp.async.cg.shared.global [%0], [%1], 16;" :: "r"(s), "l"(g));
    }
}

__global__ __launch_bounds__(512, 1)
void gemm_mma_kernel(int mode_base, const float* __restrict__ b0,
                     const float* __restrict__ b1, const float* __restrict__ b2,
                     float* __restrict__ outp)
{
    extern __shared__ __align__(128) char smem[];
    const uint32_t sb = smem_u32(smem);

    const int mode = (mode_base == 3) ? 3 : (int)blockIdx.z;
    const float* bias = (mode == 1) ? b1 : (mode == 2) ? b2 : b0;
    const __half* Ah = (mode == 3) ? g_ah : g_xh;
    const __half* Al = (mode == 3) ? g_al : g_xl;
    const __half* Bh = g_wh[mode];

    const int tid = threadIdx.x, wid = tid >> 5, lane = tid & 31;
    const int m0 = blockIdx.y * 128, n0 = blockIdx.x * 128;
    const int mw = (wid & 3) * 32, nw = (wid >> 2) * 32;   // 4x4 warp grid
    const int mid = lane >> 3, lrow = lane & 7;

    float acc[2][4][4];
    #pragma unroll
    for (int im = 0; im < 2; ++im)
        #pragma unroll
        for (int jn = 0; jn < 4; ++jn)
            #pragma unroll
            for (int r = 0; r < 4; ++r) acc[im][jn][r] = 0.f;

    load_chunk(sb, Ah, Al, Bh, m0, n0, 0, tid);
    asm volatile("cp.async.commit_group;" ::: "memory");
    load_chunk(sb + GSTAGE_B, Ah, Al, Bh, m0, n0, 32, tid);
    asm volatile("cp.async.commit_group;" ::: "memory");

    const int NCH = D_MODEL / 32;   // 32
    for (int c = 0; c < NCH; ++c) {
        const uint32_t sstage = sb + (c % 3) * GSTAGE_B;
        if (c + 1 < NCH) asm volatile("cp.async.wait_group 1;" ::: "memory");
        else             asm volatile("cp.async.wait_group 0;" ::: "memory");
        __syncthreads();

        #pragma unroll
        for (int s = 0; s < 2; ++s) {
            uint32_t ah[2][4], al[2][4], bh[4][2];
            #pragma unroll
            for (int im = 0; im < 2; ++im) {
                int row = mw + im * 16 + ((mid & 1) << 3) + lrow;
                int kc  = 2 * s + (mid >> 1);
                uint32_t addr = sstage + row * 64 + ((kc ^ ((row >> 1) & 3)) * 16);
                ldsm4(ah[im][0], ah[im][1], ah[im][2], ah[im][3], addr);
                ldsm4(al[im][0], al[im][1], al[im][2], al[im][3], addr + GTILE_B);
            }
            #pragma unroll
            for (int jp = 0; jp < 2; ++jp) {
                int row = nw + jp * 16 + ((mid >> 1) << 3) + lrow;
                int kc  = 2 * s + (mid & 1);
                uint32_t addr = sstage + 2 * GTILE_B + row * 64 + ((kc ^ ((row >> 1) & 3)) * 16);
                ldsm4(bh[2*jp][0], bh[2*jp][1], bh[2*jp+1][0], bh[2*jp+1][1], addr);
            }
            #pragma unroll
            for (int im = 0; im < 2; ++im)
                #pragma unroll
                for (int jn = 0; jn < 4; ++jn) {
                    mma16816(acc[im][jn], ah[im], bh[jn]);
                    mma16816(acc[im][jn], al[im], bh[jn]);
                }
        }
        if (c + 2 < NCH) {
            load_chunk(sb + ((c + 2) % 3) * GSTAGE_B, Ah, Al, Bh, m0, n0, (c + 2) * 32, tid);
            asm volatile("cp.async.commit_group;" ::: "memory");
        }
    }

    const int g = lane >> 2, t = lane & 3;
    const float sc = (mode == 0) ? 0.125f : 1.0f;

    #pragma unroll
    for (int im = 0; im < 2; ++im) {
        #pragma unroll
        for (int jn = 0; jn < 4; ++jn) {
            int r0 = m0 + mw + im * 16 + g;
            int cc = n0 + nw + jn * 8 + 2 * t;
            float2 b2v = *reinterpret_cast<const float2*>(bias + cc);
            float v00 = (acc[im][jn][0] + b2v.x) * sc, v01 = (acc[im][jn][1] + b2v.y) * sc;
            float v10 = (acc[im][jn][2] + b2v.x) * sc, v11 = (acc[im][jn][3] + b2v.y) * sc;
            if (mode < 3) {
                int h = cc >> 6, d = cc & 63;
                #pragma unroll
                for (int rr = 0; rr < 2; ++rr) {
                    int r = r0 + rr * 8;
                    float e0 = rr ? v10 : v00, e1 = rr ? v11 : v01;
                    int b = r >> 11, srow = r & (SEQ - 1);
                    size_t idx = (((size_t)(b * NHEAD + h)) * SEQ + srow) * DKH + d;
                    if (mode == 0) {          // Q: exact split
                        uint32_t hp, lp;
                        split_h2(e0, e1, hp, lp);
                        *reinterpret_cast<uint32_t*>(g_qh + idx) = hp;
                        *reinterpret_cast<uint32_t*>(g_ql + idx) = lp;
                    } else {                  // K or V: single fp16
                        __half2 hh = __floats2half2_rn(e0, e1);
                        __half* dst = (mode == 1) ? g_k1 : g_v1;
                        *reinterpret_cast<uint32_t*>(dst + idx) =
                            *reinterpret_cast<uint32_t*>(&hh);
                    }
                }
            } else {
                *reinterpret_cast<float2*>(outp + (size_t)r0 * D_MODEL + cc) = make_float2(v00, v01);
                *reinterpret_cast<float2*>(outp + (size_t)(r0+8) * D_MODEL + cc) = make_float2(v10, v11);
            }
        }
    }
}

// ============================================================================
// Flash attention, fp16 mma.sync.
// S  = qh*k + ql*k       (2 passes, K single)
// PV = ph*v + pl*v       (2 passes, V single, P split exact in registers)
// smem: Qh 16K, Ql 16K, 2 stages x (K 8K, V 8K) = 64KB.
// ============================================================================
#define AT_STAGE 16384
#define AT_SMEM (32768 + 2 * AT_STAGE)   // 65536

__device__ __forceinline__ void load_kv(uint32_t sstage, size_t hoff, int kt, int tid)
{
    const __half* srcs[2] = { g_k1 + hoff, g_v1 + hoff };
    #pragma unroll
    for (int tI = 0; tI < 2; ++tI)
        #pragma unroll
        for (int i = 0; i < 2; ++i) {
            int idx = tid + i * 256;
            int row = idx >> 3, c = idx & 7;
            const void* gsrc = srcs[tI] + (size_t)(kt * 64 + row) * DKH + c * 8;
            uint32_t d = sstage + tI * 8192 + row * 128 + ((c ^ (row & 7)) * 16);
            asm volatile("cp.async.cg.shared.global [%0], [%1], 16;" :: "r"(d), "l"(gsrc));
        }
}

__global__ __launch_bounds__(256)
void flash_mma_kernel()
{
    extern __shared__ __align__(128) char smem[];
    const uint32_t sb = smem_u32(smem);
    const uint32_t sQh = sb, sQl = sb + 16384, sKV = sb + 32768;

    const int tid = threadIdx.x, wid = tid >> 5, lane = tid & 31;
    const int mid = lane >> 3, lrow = lane & 7;
    const int g = lane >> 2, t = lane & 3;
    const int bh = blockIdx.x;
    const int qt = (int)(gridDim.y - 1 - blockIdx.y);   // heavy tiles first
    const int qbase = qt * 128;
    const size_t hoff = (size_t)bh * SEQ * DKH;
    const int nkt = 2 * qt + 2;

    {
        const __half* srcs[2] = { g_qh + hoff, g_ql + hoff };
        const uint32_t dsts[2] = { sQh, sQl };
        #pragma unroll
        for (int tI = 0; tI < 2; ++tI)
            #pragma unroll
            for (int i = 0; i < 4; ++i) {
                int idx = tid + i * 256;
                int row = idx >> 3, c = idx & 7;
                const void* gsrc = srcs[tI] + (size_t)(qbase + row) * DKH + c * 8;
                uint32_t d = dsts[tI] + row * 128 + ((c ^ (row & 7)) * 16);
                asm volatile("cp.async.cg.shared.global [%0], [%1], 16;" :: "r"(d), "l"(gsrc));
            }
    }
    load_kv(sKV, hoff, 0, tid);
    asm volatile("cp.async.commit_group;" ::: "memory");
    load_kv(sKV + AT_STAGE, hoff, 1, tid);
    asm volatile("cp.async.commit_group;" ::: "memory");

    float oacc[8][4];
    #pragma unroll
    for (int jn = 0; jn < 8; ++jn)
        #pragma unroll
        for (int r = 0; r < 4; ++r) oacc[jn][r] = 0.f;
    float mrow[2] = {-INFINITY, -INFINITY};
    float lsum[2] = {0.f, 0.f};
    uint32_t qh[4][4];

    for (int kt = 0; kt < nkt; ++kt) {
        if (kt + 1 < nkt) asm volatile("cp.async.wait_group 1;" ::: "memory");
        else              asm volatile("cp.async.wait_group 0;" ::: "memory");
        __syncthreads();

        if (kt == 0) {
            #pragma unroll
            for (int s = 0; s < 4; ++s) {
                int row = wid * 16 + ((mid & 1) << 3) + lrow;
                int kc = 2 * s + (mid >> 1);
                uint32_t a = sQh + row * 128 + ((kc ^ (row & 7)) * 16);
                ldsm4(qh[s][0], qh[s][1], qh[s][2], qh[s][3], a);
            }
        }

        const uint32_t sK = sKV + (kt & 1) * AT_STAGE;
        const uint32_t sV = sK + 8192;

        // ---- S = q·K (2 passes over one K fragment set) ----
        float sacc[8][4];
        #pragma unroll
        for (int jn = 0; jn < 8; ++jn)
            #pragma unroll
            for (int r = 0; r < 4; ++r) sacc[jn][r] = 0.f;

        #pragma unroll
        for (int s = 0; s < 4; ++s) {
            uint32_t kb[8][2];
            #pragma unroll
            for (int jp = 0; jp < 4; ++jp) {
                int row = jp * 16 + ((mid >> 1) << 3) + lrow;
                int kc = 2 * s + (mid & 1);
                uint32_t a = sK + row * 128 + ((kc ^ (row & 7)) * 16);
                ldsm4(kb[2*jp][0], kb[2*jp][1], kb[2*jp+1][0], kb[2*jp+1][1], a);
            }
            #pragma unroll
            for (int jn = 0; jn < 8; ++jn) mma16816(sacc[jn], qh[s], kb[jn]);
            uint32_t qlf[4];
            {
                int row = wid * 16 + ((mid & 1) << 3) + lrow;
                int kc = 2 * s + (mid >> 1);
                uint32_t a = sQl + row * 128 + ((kc ^ (row & 7)) * 16);
                ldsm4(qlf[0], qlf[1], qlf[2], qlf[3], a);
            }
            #pragma unroll
            for (int jn = 0; jn < 8; ++jn) mma16816(sacc[jn], qlf, kb[jn]);
        }

        if (kt >= 2 * qt) {
            int q0 = qbase + wid * 16 + g;
            #pragma unroll
            for (int jn = 0; jn < 8; ++jn) {
                int j0 = kt * 64 + jn * 8 + 2 * t;
                if (j0     > q0)     sacc[jn][0] = -INFINITY;
                if (j0 + 1 > q0)     sacc[jn][1] = -INFINITY;
                if (j0     > q0 + 8) sacc[jn][2] = -INFINITY;
                if (j0 + 1 > q0 + 8) sacc[jn][3] = -INFINITY;
            }
        }

        #pragma unroll
        for (int hf = 0; hf < 2; ++hf) {
            float mx = -INFINITY;
            #pragma unroll
            for (int jn = 0; jn < 8; ++jn)
                mx = fmaxf(mx, fmaxf(sacc[jn][2*hf], sacc[jn][2*hf+1]));
            mx = fmaxf(mx, __shfl_xor_sync(0xffffffffu, mx, 1));
            mx = fmaxf(mx, __shfl_xor_sync(0xffffffffu, mx, 2));
            float mn = fmaxf(mrow[hf], mx);
            float al = __expf(mrow[hf] - mn);
            mrow[hf] = mn;
            float sum = 0.f;
            #pragma unroll
            for (int jn = 0; jn < 8; ++jn) {
                float p0 = __expf(sacc[jn][2*hf]   - mn);
                float p1 = __expf(sacc[jn][2*hf+1] - mn);
                sacc[jn][2*hf] = p0; sacc[jn][2*hf+1] = p1;
                sum += p0 + p1;
            }
            sum += __shfl_xor_sync(0xffffffffu, sum, 1);
            sum += __shfl_xor_sync(0xffffffffu, sum, 2);
            lsum[hf] = lsum[hf] * al + sum;
            #pragma unroll
            for (int jn = 0; jn < 8; ++jn) { oacc[jn][2*hf] *= al; oacc[jn][2*hf+1] *= al; }
        }

        // ---- O += P V : ph*v + pl*v (V single; drops only pl residuals of P) ----
        #pragma unroll
        for (int s = 0; s < 4; ++s) {
            uint32_t ph[4], pl[4];
            #pragma unroll
            for (int r = 0; r < 4; ++r) {
                int tile = 2 * s + (r >> 1);
                int c0 = (r & 1) * 2;
                split_h2(sacc[tile][c0], sacc[tile][c0 + 1], ph[r], pl[r]);
            }
            uint32_t vb[8][2];
            #pragma unroll
            for (int jp = 0; jp < 4; ++jp) {
                int row = 16 * s + ((mid & 1) << 3) + lrow;
                int c = 2 * jp + (mid >> 1);
                uint32_t a = sV + row * 128 + ((c ^ (row & 7)) * 16);
                ldsm4t(vb[2*jp][0], vb[2*jp][1], vb[2*jp+1][0], vb[2*jp+1][1], a);
            }
            #pragma unroll
            for (int jn = 0; jn < 8; ++jn) mma16816(oacc[jn], ph, vb[jn]);
            #pragma unroll
            for (int jn = 0; jn < 8; ++jn) mma16816(oacc[jn], pl, vb[jn]);
        }

        __syncthreads();
        if (kt + 2 < nkt) {
            load_kv(sKV + (kt & 1) * AT_STAGE, hoff, kt + 2, tid);
            asm volatile("cp.async.commit_group;" ::: "memory");
        }
    }

    // ---- normalize + write fp16 hi/lo into [B,S,H*dk] (g_ah / g_al) ----
    const int b = bh >> 4, h = bh & 15;
    #pragma unroll
    for (int hf = 0; hf < 2; ++hf) {
        float inv = 1.0f / lsum[hf];
        int row = qbase + wid * 16 + g + 8 * hf;
        size_t base = ((size_t)(b * SEQ + row)) * D_MODEL + h * 64;
        #pragma unroll
        for (int jn = 0; jn < 8; ++jn) {
            uint32_t hp, lp;
            split_h2(oacc[jn][2*hf] * inv, oacc[jn][2*hf+1] * inv, hp, lp);
            *reinterpret_cast<uint32_t*>(g_ah + base + jn * 8 + 2 * t) = hp;
            *reinterpret_cast<uint32_t*>(g_al + base + jn * 8 + 2 * t) = lp;
        }
    }
}

// ============================================================================
extern "C" void kernel_launch(void* const* d_in, const int* in_sizes, int n_in,
                              void* d_out, int out_size)
{
    const float* x  = (const float*)d_in[0];
    const float* Wq = (const float*)d_in[1];
    const float* bq = (const float*)d_in[2];
    const float* Wk = (const float*)d_in[3];
    const float* bk = (const float*)d_in[4];
    const float* Wv = (const float*)d_in[5];
    const float* bv = (const float*)d_in[6];
    const float* Wo = (const float*)d_in[7];
    const float* bo = (const float*)d_in[8];
    float* out = (float*)d_out;

    const int nx4 = M_TOT * D_MODEL / 4;
    const int nw4 = D_MODEL * D_MODEL / 4;

    split_x_kernel<<<nx4 / 256, 256>>>(x, nx4);
    split_w4_kernel<<<dim3(nw4 / 256, 4), 256>>>(Wq, Wk, Wv, Wo, nw4);

    cudaFuncSetAttribute(gemm_mma_kernel,
                         cudaFuncAttributeMaxDynamicSharedMemorySize, GEMM_SMEM);

    // fused QKV: blockIdx.z = mode (0=Q, 1=K, 2=V) — all 2-pass
    gemm_mma_kernel<<<dim3(D_MODEL / 128, M_TOT / 128, 3), 512, GEMM_SMEM>>>(
        0, bq, bk, bv, nullptr);

    cudaFuncSetAttribute(flash_mma_kernel,
                         cudaFuncAttributeMaxDynamicSharedMemorySize, AT_SMEM);
    flash_mma_kernel<<<dim3(BH, SEQ / 128), 256, AT_SMEM>>>();

    gemm_mma_kernel<<<dim3(D_MODEL / 128, M_TOT / 128, 1), 512, GEMM_SMEM>>>(
        3, bo, bo, bo, out);
}

// round 12
// speedup vs baseline: 7.2711x; 1.6371x over previous
#include <cuda_runtime.h>
#include <cuda_fp16.h>
#include <math.h>
#include <stdint.h>

#define D_MODEL 1024
#define NHEAD   16
#define DKH     64
#define BATCH   4
#define SEQ     2048
#define M_TOT   (BATCH*SEQ)     // 8192
#define BH      (BATCH*NHEAD)   // 64

// ---- scratch (__device__ globals: allocation-free rule) ----
__device__ __half g_x1[(size_t)M_TOT*D_MODEL];       // x single fp16
__device__ __half g_a1[(size_t)M_TOT*D_MODEL];       // attn out single fp16
__device__ __half g_wh[4][(size_t)D_MODEL*D_MODEL];  // weights single fp16
// q (pre-scaled 1/8), k, v — all single fp16 [B,H,S,dk]
__device__ __half g_q1[(size_t)BH*SEQ*DKH];
__device__ __half g_k1[(size_t)BH*SEQ*DKH];
__device__ __half g_v1[(size_t)BH*SEQ*DKH];

typedef unsigned long long ull;

__device__ __forceinline__ uint32_t smem_u32(const void* p) {
    uint32_t a;
    asm("{ .reg .u64 t; cvta.to.shared.u64 t, %1; cvt.u32.u64 %0, t; }" : "=r"(a) : "l"(p));
    return a;
}
__device__ __forceinline__ void ldsm4(uint32_t& r0, uint32_t& r1, uint32_t& r2, uint32_t& r3,
                                      uint32_t addr) {
    asm volatile("ldmatrix.sync.aligned.m8n8.x4.shared.b16 {%0,%1,%2,%3}, [%4];"
                 : "=r"(r0), "=r"(r1), "=r"(r2), "=r"(r3) : "r"(addr));
}
__device__ __forceinline__ void ldsm4t(uint32_t& r0, uint32_t& r1, uint32_t& r2, uint32_t& r3,
                                       uint32_t addr) {
    asm volatile("ldmatrix.sync.aligned.m8n8.x4.trans.shared.b16 {%0,%1,%2,%3}, [%4];"
                 : "=r"(r0), "=r"(r1), "=r"(r2), "=r"(r3) : "r"(addr));
}
__device__ __forceinline__ void mma16816(float* c, const uint32_t* a, const uint32_t* b) {
    asm volatile(
        "mma.sync.aligned.m16n8k16.row.col.f32.f16.f16.f32 "
        "{%0,%1,%2,%3}, {%4,%5,%6,%7}, {%8,%9}, {%0,%1,%2,%3};"
        : "+f"(c[0]), "+f"(c[1]), "+f"(c[2]), "+f"(c[3])
        : "r"(a[0]), "r"(a[1]), "r"(a[2]), "r"(a[3]), "r"(b[0]), "r"(b[1]));
}
// exact fp16 split of (e0,e1): hp = rounded pair (e0 low), lp = residual pair
__device__ __forceinline__ void split_h2(float e0, float e1, uint32_t& hp, uint32_t& lp) {
    __half2 hh = __floats2half2_rn(e0, e1);
    float2 bk = __half22float2(hh);
    __half2 ll = __floats2half2_rn(e0 - bk.x, e1 - bk.y);
    hp = *reinterpret_cast<uint32_t*>(&hh);
    lp = *reinterpret_cast<uint32_t*>(&ll);
}

// ============================================================================
// conversions: x -> g_x1;  4 weights -> g_wh (single launch, blockIdx.y)
// ============================================================================
__global__ void conv_x_kernel(const float* __restrict__ in, int n4)
{
    int i = blockIdx.x * blockDim.x + threadIdx.x;
    if (i >= n4) return;
    float4 v = reinterpret_cast<const float4*>(in)[i];
    __half h[4];
    h[0] = __float2half_rn(v.x); h[1] = __float2half_rn(v.y);
    h[2] = __float2half_rn(v.z); h[3] = __float2half_rn(v.w);
    reinterpret_cast<ull*>(g_x1)[i] = *reinterpret_cast<ull*>(h);
}

__global__ void conv_w4_kernel(const float* __restrict__ W0, const float* __restrict__ W1,
                               const float* __restrict__ W2, const float* __restrict__ W3,
                               int n4)
{
    int which = blockIdx.y;
    const float* src = (which == 0) ? W0 : (which == 1) ? W1 : (which == 2) ? W2 : W3;
    int i = blockIdx.x * blockDim.x + threadIdx.x;
    if (i >= n4) return;
    float4 v = reinterpret_cast<const float4*>(src)[i];
    __half h[4];
    h[0] = __float2half_rn(v.x); h[1] = __float2half_rn(v.y);
    h[2] = __float2half_rn(v.z); h[3] = __float2half_rn(v.w);
    reinterpret_cast<ull*>(g_wh[which])[i] = *reinterpret_cast<ull*>(h);
}

// ============================================================================
// mma.sync fp16 GEMM — single-pass (A single, B single).
// 512 threads, CTA 128x128, K-chunk 64, 3-stage cp.async ring (2x16KB/stage).
// Epilogues: 0: q/8 fp16; 1: K fp16; 2: V fp16; 3: fp32+bias out.
// ============================================================================
#define GTILE_B 16384                // 128 rows x 128B (64 halves)
#define GSTAGE_B (2 * GTILE_B)       // A, B
#define GEMM_SMEM (3 * GSTAGE_B)     // 98304

__device__ __forceinline__ void load_chunk(
    uint32_t sstage, const __half* A, const __half* B,
    int m0, int n0, int k0, int tid)
{
    const __half* srcs[2] = {A, B};
    const int bases[2] = {m0, n0};
    #pragma unroll
    for (int t = 0; t < 2; ++t) {
        #pragma unroll
        for (int i = 0; i < 2; ++i) {
            int idx = tid + i * 512;               // 1024 x 16B per tile
            int row = idx >> 3, c = idx & 7;
            const void* g = srcs[t] + (size_t)(bases[t] + row) * D_MODEL + k0 + c * 8;
            uint32_t s = sstage + t * GTILE_B + row * 128 + ((c ^ (row & 7)) * 16);
            asm volatile("cp.async.cg.shared.global [%0], [%1], 16;" :: "r"(s), "l"(g));
        }
    }
}

__global__ __launch_bounds__(512, 1)
void gemm_mma_kernel(int mode_base, const float* __restrict__ b0,
                     const float* __restrict__ b1, const float* __restrict__ b2,
                     float* __restrict__ outp)
{
    extern __shared__ __align__(128) char smem[];
    const uint32_t sb = smem_u32(smem);

    const int mode = (mode_base == 3) ? 3 : (int)blockIdx.z;
    const float* bias = (mode == 1) ? b1 : (mode == 2) ? b2 : b0;
    const __half* A = (mode == 3) ? g_a1 : g_x1;
    const __half* B = g_wh[mode];

    const int tid = threadIdx.x, wid = tid >> 5, lane = tid & 31;
    const int m0 = blockIdx.y * 128, n0 = blockIdx.x * 128;
    const int mw = (wid & 3) * 32, nw = (wid >> 2) * 32;   // 4x4 warp grid
    const int mid = lane >> 3, lrow = lane & 7;

    float acc[2][4][4];
    #pragma unroll
    for (int im = 0; im < 2; ++im)
        #pragma unroll
        for (int jn = 0; jn < 4; ++jn)
            #pragma unroll
            for (int r = 0; r < 4; ++r) acc[im][jn][r] = 0.f;

    load_chunk(sb, A, B, m0, n0, 0, tid);
    asm volatile("cp.async.commit_group;" ::: "memory");
    load_chunk(sb + GSTAGE_B, A, B, m0, n0, 64, tid);
    asm volatile("cp.async.commit_group;" ::: "memory");

    const int NCH = D_MODEL / 64;   // 16
    for (int c = 0; c < NCH; ++c) {
        const uint32_t sstage = sb + (c % 3) * GSTAGE_B;
        if (c + 1 < NCH) asm volatile("cp.async.wait_group 1;" ::: "memory");
        else             asm volatile("cp.async.wait_group 0;" ::: "memory");
        __syncthreads();

        #pragma unroll
        for (int s = 0; s < 4; ++s) {          // 4 k-steps of 16 per chunk
            uint32_t ah[2][4], bh[4][2];
            #pragma unroll
            for (int im = 0; im < 2; ++im) {
                int row = mw + im * 16 + ((mid & 1) << 3) + lrow;
                int kc  = 2 * s + (mid >> 1);
                uint32_t addr = sstage + row * 128 + ((kc ^ (row & 7)) * 16);
                ldsm4(ah[im][0], ah[im][1], ah[im][2], ah[im][3], addr);
            }
            #pragma unroll
            for (int jp = 0; jp < 2; ++jp) {
                int row = nw + jp * 16 + ((mid >> 1) << 3) + lrow;
                int kc  = 2 * s + (mid & 1);
                uint32_t addr = sstage + GTILE_B + row * 128 + ((kc ^ (row & 7)) * 16);
                ldsm4(bh[2*jp][0], bh[2*jp][1], bh[2*jp+1][0], bh[2*jp+1][1], addr);
            }
            #pragma unroll
            for (int im = 0; im < 2; ++im)
                #pragma unroll
                for (int jn = 0; jn < 4; ++jn)
                    mma16816(acc[im][jn], ah[im], bh[jn]);
        }
        if (c + 2 < NCH) {
            load_chunk(sb + ((c + 2) % 3) * GSTAGE_B, A, B, m0, n0, (c + 2) * 64, tid);
            asm volatile("cp.async.commit_group;" ::: "memory");
        }
    }

    const int g = lane >> 2, t = lane & 3;
    const float sc = (mode == 0) ? 0.125f : 1.0f;

    #pragma unroll
    for (int im = 0; im < 2; ++im) {
        #pragma unroll
        for (int jn = 0; jn < 4; ++jn) {
            int r0 = m0 + mw + im * 16 + g;
            int cc = n0 + nw + jn * 8 + 2 * t;
            float2 b2v = *reinterpret_cast<const float2*>(bias + cc);
            float v00 = (acc[im][jn][0] + b2v.x) * sc, v01 = (acc[im][jn][1] + b2v.y) * sc;
            float v10 = (acc[im][jn][2] + b2v.x) * sc, v11 = (acc[im][jn][3] + b2v.y) * sc;
            if (mode < 3) {
                int h = cc >> 6, d = cc & 63;
                __half* dst = (mode == 0) ? g_q1 : (mode == 1) ? g_k1 : g_v1;
                #pragma unroll
                for (int rr = 0; rr < 2; ++rr) {
                    int r = r0 + rr * 8;
                    float e0 = rr ? v10 : v00, e1 = rr ? v11 : v01;
                    int b = r >> 11, srow = r & (SEQ - 1);
                    size_t idx = (((size_t)(b * NHEAD + h)) * SEQ + srow) * DKH + d;
                    __half2 hh = __floats2half2_rn(e0, e1);
                    *reinterpret_cast<uint32_t*>(dst + idx) = *reinterpret_cast<uint32_t*>(&hh);
                }
            } else {
                *reinterpret_cast<float2*>(outp + (size_t)r0 * D_MODEL + cc) = make_float2(v00, v01);
                *reinterpret_cast<float2*>(outp + (size_t)(r0+8) * D_MODEL + cc) = make_float2(v10, v11);
            }
        }
    }
}

// ============================================================================
// Flash attention, fp16 mma.sync.
// S  = q·K            (1 pass, Q and K single)
// PV = ph·v + pl·v    (2 passes, V single, P split exact in registers)
// smem: Q 16K, 2 stages x (K 8K, V 8K) = 48KB total.
// ============================================================================
#define AT_STAGE 16384
#define AT_SMEM (16384 + 2 * AT_STAGE)   // 49152

__device__ __forceinline__ void load_kv(uint32_t sstage, size_t hoff, int kt, int tid)
{
    const __half* srcs[2] = { g_k1 + hoff, g_v1 + hoff };
    #pragma unroll
    for (int tI = 0; tI < 2; ++tI)
        #pragma unroll
        for (int i = 0; i < 2; ++i) {
            int idx = tid + i * 256;
            int row = idx >> 3, c = idx & 7;
            const void* gsrc = srcs[tI] + (size_t)(kt * 64 + row) * DKH + c * 8;
            uint32_t d = sstage + tI * 8192 + row * 128 + ((c ^ (row & 7)) * 16);
            asm volatile("cp.async.cg.shared.global [%0], [%1], 16;" :: "r"(d), "l"(gsrc));
        }
}

__global__ __launch_bounds__(256)
void flash_mma_kernel()
{
    extern __shared__ __align__(128) char smem[];
    const uint32_t sb = smem_u32(smem);
    const uint32_t sQ = sb, sKV = sb + 16384;

    const int tid = threadIdx.x, wid = tid >> 5, lane = tid & 31;
    const int mid = lane >> 3, lrow = lane & 7;
    const int g = lane >> 2, t = lane & 3;
    const int bh = blockIdx.x;
    const int qt = (int)(gridDim.y - 1 - blockIdx.y);   // heavy tiles first
    const int qbase = qt * 128;
    const size_t hoff = (size_t)bh * SEQ * DKH;
    const int nkt = 2 * qt + 2;

    {
        #pragma unroll
        for (int i = 0; i < 4; ++i) {
            int idx = tid + i * 256;
            int row = idx >> 3, c = idx & 7;
            const void* gsrc = g_q1 + hoff + (size_t)(qbase + row) * DKH + c * 8;
            uint32_t d = sQ + row * 128 + ((c ^ (row & 7)) * 16);
            asm volatile("cp.async.cg.shared.global [%0], [%1], 16;" :: "r"(d), "l"(gsrc));
        }
    }
    load_kv(sKV, hoff, 0, tid);
    asm volatile("cp.async.commit_group;" ::: "memory");
    load_kv(sKV + AT_STAGE, hoff, 1, tid);
    asm volatile("cp.async.commit_group;" ::: "memory");

    float oacc[8][4];
    #pragma unroll
    for (int jn = 0; jn < 8; ++jn)
        #pragma unroll
        for (int r = 0; r < 4; ++r) oacc[jn][r] = 0.f;
    float mrow[2] = {-INFINITY, -INFINITY};
    float lsum[2] = {0.f, 0.f};
    uint32_t qh[4][4];

    for (int kt = 0; kt < nkt; ++kt) {
        if (kt + 1 < nkt) asm volatile("cp.async.wait_group 1;" ::: "memory");
        else              asm volatile("cp.async.wait_group 0;" ::: "memory");
        __syncthreads();

        if (kt == 0) {
            #pragma unroll
            for (int s = 0; s < 4; ++s) {
                int row = wid * 16 + ((mid & 1) << 3) + lrow;
                int kc = 2 * s + (mid >> 1);
                uint32_t a = sQ + row * 128 + ((kc ^ (row & 7)) * 16);
                ldsm4(qh[s][0], qh[s][1], qh[s][2], qh[s][3], a);
            }
        }

        const uint32_t sK = sKV + (kt & 1) * AT_STAGE;
        const uint32_t sV = sK + 8192;

        // ---- S = q·K (single pass) ----
        float sacc[8][4];
        #pragma unroll
        for (int jn = 0; jn < 8; ++jn)
            #pragma unroll
            for (int r = 0; r < 4; ++r) sacc[jn][r] = 0.f;

        #pragma unroll
        for (int s = 0; s < 4; ++s) {
            uint32_t kb[8][2];
            #pragma unroll
            for (int jp = 0; jp < 4; ++jp) {
                int row = jp * 16 + ((mid >> 1) << 3) + lrow;
                int kc = 2 * s + (mid & 1);
                uint32_t a = sK + row * 128 + ((kc ^ (row & 7)) * 16);
                ldsm4(kb[2*jp][0], kb[2*jp][1], kb[2*jp+1][0], kb[2*jp+1][1], a);
            }
            #pragma unroll
            for (int jn = 0; jn < 8; ++jn) mma16816(sacc[jn], qh[s], kb[jn]);
        }

        if (kt >= 2 * qt) {
            int q0 = qbase + wid * 16 + g;
            #pragma unroll
            for (int jn = 0; jn < 8; ++jn) {
                int j0 = kt * 64 + jn * 8 + 2 * t;
                if (j0     > q0)     sacc[jn][0] = -INFINITY;
                if (j0 + 1 > q0)     sacc[jn][1] = -INFINITY;
                if (j0     > q0 + 8) sacc[jn][2] = -INFINITY;
                if (j0 + 1 > q0 + 8) sacc[jn][3] = -INFINITY;
            }
        }

        #pragma unroll
        for (int hf = 0; hf < 2; ++hf) {
            float mx = -INFINITY;
            #pragma unroll
            for (int jn = 0; jn < 8; ++jn)
                mx = fmaxf(mx, fmaxf(sacc[jn][2*hf], sacc[jn][2*hf+1]));
            mx = fmaxf(mx, __shfl_xor_sync(0xffffffffu, mx, 1));
            mx = fmaxf(mx, __shfl_xor_sync(0xffffffffu, mx, 2));
            float mn = fmaxf(mrow[hf], mx);
            float al = __expf(mrow[hf] - mn);
            mrow[hf] = mn;
            float sum = 0.f;
            #pragma unroll
            for (int jn = 0; jn < 8; ++jn) {
                float p0 = __expf(sacc[jn][2*hf]   - mn);
                float p1 = __expf(sacc[jn][2*hf+1] - mn);
                sacc[jn][2*hf] = p0; sacc[jn][2*hf+1] = p1;
                sum += p0 + p1;
            }
            sum += __shfl_xor_sync(0xffffffffu, sum, 1);
            sum += __shfl_xor_sync(0xffffffffu, sum, 2);
            lsum[hf] = lsum[hf] * al + sum;
            #pragma unroll
            for (int jn = 0; jn < 8; ++jn) { oacc[jn][2*hf] *= al; oacc[jn][2*hf+1] *= al; }
        }

        // ---- O += P V : ph*v + pl*v (P split exact in registers, V single) ----
        #pragma unroll
        for (int s = 0; s < 4; ++s) {
            uint32_t ph[4], pl[4];
            #pragma unroll
            for (int r = 0; r < 4; ++r) {
                int tile = 2 * s + (r >> 1);
                int c0 = (r & 1) * 2;
                split_h2(sacc[tile][c0], sacc[tile][c0 + 1], ph[r], pl[r]);
            }
            uint32_t vb[8][2];
            #pragma unroll
            for (int jp = 0; jp < 4; ++jp) {
                int row = 16 * s + ((mid & 1) << 3) + lrow;
                int c = 2 * jp + (mid >> 1);
                uint32_t a = sV + row * 128 + ((c ^ (row & 7)) * 16);
                ldsm4t(vb[2*jp][0], vb[2*jp][1], vb[2*jp+1][0], vb[2*jp+1][1], a);
            }
            #pragma unroll
            for (int jn = 0; jn < 8; ++jn) mma16816(oacc[jn], ph, vb[jn]);
            #pragma unroll
            for (int jn = 0; jn < 8; ++jn) mma16816(oacc[jn], pl, vb[jn]);
        }

        __syncthreads();
        if (kt + 2 < nkt) {
            load_kv(sKV + (kt & 1) * AT_STAGE, hoff, kt + 2, tid);
            asm volatile("cp.async.commit_group;" ::: "memory");
        }
    }

    // ---- normalize + write single fp16 into [B,S,H*dk] (g_a1) ----
    const int b = bh >> 4, h = bh & 15;
    #pragma unroll
    for (int hf = 0; hf < 2; ++hf) {
        float inv = 1.0f / lsum[hf];
        int row = qbase + wid * 16 + g + 8 * hf;
        size_t base = ((size_t)(b * SEQ + row)) * D_MODEL + h * 64;
        #pragma unroll
        for (int jn = 0; jn < 8; ++jn) {
            __half2 hh = __floats2half2_rn(oacc[jn][2*hf] * inv, oacc[jn][2*hf+1] * inv);
            *reinterpret_cast<uint32_t*>(g_a1 + base + jn * 8 + 2 * t) =
                *reinterpret_cast<uint32_t*>(&hh);
        }
    }
}

// ============================================================================
extern "C" void kernel_launch(void* const* d_in, const int* in_sizes, int n_in,
                              void* d_out, int out_size)
{
    const float* x  = (const float*)d_in[0];
    const float* Wq = (const float*)d_in[1];
    const float* bq = (const float*)d_in[2];
    const float* Wk = (const float*)d_in[3];
    const float* bk = (const float*)d_in[4];
    const float* Wv = (const float*)d_in[5];
    const float* bv = (const float*)d_in[6];
    const float* Wo = (const float*)d_in[7];
    const float* bo = (const float*)d_in[8];
    float* out = (float*)d_out;

    const int nx4 = M_TOT * D_MODEL / 4;
    const int nw4 = D_MODEL * D_MODEL / 4;

    conv_x_kernel<<<nx4 / 256, 256>>>(x, nx4);
    conv_w4_kernel<<<dim3(nw4 / 256, 4), 256>>>(Wq, Wk, Wv, Wo, nw4);

    cudaFuncSetAttribute(gemm_mma_kernel,
                         cudaFuncAttributeMaxDynamicSharedMemorySize, GEMM_SMEM);

    // fused QKV: blockIdx.z = mode (0=Q, 1=K, 2=V) — all single-pass
    gemm_mma_kernel<<<dim3(D_MODEL / 128, M_TOT / 128, 3), 512, GEMM_SMEM>>>(
        0, bq, bk, bv, nullptr);

    cudaFuncSetAttribute(flash_mma_kernel,
                         cudaFuncAttributeMaxDynamicSharedMemorySize, AT_SMEM);
    flash_mma_kernel<<<dim3(BH, SEQ / 128), 256, AT_SMEM>>>();

    gemm_mma_kernel<<<dim3(D_MODEL / 128, M_TOT / 128, 1), 512, GEMM_SMEM>>>(
        3, bo, bo, bo, out);
}

// round 13
// speedup vs baseline: 8.6175x; 1.1852x over previous
#include <cuda_runtime.h>
#include <cuda_fp16.h>
#include <math.h>
#include <stdint.h>

#define D_MODEL 1024
#define NHEAD   16
#define DKH     64
#define BATCH   4
#define SEQ     2048
#define M_TOT   (BATCH*SEQ)     // 8192
#define BH      (BATCH*NHEAD)   // 64

// ---- scratch (__device__ globals: allocation-free rule) ----
__device__ __half g_x1[(size_t)M_TOT*D_MODEL];       // x single fp16
__device__ __half g_a1[(size_t)M_TOT*D_MODEL];       // attn out single fp16
__device__ __half g_wh[4][(size_t)D_MODEL*D_MODEL];  // weights single fp16
// q (pre-scaled 1/8), k, v — all single fp16 [B,H,S,dk]
__device__ __half g_q1[(size_t)BH*SEQ*DKH];
__device__ __half g_k1[(size_t)BH*SEQ*DKH];
__device__ __half g_v1[(size_t)BH*SEQ*DKH];

typedef unsigned long long ull;

__device__ __forceinline__ uint32_t smem_u32(const void* p) {
    uint32_t a;
    asm("{ .reg .u64 t; cvta.to.shared.u64 t, %1; cvt.u32.u64 %0, t; }" : "=r"(a) : "l"(p));
    return a;
}
__device__ __forceinline__ void ldsm4(uint32_t& r0, uint32_t& r1, uint32_t& r2, uint32_t& r3,
                                      uint32_t addr) {
    asm volatile("ldmatrix.sync.aligned.m8n8.x4.shared.b16 {%0,%1,%2,%3}, [%4];"
                 : "=r"(r0), "=r"(r1), "=r"(r2), "=r"(r3) : "r"(addr));
}
__device__ __forceinline__ void ldsm4t(uint32_t& r0, uint32_t& r1, uint32_t& r2, uint32_t& r3,
                                       uint32_t addr) {
    asm volatile("ldmatrix.sync.aligned.m8n8.x4.trans.shared.b16 {%0,%1,%2,%3}, [%4];"
                 : "=r"(r0), "=r"(r1), "=r"(r2), "=r"(r3) : "r"(addr));
}
__device__ __forceinline__ void mma16816(float* c, const uint32_t* a, const uint32_t* b) {
    asm volatile(
        "mma.sync.aligned.m16n8k16.row.col.f32.f16.f16.f32 "
        "{%0,%1,%2,%3}, {%4,%5,%6,%7}, {%8,%9}, {%0,%1,%2,%3};"
        : "+f"(c[0]), "+f"(c[1]), "+f"(c[2]), "+f"(c[3])
        : "r"(a[0]), "r"(a[1]), "r"(a[2]), "r"(a[3]), "r"(b[0]), "r"(b[1]));
}
// pack two f32 -> fp16x2 (e0 low)
__device__ __forceinline__ uint32_t packh2(float e0, float e1) {
    __half2 hh = __floats2half2_rn(e0, e1);
    return *reinterpret_cast<uint32_t*>(&hh);
}

// ============================================================================
// conversions: x -> g_x1;  4 weights -> g_wh (single launch, blockIdx.y)
// ============================================================================
__global__ void conv_x_kernel(const float* __restrict__ in, int n4)
{
    int i = blockIdx.x * blockDim.x + threadIdx.x;
    if (i >= n4) return;
    float4 v = reinterpret_cast<const float4*>(in)[i];
    __half h[4];
    h[0] = __float2half_rn(v.x); h[1] = __float2half_rn(v.y);
    h[2] = __float2half_rn(v.z); h[3] = __float2half_rn(v.w);
    reinterpret_cast<ull*>(g_x1)[i] = *reinterpret_cast<ull*>(h);
}

__global__ void conv_w4_kernel(const float* __restrict__ W0, const float* __restrict__ W1,
                               const float* __restrict__ W2, const float* __restrict__ W3,
                               int n4)
{
    int which = blockIdx.y;
    const float* src = (which == 0) ? W0 : (which == 1) ? W1 : (which == 2) ? W2 : W3;
    int i = blockIdx.x * blockDim.x + threadIdx.x;
    if (i >= n4) return;
    float4 v = reinterpret_cast<const float4*>(src)[i];
    __half h[4];
    h[0] = __float2half_rn(v.x); h[1] = __float2half_rn(v.y);
    h[2] = __float2half_rn(v.z); h[3] = __float2half_rn(v.w);
    reinterpret_cast<ull*>(g_wh[which])[i] = *reinterpret_cast<ull*>(h);
}

// ============================================================================
// mma.sync fp16 GEMM — single-pass.  512 threads, CTA 128x128, K-chunk 64,
// 3-stage cp.async ring.  Epilogues: 0 q/8, 1 K, 2 V (fp16); 3 fp32+bias.
// (unchanged from R12 — validated)
// ============================================================================
#define GTILE_B 16384                // 128 rows x 128B (64 halves)
#define GSTAGE_B (2 * GTILE_B)       // A, B
#define GEMM_SMEM (3 * GSTAGE_B)     // 98304

__device__ __forceinline__ void load_chunk(
    uint32_t sstage, const __half* A, const __half* B,
    int m0, int n0, int k0, int tid)
{
    const __half* srcs[2] = {A, B};
    const int bases[2] = {m0, n0};
    #pragma unroll
    for (int t = 0; t < 2; ++t) {
        #pragma unroll
        for (int i = 0; i < 2; ++i) {
            int idx = tid + i * 512;               // 1024 x 16B per tile
            int row = idx >> 3, c = idx & 7;
            const void* g = srcs[t] + (size_t)(bases[t] + row) * D_MODEL + k0 + c * 8;
            uint32_t s = sstage + t * GTILE_B + row * 128 + ((c ^ (row & 7)) * 16);
            asm volatile("cp.async.cg.shared.global [%0], [%1], 16;" :: "r"(s), "l"(g));
        }
    }
}

__global__ __launch_bounds__(512, 1)
void gemm_mma_kernel(int mode_base, const float* __restrict__ b0,
                     const float* __restrict__ b1, const float* __restrict__ b2,
                     float* __restrict__ outp)
{
    extern __shared__ __align__(128) char smem[];
    const uint32_t sb = smem_u32(smem);

    const int mode = (mode_base == 3) ? 3 : (int)blockIdx.z;
    const float* bias = (mode == 1) ? b1 : (mode == 2) ? b2 : b0;
    const __half* A = (mode == 3) ? g_a1 : g_x1;
    const __half* B = g_wh[mode];

    const int tid = threadIdx.x, wid = tid >> 5, lane = tid & 31;
    const int m0 = blockIdx.y * 128, n0 = blockIdx.x * 128;
    const int mw = (wid & 3) * 32, nw = (wid >> 2) * 32;   // 4x4 warp grid
    const int mid = lane >> 3, lrow = lane & 7;

    float acc[2][4][4];
    #pragma unroll
    for (int im = 0; im < 2; ++im)
        #pragma unroll
        for (int jn = 0; jn < 4; ++jn)
            #pragma unroll
            for (int r = 0; r < 4; ++r) acc[im][jn][r] = 0.f;

    load_chunk(sb, A, B, m0, n0, 0, tid);
    asm volatile("cp.async.commit_group;" ::: "memory");
    load_chunk(sb + GSTAGE_B, A, B, m0, n0, 64, tid);
    asm volatile("cp.async.commit_group;" ::: "memory");

    const int NCH = D_MODEL / 64;   // 16
    for (int c = 0; c < NCH; ++c) {
        const uint32_t sstage = sb + (c % 3) * GSTAGE_B;
        if (c + 1 < NCH) asm volatile("cp.async.wait_group 1;" ::: "memory");
        else             asm volatile("cp.async.wait_group 0;" ::: "memory");
        __syncthreads();

        #pragma unroll
        for (int s = 0; s < 4; ++s) {          // 4 k-steps of 16 per chunk
            uint32_t ah[2][4], bh[4][2];
            #pragma unroll
            for (int im = 0; im < 2; ++im) {
                int row = mw + im * 16 + ((mid & 1) << 3) + lrow;
                int kc  = 2 * s + (mid >> 1);
                uint32_t addr = sstage + row * 128 + ((kc ^ (row & 7)) * 16);
                ldsm4(ah[im][0], ah[im][1], ah[im][2], ah[im][3], addr);
            }
            #pragma unroll
            for (int jp = 0; jp < 2; ++jp) {
                int row = nw + jp * 16 + ((mid >> 1) << 3) + lrow;
                int kc  = 2 * s + (mid & 1);
                uint32_t addr = sstage + GTILE_B + row * 128 + ((kc ^ (row & 7)) * 16);
                ldsm4(bh[2*jp][0], bh[2*jp][1], bh[2*jp+1][0], bh[2*jp+1][1], addr);
            }
            #pragma unroll
            for (int im = 0; im < 2; ++im)
                #pragma unroll
                for (int jn = 0; jn < 4; ++jn)
                    mma16816(acc[im][jn], ah[im], bh[jn]);
        }
        if (c + 2 < NCH) {
            load_chunk(sb + ((c + 2) % 3) * GSTAGE_B, A, B, m0, n0, (c + 2) * 64, tid);
            asm volatile("cp.async.commit_group;" ::: "memory");
        }
    }

    const int g = lane >> 2, t = lane & 3;
    const float sc = (mode == 0) ? 0.125f : 1.0f;

    #pragma unroll
    for (int im = 0; im < 2; ++im) {
        #pragma unroll
        for (int jn = 0; jn < 4; ++jn) {
            int r0 = m0 + mw + im * 16 + g;
            int cc = n0 + nw + jn * 8 + 2 * t;
            float2 b2v = *reinterpret_cast<const float2*>(bias + cc);
            float v00 = (acc[im][jn][0] + b2v.x) * sc, v01 = (acc[im][jn][1] + b2v.y) * sc;
            float v10 = (acc[im][jn][2] + b2v.x) * sc, v11 = (acc[im][jn][3] + b2v.y) * sc;
            if (mode < 3) {
                int h = cc >> 6, d = cc & 63;
                __half* dst = (mode == 0) ? g_q1 : (mode == 1) ? g_k1 : g_v1;
                #pragma unroll
                for (int rr = 0; rr < 2; ++rr) {
                    int r = r0 + rr * 8;
                    float e0 = rr ? v10 : v00, e1 = rr ? v11 : v01;
                    int b = r >> 11, srow = r & (SEQ - 1);
                    size_t idx = (((size_t)(b * NHEAD + h)) * SEQ + srow) * DKH + d;
                    *reinterpret_cast<uint32_t*>(dst + idx) = packh2(e0, e1);
                }
            } else {
                *reinterpret_cast<float2*>(outp + (size_t)r0 * D_MODEL + cc) = make_float2(v00, v01);
                *reinterpret_cast<float2*>(outp + (size_t)(r0+8) * D_MODEL + cc) = make_float2(v10, v11);
            }
        }
    }
}

// ============================================================================
// Flash attention, fp16 mma.sync — fully single-pass.
// S = q·K (1 pass).  PV = p·v (1 pass, P rounded to fp16 in registers).
// __launch_bounds__(256, 2): cap 128 regs -> 2 CTAs/SM (occ 25%).
// smem: Q 16K, 2 stages x (K 8K, V 8K) = 48KB.
// ============================================================================
#define AT_STAGE 16384
#define AT_SMEM (16384 + 2 * AT_STAGE)   // 49152

__device__ __forceinline__ void load_kv(uint32_t sstage, size_t hoff, int kt, int tid)
{
    const __half* srcs[2] = { g_k1 + hoff, g_v1 + hoff };
    #pragma unroll
    for (int tI = 0; tI < 2; ++tI)
        #pragma unroll
        for (int i = 0; i < 2; ++i) {
            int idx = tid + i * 256;
            int row = idx >> 3, c = idx & 7;
            const void* gsrc = srcs[tI] + (size_t)(kt * 64 + row) * DKH + c * 8;
            uint32_t d = sstage + tI * 8192 + row * 128 + ((c ^ (row & 7)) * 16);
            asm volatile("cp.async.cg.shared.global [%0], [%1], 16;" :: "r"(d), "l"(gsrc));
        }
}

__global__ __launch_bounds__(256, 2)
void flash_mma_kernel()
{
    extern __shared__ __align__(128) char smem[];
    const uint32_t sb = smem_u32(smem);
    const uint32_t sQ = sb, sKV = sb + 16384;

    const int tid = threadIdx.x, wid = tid >> 5, lane = tid & 31;
    const int mid = lane >> 3, lrow = lane & 7;
    const int g = lane >> 2, t = lane & 3;
    const int bh = blockIdx.x;
    const int qt = (int)(gridDim.y - 1 - blockIdx.y);   // heavy tiles first
    const int qbase = qt * 128;
    const size_t hoff = (size_t)bh * SEQ * DKH;
    const int nkt = 2 * qt + 2;

    {
        #pragma unroll
        for (int i = 0; i < 4; ++i) {
            int idx = tid + i * 256;
            int row = idx >> 3, c = idx & 7;
            const void* gsrc = g_q1 + hoff + (size_t)(qbase + row) * DKH + c * 8;
            uint32_t d = sQ + row * 128 + ((c ^ (row & 7)) * 16);
            asm volatile("cp.async.cg.shared.global [%0], [%1], 16;" :: "r"(d), "l"(gsrc));
        }
    }
    load_kv(sKV, hoff, 0, tid);
    asm volatile("cp.async.commit_group;" ::: "memory");
    load_kv(sKV + AT_STAGE, hoff, 1, tid);
    asm volatile("cp.async.commit_group;" ::: "memory");

    float oacc[8][4];
    #pragma unroll
    for (int jn = 0; jn < 8; ++jn)
        #pragma unroll
        for (int r = 0; r < 4; ++r) oacc[jn][r] = 0.f;
    float mrow[2] = {-INFINITY, -INFINITY};
    float lsum[2] = {0.f, 0.f};
    uint32_t qh[4][4];

    for (int kt = 0; kt < nkt; ++kt) {
        if (kt + 1 < nkt) asm volatile("cp.async.wait_group 1;" ::: "memory");
        else              asm volatile("cp.async.wait_group 0;" ::: "memory");
        __syncthreads();

        if (kt == 0) {
            #pragma unroll
            for (int s = 0; s < 4; ++s) {
                int row = wid * 16 + ((mid & 1) << 3) + lrow;
                int kc = 2 * s + (mid >> 1);
                uint32_t a = sQ + row * 128 + ((kc ^ (row & 7)) * 16);
                ldsm4(qh[s][0], qh[s][1], qh[s][2], qh[s][3], a);
            }
        }

        const uint32_t sK = sKV + (kt & 1) * AT_STAGE;
        const uint32_t sV = sK + 8192;

        // ---- S = q·K (single pass) ----
        float sacc[8][4];
        #pragma unroll
        for (int jn = 0; jn < 8; ++jn)
            #pragma unroll
            for (int r = 0; r < 4; ++r) sacc[jn][r] = 0.f;

        #pragma unroll
        for (int s = 0; s < 4; ++s) {
            uint32_t kb[8][2];
            #pragma unroll
            for (int jp = 0; jp < 4; ++jp) {
                int row = jp * 16 + ((mid >> 1) << 3) + lrow;
                int kc = 2 * s + (mid & 1);
                uint32_t a = sK + row * 128 + ((kc ^ (row & 7)) * 16);
                ldsm4(kb[2*jp][0], kb[2*jp][1], kb[2*jp+1][0], kb[2*jp+1][1], a);
            }
            #pragma unroll
            for (int jn = 0; jn < 8; ++jn) mma16816(sacc[jn], qh[s], kb[jn]);
        }

        if (kt >= 2 * qt) {
            int q0 = qbase + wid * 16 + g;
            #pragma unroll
            for (int jn = 0; jn < 8; ++jn) {
                int j0 = kt * 64 + jn * 8 + 2 * t;
                if (j0     > q0)     sacc[jn][0] = -INFINITY;
                if (j0 + 1 > q0)     sacc[jn][1] = -INFINITY;
                if (j0     > q0 + 8) sacc[jn][2] = -INFINITY;
                if (j0 + 1 > q0 + 8) sacc[jn][3] = -INFINITY;
            }
        }

        #pragma unroll
        for (int hf = 0; hf < 2; ++hf) {
            float mx = -INFINITY;
            #pragma unroll
            for (int jn = 0; jn < 8; ++jn)
                mx = fmaxf(mx, fmaxf(sacc[jn][2*hf], sacc[jn][2*hf+1]));
            mx = fmaxf(mx, __shfl_xor_sync(0xffffffffu, mx, 1));
            mx = fmaxf(mx, __shfl_xor_sync(0xffffffffu, mx, 2));
            float mn = fmaxf(mrow[hf], mx);
            float al = __expf(mrow[hf] - mn);
            mrow[hf] = mn;
            float sum = 0.f;
            #pragma unroll
            for (int jn = 0; jn < 8; ++jn) {
                float p0 = __expf(sacc[jn][2*hf]   - mn);
                float p1 = __expf(sacc[jn][2*hf+1] - mn);
                sacc[jn][2*hf] = p0; sacc[jn][2*hf+1] = p1;
                sum += p0 + p1;
            }
            sum += __shfl_xor_sync(0xffffffffu, sum, 1);
            sum += __shfl_xor_sync(0xffffffffu, sum, 2);
            lsum[hf] = lsum[hf] * al + sum;
            #pragma unroll
            for (int jn = 0; jn < 8; ++jn) { oacc[jn][2*hf] *= al; oacc[jn][2*hf+1] *= al; }
        }

        // ---- O += P V (single pass; P rounded to fp16 in registers) ----
        #pragma unroll
        for (int s = 0; s < 4; ++s) {
            uint32_t ph[4];
            #pragma unroll
            for (int r = 0; r < 4; ++r) {
                int tile = 2 * s + (r >> 1);
                int c0 = (r & 1) * 2;
                ph[r] = packh2(sacc[tile][c0], sacc[tile][c0 + 1]);
            }
            uint32_t vb[8][2];
            #pragma unroll
            for (int jp = 0; jp < 4; ++jp) {
                int row = 16 * s + ((mid & 1) << 3) + lrow;
                int c = 2 * jp + (mid >> 1);
                uint32_t a = sV + row * 128 + ((c ^ (row & 7)) * 16);
                ldsm4t(vb[2*jp][0], vb[2*jp][1], vb[2*jp+1][0], vb[2*jp+1][1], a);
            }
            #pragma unroll
            for (int jn = 0; jn < 8; ++jn) mma16816(oacc[jn], ph, vb[jn]);
        }

        __syncthreads();
        if (kt + 2 < nkt) {
            load_kv(sKV + (kt & 1) * AT_STAGE, hoff, kt + 2, tid);
            asm volatile("cp.async.commit_group;" ::: "memory");
        }
    }

    // ---- normalize + write single fp16 into [B,S,H*dk] (g_a1) ----
    const int b = bh >> 4, h = bh & 15;
    #pragma unroll
    for (int hf = 0; hf < 2; ++hf) {
        float inv = 1.0f / lsum[hf];
        int row = qbase + wid * 16 + g + 8 * hf;
        size_t base = ((size_t)(b * SEQ + row)) * D_MODEL + h * 64;
        #pragma unroll
        for (int jn = 0; jn < 8; ++jn) {
            *reinterpret_cast<uint32_t*>(g_a1 + base + jn * 8 + 2 * t) =
                packh2(oacc[jn][2*hf] * inv, oacc[jn][2*hf+1] * inv);
        }
    }
}

// ============================================================================
extern "C" void kernel_launch(void* const* d_in, const int* in_sizes, int n_in,
                              void* d_out, int out_size)
{
    const float* x  = (const float*)d_in[0];
    const float* Wq = (const float*)d_in[1];
    const float* bq = (const float*)d_in[2];
    const float* Wk = (const float*)d_in[3];
    const float* bk = (const float*)d_in[4];
    const float* Wv = (const float*)d_in[5];
    const float* bv = (const float*)d_in[6];
    const float* Wo = (const float*)d_in[7];
    const float* bo = (const float*)d_in[8];
    float* out = (float*)d_out;

    const int nx4 = M_TOT * D_MODEL / 4;
    const int nw4 = D_MODEL * D_MODEL / 4;

    conv_x_kernel<<<nx4 / 256, 256>>>(x, nx4);
    conv_w4_kernel<<<dim3(nw4 / 256, 4), 256>>>(Wq, Wk, Wv, Wo, nw4);

    cudaFuncSetAttribute(gemm_mma_kernel,
                         cudaFuncAttributeMaxDynamicSharedMemorySize, GEMM_SMEM);

    // fused QKV: blockIdx.z = mode (0=Q, 1=K, 2=V) — all single-pass
    gemm_mma_kernel<<<dim3(D_MODEL / 128, M_TOT / 128, 3), 512, GEMM_SMEM>>>(
        0, bq, bk, bv, nullptr);

    cudaFuncSetAttribute(flash_mma_kernel,
                         cudaFuncAttributeMaxDynamicSharedMemorySize, AT_SMEM);
    flash_mma_kernel<<<dim3(BH, SEQ / 128), 256, AT_SMEM>>>();

    gemm_mma_kernel<<<dim3(D_MODEL / 128, M_TOT / 128, 1), 512, GEMM_SMEM>>>(
        3, bo, bo, bo, out);
}